// round 9
// baseline (speedup 1.0000x reference)
#include <cuda_runtime.h>
#include <cuda_bf16.h>
#include <math.h>

#define BB 64
#define PP 512
#define NN 512
#define EE 128
#define FFD 512
#define LLAYERS 6
#define M_TOT (BB*NN)
#define EPS 1e-5f
#define INV_SQRT_E 0.08838834764831845f  /* 1/sqrt(128) */

typedef unsigned short u16;
typedef unsigned int   u32;

// ---------------- scratch (static device globals; no alloc allowed) ----------------
__device__ float g_x  [BB*NN*EE];
__device__ float g_y  [BB*NN*EE];
__device__ float g_h  [BB*NN*EE];
__device__ float g_sq [BB*NN*EE];
__device__ float g_ek [BB*NN*EE];
__device__ float g_ekv[BB*NN*EE];
__device__ float g_hid[BB*NN*FFD];
__device__ float g_aft[BB*PP*EE];
__device__ float g_gq [BB*EE];
__device__ float g_gm [BB*EE];

// ================= bf16 split helpers =================
__device__ __forceinline__ void cvt_hl(float x, u16& h, u16& l) {
    __nv_bfloat16 bh = __float2bfloat16(x);
    float hf = __bfloat162float(bh);
    __nv_bfloat16 bl = __float2bfloat16(x - hf);
    h = __bfloat16_as_ushort(bh);
    l = __bfloat16_as_ushort(bl);
}

// convert 8 floats -> hi/lo bf16 rows (16B stores, dst 16B aligned)
__device__ __forceinline__ void cv8(const float* v, u16* ph, u16* pl) {
    u16 h[8], l[8];
    #pragma unroll
    for (int i = 0; i < 8; i++) cvt_hl(v[i], h[i], l[i]);
    *(uint4*)ph = *(uint4*)h;
    *(uint4*)pl = *(uint4*)l;
}

#define MMAB(d, a, b)                                                        \
    asm volatile("mma.sync.aligned.m16n8k16.row.col.f32.bf16.bf16.f32 "      \
        "{%0,%1,%2,%3},{%4,%5,%6,%7},{%8,%9},{%0,%1,%2,%3};"                 \
        : "+f"(d[0]), "+f"(d[1]), "+f"(d[2]), "+f"(d[3])                     \
        : "r"(a[0]), "r"(a[1]), "r"(a[2]), "r"(a[3]), "r"(b[0]), "r"(b[1]))

// ---------------- smem tile loaders (256 threads, BK=16) ----------------
// A: 128 rows x 16 k from row-major G[lda] -> Ah/Al [128][16] bf16
__device__ __forceinline__ void load_A_bf(const float* __restrict__ G, size_t lda,
                                          int m0, int k0, u16* Ah, u16* Al, int tid) {
    int r = tid >> 1, c = (tid & 1)*8;
    const float* p = G + (size_t)(m0 + r)*lda + k0 + c;
    float4 v0 = *(const float4*)p, v1 = *(const float4*)(p + 4);
    float v[8] = {v0.x,v0.y,v0.z,v0.w,v1.x,v1.y,v1.z,v1.w};
    cv8(v, Ah + r*16 + c, Al + r*16 + c);
}

// A = exp(s*G)
__device__ __forceinline__ void load_A_exp_bf(const float* __restrict__ G, size_t lda,
                                              int m0, int k0, u16* Ah, u16* Al, int tid, float s) {
    int r = tid >> 1, c = (tid & 1)*8;
    const float* p = G + (size_t)(m0 + r)*lda + k0 + c;
    float4 v0 = *(const float4*)p, v1 = *(const float4*)(p + 4);
    float v[8] = {__expf(s*v0.x),__expf(s*v0.y),__expf(s*v0.z),__expf(s*v0.w),
                  __expf(s*v1.x),__expf(s*v1.y),__expf(s*v1.z),__expf(s*v1.w)};
    cv8(v, Ah + r*16 + c, Al + r*16 + c);
}

// A = exp(s*G + M)
__device__ __forceinline__ void load_A_expmask_bf(const float* __restrict__ G,
                                                  const float* __restrict__ Msk, size_t lda,
                                                  int m0, int k0, u16* Ah, u16* Al, int tid, float s) {
    int r = tid >> 1, c = (tid & 1)*8;
    size_t off = (size_t)(m0 + r)*lda + k0 + c;
    float4 v0 = *(const float4*)(G + off),   v1 = *(const float4*)(G + off + 4);
    float4 m0v = *(const float4*)(Msk + off), m1v = *(const float4*)(Msk + off + 4);
    float v[8] = {__expf(s*v0.x+m0v.x),__expf(s*v0.y+m0v.y),__expf(s*v0.z+m0v.z),__expf(s*v0.w+m0v.w),
                  __expf(s*v1.x+m1v.x),__expf(s*v1.y+m1v.y),__expf(s*v1.z+m1v.z),__expf(s*v1.w+m1v.w)};
    cv8(v, Ah + r*16 + c, Al + r*16 + c);
}

// B transpose: global [k][n] (n contiguous) -> Bh/Bl [n][16] (128 cols)
__device__ __forceinline__ void load_B_T(const float* __restrict__ G, size_t ldb,
                                         int k0, int n0, u16* Bh, u16* Bl, int tid) {
    int k = tid >> 4, nt = (tid & 15)*8;
    const float* p = G + (size_t)(k0 + k)*ldb + n0 + nt;
    float4 v0 = *(const float4*)p, v1 = *(const float4*)(p + 4);
    float v[8] = {v0.x,v0.y,v0.z,v0.w,v1.x,v1.y,v1.z,v1.w};
    #pragma unroll
    for (int u = 0; u < 8; u++) {
        u16 h, l; cvt_hl(v[u], h, l);
        Bh[(nt+u)*16 + k] = h;
        Bl[(nt+u)*16 + k] = l;
    }
}

// dual B transpose: two [k][n] globals -> 64-col tiles each
__device__ __forceinline__ void load_B64x2_T(const float* __restrict__ G1,
                                             const float* __restrict__ G2, size_t ldb,
                                             int k0, int n0,
                                             u16* B1h, u16* B1l, u16* B2h, u16* B2l, int tid) {
    int k = tid >> 4, nt = (tid & 15)*4;
    size_t off = (size_t)(k0 + k)*ldb + n0 + nt;
    float4 a = *(const float4*)(G1 + off);
    float4 b = *(const float4*)(G2 + off);
    float va[4] = {a.x,a.y,a.z,a.w};
    float vb[4] = {b.x,b.y,b.z,b.w};
    #pragma unroll
    for (int u = 0; u < 4; u++) {
        u16 h, l;
        cvt_hl(va[u], h, l); B1h[(nt+u)*16 + k] = h; B1l[(nt+u)*16 + k] = l;
        cvt_hl(vb[u], h, l); B2h[(nt+u)*16 + k] = h; B2l[(nt+u)*16 + k] = l;
    }
}

// B direct (already [n][k], k contiguous): rows = n (128)
__device__ __forceinline__ void load_B_direct(const float* __restrict__ G, size_t lda,
                                              int n0, int k0, u16* Bh, u16* Bl, int tid) {
    int r = tid >> 1, c = (tid & 1)*8;
    const float* p = G + (size_t)(n0 + r)*lda + k0 + c;
    float4 v0 = *(const float4*)p, v1 = *(const float4*)(p + 4);
    float v[8] = {v0.x,v0.y,v0.z,v0.w,v1.x,v1.y,v1.z,v1.w};
    cv8(v, Bh + r*16 + c, Bl + r*16 + c);
}

// ---------------- warp mma: BN=128 (warp 32x64, j=8) ----------------
__device__ __forceinline__ void mma_block128(const u16* Ah, const u16* Al,
        const u16* Bh, const u16* Bl, float d[2][8][4],
        int wr0, int wc0, int qr, int qc) {
    u32 ah[2][4], al[2][4];
    #pragma unroll
    for (int i = 0; i < 2; i++) {
        int r = wr0 + i*16 + qr;
        const u32* p0 = (const u32*)(Ah + r*16) + qc;
        const u32* p1 = (const u32*)(Ah + (r+8)*16) + qc;
        ah[i][0]=p0[0]; ah[i][1]=p1[0]; ah[i][2]=p0[4]; ah[i][3]=p1[4];
        const u32* q0 = (const u32*)(Al + r*16) + qc;
        const u32* q1 = (const u32*)(Al + (r+8)*16) + qc;
        al[i][0]=q0[0]; al[i][1]=q1[0]; al[i][2]=q0[4]; al[i][3]=q1[4];
    }
    #pragma unroll
    for (int j = 0; j < 8; j++) {
        int n = wc0 + j*8 + qr;
        const u32* pb = (const u32*)(Bh + n*16) + qc;
        u32 bh[2] = {pb[0], pb[4]};
        const u32* pl = (const u32*)(Bl + n*16) + qc;
        u32 bl[2] = {pl[0], pl[4]};
        #pragma unroll
        for (int i = 0; i < 2; i++) {
            MMAB(d[i][j], ah[i], bh);
            MMAB(d[i][j], al[i], bh);
            MMAB(d[i][j], ah[i], bl);
        }
    }
}

// ---------------- warp mma: BN=64 dual matrices (warp 32x32, j=4) ----------------
__device__ __forceinline__ void mma_block64x2(const u16* Ah, const u16* Al,
        const u16* B1h, const u16* B1l, const u16* B2h, const u16* B2l,
        float d1[2][4][4], float d2[2][4][4],
        int wr0, int wc0, int qr, int qc) {
    u32 ah[2][4], al[2][4];
    #pragma unroll
    for (int i = 0; i < 2; i++) {
        int r = wr0 + i*16 + qr;
        const u32* p0 = (const u32*)(Ah + r*16) + qc;
        const u32* p1 = (const u32*)(Ah + (r+8)*16) + qc;
        ah[i][0]=p0[0]; ah[i][1]=p1[0]; ah[i][2]=p0[4]; ah[i][3]=p1[4];
        const u32* q0 = (const u32*)(Al + r*16) + qc;
        const u32* q1 = (const u32*)(Al + (r+8)*16) + qc;
        al[i][0]=q0[0]; al[i][1]=q1[0]; al[i][2]=q0[4]; al[i][3]=q1[4];
    }
    #pragma unroll
    for (int j = 0; j < 4; j++) {
        int n = wc0 + j*8 + qr;
        {
            const u32* pb = (const u32*)(B1h + n*16) + qc;
            u32 bh[2] = {pb[0], pb[4]};
            const u32* pl = (const u32*)(B1l + n*16) + qc;
            u32 bl[2] = {pl[0], pl[4]};
            #pragma unroll
            for (int i = 0; i < 2; i++) {
                MMAB(d1[i][j], ah[i], bh);
                MMAB(d1[i][j], al[i], bh);
                MMAB(d1[i][j], ah[i], bl);
            }
        }
        {
            const u32* pb = (const u32*)(B2h + n*16) + qc;
            u32 bh[2] = {pb[0], pb[4]};
            const u32* pl = (const u32*)(B2l + n*16) + qc;
            u32 bl[2] = {pl[0], pl[4]};
            #pragma unroll
            for (int i = 0; i < 2; i++) {
                MMAB(d2[i][j], ah[i], bh);
                MMAB(d2[i][j], al[i], bh);
                MMAB(d2[i][j], ah[i], bl);
            }
        }
    }
}

// ---------------- embedding ----------------
__global__ void embed_kernel(const float* __restrict__ data,
                             const float* __restrict__ W,
                             const float* __restrict__ bias,
                             float* __restrict__ X) {
    int idx = blockIdx.x;
    int e   = threadIdx.x;
    float d0 = data[idx*2+0], d1 = data[idx*2+1];
    X[(size_t)idx*EE + e] = d0*W[e] + d1*W[EE+e] + bias[e];
}

// =====================================================================
// qkv: 3 passes (q -> SQ, k -> EK, v -> EKV via EK reload); BM=128, N=128
// =====================================================================
__global__ __launch_bounds__(256) void qkv_tc(
        const float* __restrict__ X,
        const float* __restrict__ Wq,
        const float* __restrict__ Wk,
        const float* __restrict__ Wv,
        float* __restrict__ SQ,
        float* __restrict__ EK,
        float* __restrict__ EKV) {
    __shared__ u16 Ah[128*16], Al[128*16], Bh[128*16], Bl[128*16];
    const int tid = threadIdx.x, lane = tid & 31, w = tid >> 5;
    const int wr0 = (w >> 1)*32, wc0 = (w & 1)*64;
    const int qr = lane >> 2, qc = lane & 3;
    const int m0 = blockIdx.x*128;

    for (int pass = 0; pass < 3; pass++) {
        const float* Wm = (pass == 0) ? Wq : (pass == 1) ? Wk : Wv;
        float d[2][8][4] = {};
        for (int k0 = 0; k0 < EE; k0 += 16) {
            load_A_bf(X, EE, m0, k0, Ah, Al, tid);
            load_B_T(Wm, EE, k0, 0, Bh, Bl, tid);
            __syncthreads();
            mma_block128(Ah, Al, Bh, Bl, d, wr0, wc0, qr, qc);
            __syncthreads();
        }
        #pragma unroll
        for (int i = 0; i < 2; i++)
            #pragma unroll
            for (int h = 0; h < 2; h++) {
                int row = m0 + wr0 + i*16 + qr + h*8;
                #pragma unroll
                for (int j = 0; j < 8; j++) {
                    int col = wc0 + j*8 + qc*2;
                    size_t o = (size_t)row*EE + col;
                    float v0 = d[i][j][h*2], v1 = d[i][j][h*2+1];
                    if (pass == 0) {
                        *(float2*)&SQ[o] = make_float2(
                            1.f/(1.f + __expf(-v0)), 1.f/(1.f + __expf(-v1)));
                    } else if (pass == 1) {
                        *(float2*)&EK[o] = make_float2(__expf(v0), __expf(v1));
                    } else {
                        float2 e = *(const float2*)&EK[o];
                        *(float2*)&EKV[o] = make_float2(e.x*v0, e.y*v1);
                    }
                }
            }
    }
}

// =====================================================================
// dec k/v: 2 passes
// =====================================================================
__global__ __launch_bounds__(256) void deckv_tc(
        const float* __restrict__ X,
        const float* __restrict__ Wk,
        const float* __restrict__ Wv,
        float* __restrict__ EK,
        float* __restrict__ EKV) {
    __shared__ u16 Ah[128*16], Al[128*16], Bh[128*16], Bl[128*16];
    const int tid = threadIdx.x, lane = tid & 31, w = tid >> 5;
    const int wr0 = (w >> 1)*32, wc0 = (w & 1)*64;
    const int qr = lane >> 2, qc = lane & 3;
    const int m0 = blockIdx.x*128;

    for (int pass = 0; pass < 2; pass++) {
        const float* Wm = (pass == 0) ? Wk : Wv;
        float d[2][8][4] = {};
        for (int k0 = 0; k0 < EE; k0 += 16) {
            load_A_bf(X, EE, m0, k0, Ah, Al, tid);
            load_B_T(Wm, EE, k0, 0, Bh, Bl, tid);
            __syncthreads();
            mma_block128(Ah, Al, Bh, Bl, d, wr0, wc0, qr, qc);
            __syncthreads();
        }
        #pragma unroll
        for (int i = 0; i < 2; i++)
            #pragma unroll
            for (int h = 0; h < 2; h++) {
                int row = m0 + wr0 + i*16 + qr + h*8;
                #pragma unroll
                for (int j = 0; j < 8; j++) {
                    int col = wc0 + j*8 + qc*2;
                    size_t o = (size_t)row*EE + col;
                    float v0 = d[i][j][h*2], v1 = d[i][j][h*2+1];
                    if (pass == 0) {
                        *(float2*)&EK[o] = make_float2(__expf(v0), __expf(v1));
                    } else {
                        float2 e = *(const float2*)&EK[o];
                        *(float2*)&EKV[o] = make_float2(e.x*v0, e.y*v1);
                    }
                }
            }
    }
}

// =====================================================================
// encoder AFT: BM=128 nodes, BN=64 of E, dual accumulation (num/den)
// =====================================================================
__global__ __launch_bounds__(256) void aft_enc_tc(
        const float* __restrict__ dist,
        const float* __restrict__ ls,
        const float* __restrict__ alpha, int l,
        const float* __restrict__ EKV,
        const float* __restrict__ EK,
        const float* __restrict__ X,
        const float* __restrict__ SQ,
        float* __restrict__ Y) {
    __shared__ u16 Ah[128*16], Al[128*16];
    __shared__ u16 B1h[64*16], B1l[64*16], B2h[64*16], B2l[64*16];
    const int b = blockIdx.z;
    const int m0 = blockIdx.x*128, n0 = blockIdx.y*64;
    const float s = ls[0]*alpha[l];
    const float* D  = dist + (size_t)b*NN*NN;
    const float* B1 = EKV  + (size_t)b*NN*EE;
    const float* B2 = EK   + (size_t)b*NN*EE;
    const int tid = threadIdx.x, lane = tid & 31, w = tid >> 5;
    const int wr0 = (w >> 1)*32, wc0 = (w & 1)*32;
    const int qr = lane >> 2, qc = lane & 3;
    float d1[2][4][4] = {}, d2[2][4][4] = {};

    for (int k0 = 0; k0 < NN; k0 += 16) {
        load_A_exp_bf(D, NN, m0, k0, Ah, Al, tid, s);
        load_B64x2_T(B1, B2, EE, k0, n0, B1h, B1l, B2h, B2l, tid);
        __syncthreads();
        mma_block64x2(Ah, Al, B1h, B1l, B2h, B2l, d1, d2, wr0, wc0, qr, qc);
        __syncthreads();
    }
    #pragma unroll
    for (int i = 0; i < 2; i++)
        #pragma unroll
        for (int h = 0; h < 2; h++) {
            int row = m0 + wr0 + i*16 + qr + h*8;
            #pragma unroll
            for (int j = 0; j < 4; j++) {
                int col = n0 + wc0 + j*8 + qc*2;
                size_t o = ((size_t)b*NN + row)*EE + col;
                float2 xv = *(const float2*)&X[o];
                float2 sv = *(const float2*)&SQ[o];
                float n0v = d1[i][j][h*2], n1v = d1[i][j][h*2+1];
                float de0 = d2[i][j][h*2], de1 = d2[i][j][h*2+1];
                *(float2*)&Y[o] = make_float2(
                    xv.x + sv.x*(n0v/de0), xv.y + sv.y*(n1v/de1));
            }
        }
}

// =====================================================================
// decoder AFT
// =====================================================================
__global__ __launch_bounds__(256) void dec_aft_tc(
        const float* __restrict__ cur_dist,
        const float* __restrict__ ninf,
        const float* __restrict__ ls,
        const float* __restrict__ dalpha,
        const float* __restrict__ EKV,
        const float* __restrict__ EK,
        const float* __restrict__ GQ,
        const float* __restrict__ cap,
        const float* __restrict__ dWq,
        float* __restrict__ AFT) {
    __shared__ u16 Ah[128*16], Al[128*16];
    __shared__ u16 B1h[64*16], B1l[64*16], B2h[64*16], B2l[64*16];
    const int b = blockIdx.z;
    const int m0 = blockIdx.x*128, n0 = blockIdx.y*64;
    const float s = ls[0]*dalpha[0];
    const float* CD = cur_dist + (size_t)b*PP*NN;
    const float* NM = ninf     + (size_t)b*PP*NN;
    const float* B1 = EKV + (size_t)b*NN*EE;
    const float* B2 = EK  + (size_t)b*NN*EE;
    const int tid = threadIdx.x, lane = tid & 31, w = tid >> 5;
    const int wr0 = (w >> 1)*32, wc0 = (w & 1)*32;
    const int qr = lane >> 2, qc = lane & 3;
    float d1[2][4][4] = {}, d2[2][4][4] = {};

    for (int k0 = 0; k0 < NN; k0 += 16) {
        load_A_expmask_bf(CD, NM, NN, m0, k0, Ah, Al, tid, s);
        load_B64x2_T(B1, B2, EE, k0, n0, B1h, B1l, B2h, B2l, tid);
        __syncthreads();
        mma_block64x2(Ah, Al, B1h, B1l, B2h, B2l, d1, d2, wr0, wc0, qr, qc);
        __syncthreads();
    }
    #pragma unroll
    for (int i = 0; i < 2; i++)
        #pragma unroll
        for (int h = 0; h < 2; h++) {
            int p = m0 + wr0 + i*16 + qr + h*8;
            float cv = cap[(size_t)b*PP + p];
            #pragma unroll
            for (int j = 0; j < 4; j++) {
                int col = n0 + wc0 + j*8 + qc*2;
                float2 gq2 = *(const float2*)&GQ[b*EE + col];
                float2 wq2 = *(const float2*)&dWq[EE*EE + col];
                float q0 = gq2.x + cv*wq2.x;
                float q1 = gq2.y + cv*wq2.y;
                float sg0 = 1.f/(1.f + __expf(-q0));
                float sg1 = 1.f/(1.f + __expf(-q1));
                float n0v = d1[i][j][h*2], n1v = d1[i][j][h*2+1];
                float de0 = d2[i][j][h*2], de1 = d2[i][j][h*2+1];
                size_t o = ((size_t)b*PP + p)*EE + col;
                *(float2*)&AFT[o] = make_float2(sg0*(n0v/de0), sg1*(n1v/de1));
            }
        }
}

// =====================================================================
// FF1: hid = relu(h@W1 + b1); BM=128, BN=128
// =====================================================================
__global__ __launch_bounds__(256) void ff1_tc(
        const float* __restrict__ H,
        const float* __restrict__ W1,
        const float* __restrict__ b1,
        float* __restrict__ HID) {
    __shared__ u16 Ah[128*16], Al[128*16], Bh[128*16], Bl[128*16];
    const int tid = threadIdx.x, lane = tid & 31, w = tid >> 5;
    const int wr0 = (w >> 1)*32, wc0 = (w & 1)*64;
    const int qr = lane >> 2, qc = lane & 3;
    const int m0 = blockIdx.x*128, n0 = blockIdx.y*128;
    float d[2][8][4] = {};

    for (int k0 = 0; k0 < EE; k0 += 16) {
        load_A_bf(H, EE, m0, k0, Ah, Al, tid);
        load_B_T(W1, FFD, k0, n0, Bh, Bl, tid);
        __syncthreads();
        mma_block128(Ah, Al, Bh, Bl, d, wr0, wc0, qr, qc);
        __syncthreads();
    }
    #pragma unroll
    for (int i = 0; i < 2; i++)
        #pragma unroll
        for (int h = 0; h < 2; h++) {
            int row = m0 + wr0 + i*16 + qr + h*8;
            #pragma unroll
            for (int j = 0; j < 8; j++) {
                int col = n0 + wc0 + j*8 + qc*2;
                float2 bb = *(const float2*)&b1[col];
                size_t o = (size_t)row*FFD + col;
                *(float2*)&HID[o] = make_float2(
                    fmaxf(d[i][j][h*2]   + bb.x, 0.f),
                    fmaxf(d[i][j][h*2+1] + bb.y, 0.f));
            }
        }
}

// =====================================================================
// FF2: y = h + hid@W2 + b2   (K=512, N=128)
// =====================================================================
__global__ __launch_bounds__(256) void ff2_tc(
        const float* __restrict__ HID,
        const float* __restrict__ W2,
        const float* __restrict__ b2,
        const float* __restrict__ H,
        float* __restrict__ Y) {
    __shared__ u16 Ah[128*16], Al[128*16], Bh[128*16], Bl[128*16];
    const int tid = threadIdx.x, lane = tid & 31, w = tid >> 5;
    const int wr0 = (w >> 1)*32, wc0 = (w & 1)*64;
    const int qr = lane >> 2, qc = lane & 3;
    const int m0 = blockIdx.x*128;
    float d[2][8][4] = {};

    for (int k0 = 0; k0 < FFD; k0 += 16) {
        load_A_bf(HID, FFD, m0, k0, Ah, Al, tid);
        load_B_T(W2, EE, k0, 0, Bh, Bl, tid);
        __syncthreads();
        mma_block128(Ah, Al, Bh, Bl, d, wr0, wc0, qr, qc);
        __syncthreads();
    }
    #pragma unroll
    for (int i = 0; i < 2; i++)
        #pragma unroll
        for (int h = 0; h < 2; h++) {
            int row = m0 + wr0 + i*16 + qr + h*8;
            #pragma unroll
            for (int j = 0; j < 8; j++) {
                int col = wc0 + j*8 + qc*2;
                float2 bb = *(const float2*)&b2[col];
                size_t o = (size_t)row*EE + col;
                float2 hv = *(const float2*)&H[o];
                *(float2*)&Y[o] = make_float2(
                    hv.x + d[i][j][h*2]   + bb.x,
                    hv.y + d[i][j][h*2+1] + bb.y);
            }
        }
}

// =====================================================================
// score: S = aft @ enc^T + epilogue (K=128)
// =====================================================================
__global__ __launch_bounds__(256) void score_tc(
        const float* __restrict__ AFT,
        const float* __restrict__ ENC,
        const float* __restrict__ cur_dist,
        const float* __restrict__ ninf,
        const float* __restrict__ ls,
        const float* __restrict__ palpha,
        float* __restrict__ OUT) {
    __shared__ u16 Ah[128*16], Al[128*16], Bh[128*16], Bl[128*16];
    const int b = blockIdx.z;
    const int p0 = blockIdx.x*128, n0 = blockIdx.y*128;
    const float ps = ls[0]*palpha[0];
    const float* A  = AFT + (size_t)b*PP*EE;
    const float* Eb = ENC + (size_t)b*NN*EE;
    const int tid = threadIdx.x, lane = tid & 31, w = tid >> 5;
    const int wr0 = (w >> 1)*32, wc0 = (w & 1)*64;
    const int qr = lane >> 2, qc = lane & 3;
    float d[2][8][4] = {};

    for (int k0 = 0; k0 < EE; k0 += 16) {
        load_A_bf(A, EE, p0, k0, Ah, Al, tid);
        load_B_direct(Eb, EE, n0, k0, Bh, Bl, tid);
        __syncthreads();
        mma_block128(Ah, Al, Bh, Bl, d, wr0, wc0, qr, qc);
        __syncthreads();
    }
    #pragma unroll
    for (int i = 0; i < 2; i++)
        #pragma unroll
        for (int h = 0; h < 2; h++) {
            int p = p0 + wr0 + i*16 + qr + h*8;
            #pragma unroll
            for (int j = 0; j < 8; j++) {
                int n = n0 + wc0 + j*8 + qc*2;
                size_t o = ((size_t)b*PP + p)*NN + n;
                float2 cd = *(const float2*)&cur_dist[o];
                float2 nm = *(const float2*)&ninf[o];
                float s0 = d[i][j][h*2]  *INV_SQRT_E + ps*cd.x;
                float s1 = d[i][j][h*2+1]*INV_SQRT_E + ps*cd.y;
                *(float2*)&OUT[o] = make_float2(
                    10.f*tanhf(s0) + nm.x, 10.f*tanhf(s1) + nm.y);
            }
        }
}

// ---------------- instance norm over node dim (axis=1) ----------------
__global__ void inorm_kernel(const float* __restrict__ src,
                             float* __restrict__ dst,
                             const float* __restrict__ w,
                             const float* __restrict__ bias) {
    int b = blockIdx.x;
    int e = threadIdx.x;
    int c = threadIdx.y;
    const float* S = src + (size_t)b*NN*EE;
    float s = 0.f, s2 = 0.f;
    for (int n = c*64; n < c*64 + 64; n++) {
        float v = S[(size_t)n*EE + e];
        s += v; s2 += v*v;
    }
    __shared__ float ssum[8][128], ssq[8][128];
    __shared__ float smu[128], srs[128];
    ssum[c][e] = s; ssq[c][e] = s2;
    __syncthreads();
    if (c == 0) {
        float ts = 0.f, t2 = 0.f;
        #pragma unroll
        for (int i = 0; i < 8; i++) { ts += ssum[i][e]; t2 += ssq[i][e]; }
        float mu = ts*(1.f/NN);
        float var = t2*(1.f/NN) - mu*mu;
        smu[e] = mu;
        srs[e] = rsqrtf(var + EPS);
    }
    __syncthreads();
    float mu = smu[e], rs = srs[e], ww = w[e], bb = bias[e];
    float* Dd = dst + (size_t)b*NN*EE;
    for (int n = c*64; n < c*64 + 64; n++) {
        size_t o = (size_t)n*EE + e;
        Dd[o] = (S[o] - mu)*rs*ww + bb;
    }
}

// ---------------- graph mean over nodes ----------------
__global__ void gmean_kernel(const float* __restrict__ X, float* __restrict__ GM) {
    int b = blockIdx.x, e = threadIdx.x, c = threadIdx.y;
    float s = 0.f;
    for (int n = c*64; n < c*64 + 64; n++)
        s += X[((size_t)b*NN + n)*EE + e];
    __shared__ float sm[8][128];
    sm[c][e] = s;
    __syncthreads();
    if (c == 0) {
        float t = 0.f;
        #pragma unroll
        for (int i = 0; i < 8; i++) t += sm[i][e];
        GM[b*EE + e] = t*(1.f/NN);
    }
}

// ---------------- gq = gmean @ dWq[0:E,:] ----------------
__global__ void gq_kernel(const float* __restrict__ GM,
                          const float* __restrict__ dWq,
                          float* __restrict__ GQ) {
    int b = blockIdx.x, e = threadIdx.x;
    float acc = 0.f;
    for (int i = 0; i < EE; i++)
        acc += GM[b*EE + i]*dWq[i*EE + e];
    GQ[b*EE + e] = acc;
}

// ---------------- row softmax over last dim (512) ----------------
__global__ void softmax_kernel(float* __restrict__ OUT) {
    float* row = OUT + (size_t)blockIdx.x*NN;
    int t = threadIdx.x;
    float v[4];
    #pragma unroll
    for (int i = 0; i < 4; i++) v[i] = row[t + i*128];
    float m = fmaxf(fmaxf(v[0], v[1]), fmaxf(v[2], v[3]));
    __shared__ float red[4];
    #pragma unroll
    for (int off = 16; off > 0; off >>= 1)
        m = fmaxf(m, __shfl_xor_sync(0xffffffff, m, off));
    if ((t & 31) == 0) red[t >> 5] = m;
    __syncthreads();
    m = fmaxf(fmaxf(red[0], red[1]), fmaxf(red[2], red[3]));
    __syncthreads();
    float s = 0.f;
    #pragma unroll
    for (int i = 0; i < 4; i++) { v[i] = __expf(v[i] - m); s += v[i]; }
    #pragma unroll
    for (int off = 16; off > 0; off >>= 1)
        s += __shfl_xor_sync(0xffffffff, s, off);
    if ((t & 31) == 0) red[t >> 5] = s;
    __syncthreads();
    s = red[0] + red[1] + red[2] + red[3];
    float inv = 1.f/s;
    #pragma unroll
    for (int i = 0; i < 4; i++) row[t + i*128] = v[i]*inv;
}

// ---------------- launch ----------------
extern "C" void kernel_launch(void* const* d_in, const int* in_sizes, int n_in,
                              void* d_out, int out_size) {
    const float* data      = (const float*)d_in[0];
    const float* dist      = (const float*)d_in[1];
    const float* cur_dist  = (const float*)d_in[2];
    const float* capacity  = (const float*)d_in[3];
    const float* ninf_mask = (const float*)d_in[4];
    const float* log_scale = (const float*)d_in[5];
    const float* emb_W     = (const float*)d_in[6];
    const float* emb_b     = (const float*)d_in[7];
    const float* Wq        = (const float*)d_in[8];
    const float* Wk        = (const float*)d_in[9];
    const float* Wv        = (const float*)d_in[10];
    const float* aft_alpha = (const float*)d_in[11];
    const float* n1_w      = (const float*)d_in[12];
    const float* n1_b      = (const float*)d_in[13];
    const float* ff_W1     = (const float*)d_in[14];
    const float* ff_b1     = (const float*)d_in[15];
    const float* ff_W2     = (const float*)d_in[16];
    const float* ff_b2     = (const float*)d_in[17];
    const float* n2_w      = (const float*)d_in[18];
    const float* n2_b      = (const float*)d_in[19];
    const float* dWq       = (const float*)d_in[20];
    const float* dWk       = (const float*)d_in[21];
    const float* dWv       = (const float*)d_in[22];
    const float* dec_alpha = (const float*)d_in[23];
    const float* p_alpha   = (const float*)d_in[24];
    float* out = (float*)d_out;

    float *x, *y, *h, *sq, *ek, *ekv, *hid, *aft, *gq, *gm;
    cudaGetSymbolAddress((void**)&x,   g_x);
    cudaGetSymbolAddress((void**)&y,   g_y);
    cudaGetSymbolAddress((void**)&h,   g_h);
    cudaGetSymbolAddress((void**)&sq,  g_sq);
    cudaGetSymbolAddress((void**)&ek,  g_ek);
    cudaGetSymbolAddress((void**)&ekv, g_ekv);
    cudaGetSymbolAddress((void**)&hid, g_hid);
    cudaGetSymbolAddress((void**)&aft, g_aft);
    cudaGetSymbolAddress((void**)&gq,  g_gq);
    cudaGetSymbolAddress((void**)&gm,  g_gm);

    embed_kernel<<<M_TOT, EE>>>(data, emb_W, emb_b, x);

    for (int l = 0; l < LLAYERS; l++) {
        qkv_tc<<<M_TOT/128, 256>>>(
            x, Wq + (size_t)l*EE*EE, Wk + (size_t)l*EE*EE, Wv + (size_t)l*EE*EE,
            sq, ek, ekv);
        aft_enc_tc<<<dim3(NN/128, EE/64, BB), 256>>>(
            dist, log_scale, aft_alpha, l, ekv, ek, x, sq, y);
        inorm_kernel<<<BB, dim3(128, 8)>>>(y, h, n1_w + l*EE, n1_b + l*EE);
        ff1_tc<<<dim3(M_TOT/128, FFD/128), 256>>>(
            h, ff_W1 + (size_t)l*EE*FFD, ff_b1 + l*FFD, hid);
        ff2_tc<<<M_TOT/128, 256>>>(
            hid, ff_W2 + (size_t)l*FFD*EE, ff_b2 + l*EE, h, y);
        inorm_kernel<<<BB, dim3(128, 8)>>>(y, x, n2_w + l*EE, n2_b + l*EE);
    }

    // decoder
    deckv_tc<<<M_TOT/128, 256>>>(x, dWk, dWv, ek, ekv);
    gmean_kernel<<<BB, dim3(128, 8)>>>(x, gm);
    gq_kernel<<<BB, 128>>>(gm, dWq, gq);
    dec_aft_tc<<<dim3(PP/128, EE/64, BB), 256>>>(
        cur_dist, ninf_mask, log_scale, dec_alpha, ekv, ek, gq, capacity, dWq, aft);
    score_tc<<<dim3(PP/128, NN/128, BB), 256>>>(
        aft, x, cur_dist, ninf_mask, log_scale, p_alpha, out);
    softmax_kernel<<<BB*PP, 128>>>(out);
}

// round 12
// speedup vs baseline: 1.0561x; 1.0561x over previous
#include <cuda_runtime.h>
#include <cuda_bf16.h>
#include <math.h>

#define BB 64
#define PP 512
#define NN 512
#define EE 128
#define FFD 512
#define LLAYERS 6
#define M_TOT (BB*NN)
#define EPS 1e-5f
#define INV_SQRT_E 0.08838834764831845f

typedef unsigned short u16;
typedef unsigned int   u32;

#define TS 20   /* smem tile row stride in u32 (80B): conflict-free for frag loads */

// ---------------- f32 scratch ----------------
__device__ float g_x  [BB*NN*EE];
__device__ float g_y  [BB*NN*EE];
__device__ float g_h  [BB*NN*EE];
__device__ float g_sq [BB*NN*EE];
__device__ float g_ek [BB*NN*EE];
__device__ float g_ekv[BB*NN*EE];
__device__ float g_gq [BB*EE];
__device__ float g_gm [BB*EE];
// ---------------- bf16 hi/lo scratch ----------------
__device__ u16 g_xH  [M_TOT*EE],  g_xL  [M_TOT*EE];
__device__ u16 g_hH  [M_TOT*EE],  g_hL  [M_TOT*EE];
__device__ u16 g_hidH[M_TOT*FFD], g_hidL[M_TOT*FFD];
__device__ u16 g_aftH[BB*PP*EE],  g_aftL[BB*PP*EE];
__device__ u16 g_ekTH [BB*EE*NN], g_ekTL [BB*EE*NN];
__device__ u16 g_ekvTH[BB*EE*NN], g_ekvTL[BB*EE*NN];
// weights (transposed [n][k])
__device__ u16 g_wqTH[LLAYERS*EE*EE],  g_wqTL[LLAYERS*EE*EE];
__device__ u16 g_wkTH[LLAYERS*EE*EE],  g_wkTL[LLAYERS*EE*EE];
__device__ u16 g_wvTH[LLAYERS*EE*EE],  g_wvTL[LLAYERS*EE*EE];
__device__ u16 g_w1TH[LLAYERS*FFD*EE], g_w1TL[LLAYERS*FFD*EE];
__device__ u16 g_w2TH[LLAYERS*EE*FFD], g_w2TL[LLAYERS*EE*FFD];
__device__ u16 g_dkTH[EE*EE], g_dkTL[EE*EE];
__device__ u16 g_dvTH[EE*EE], g_dvTL[EE*EE];

// ================= helpers =================
__device__ __forceinline__ void cvt_hl(float x, u16& h, u16& l) {
    __nv_bfloat16 bh = __float2bfloat16(x);
    float hf = __bfloat162float(bh);
    __nv_bfloat16 bl = __float2bfloat16(x - hf);
    h = __bfloat16_as_ushort(bh);
    l = __bfloat16_as_ushort(bl);
}
__device__ __forceinline__ void pack_hl(float x, float y, u32& h, u32& l) {
    u16 hx, lx, hy, ly;
    cvt_hl(x, hx, lx); cvt_hl(y, hy, ly);
    h = (u32)hx | ((u32)hy << 16);
    l = (u32)lx | ((u32)ly << 16);
}

#define MMAB(d, a, b)                                                        \
    asm volatile("mma.sync.aligned.m16n8k16.row.col.f32.bf16.bf16.f32 "      \
        "{%0,%1,%2,%3},{%4,%5,%6,%7},{%8,%9},{%0,%1,%2,%3};"                 \
        : "+f"(d[0]), "+f"(d[1]), "+f"(d[2]), "+f"(d[3])                     \
        : "r"(a[0]), "r"(a[1]), "r"(a[2]), "r"(a[3]), "r"(b[0]), "r"(b[1]))

// ---------- tile loaders (BK=32, preconverted bf16 hi/lo sources) ----------
// 128 rows x 32 k: thread t -> row t>>1, half (t&1)*16 bf16
__device__ __forceinline__ void ld_tile128(const u16* __restrict__ GH,
                                           const u16* __restrict__ GL,
                                           size_t ld, int r0, int k0,
                                           u32* SH, u32* SL, int tid) {
    int r = tid >> 1, h8 = (tid & 1)*8;
    const uint4* pH = (const uint4*)(GH + (size_t)(r0 + r)*ld + k0) + (tid & 1)*2;
    const uint4* pL = (const uint4*)(GL + (size_t)(r0 + r)*ld + k0) + (tid & 1)*2;
    uint4 a = pH[0], b = pH[1];
    uint4 c = pL[0], d = pL[1];
    *(uint4*)(SH + r*TS + h8)     = a;
    *((uint4*)(SH + r*TS + h8)+1) = b;
    *(uint4*)(SL + r*TS + h8)     = c;
    *((uint4*)(SL + r*TS + h8)+1) = d;
}

// two 64-row B tiles (ekvT, ekT): threads 0-127 tensor1, 128-255 tensor2
__device__ __forceinline__ void ld_tile64x2(const u16* __restrict__ G1H,
                                            const u16* __restrict__ G1L,
                                            const u16* __restrict__ G2H,
                                            const u16* __restrict__ G2L,
                                            size_t ld, int n0, int k0,
                                            u32* B1H, u32* B1L, u32* B2H, u32* B2L,
                                            int tid) {
    int t = tid & 127;
    int r = t >> 1, h8 = (t & 1)*8;
    const u16* srcH; const u16* srcL; u32* dH; u32* dL;
    if (tid < 128) { srcH = G1H; srcL = G1L; dH = B1H; dL = B1L; }
    else           { srcH = G2H; srcL = G2L; dH = B2H; dL = B2L; }
    const uint4* pH = (const uint4*)(srcH + (size_t)(n0 + r)*ld + k0) + (t & 1)*2;
    const uint4* pL = (const uint4*)(srcL + (size_t)(n0 + r)*ld + k0) + (t & 1)*2;
    uint4 a = pH[0], b = pH[1];
    uint4 c = pL[0], d = pL[1];
    *(uint4*)(dH + r*TS + h8)     = a;
    *((uint4*)(dH + r*TS + h8)+1) = b;
    *(uint4*)(dL + r*TS + h8)     = c;
    *((uint4*)(dL + r*TS + h8)+1) = d;
}

// A = exp(s*G) from f32 (128 rows x 32 k)
__device__ __forceinline__ void ld_Aexp(const float* __restrict__ G, size_t ld,
                                        int m0, int k0, u32* SH, u32* SL,
                                        int tid, float s) {
    int r = tid >> 1, c = (tid & 1)*16;
    const float* p = G + (size_t)(m0 + r)*ld + k0 + c;
    float v[16];
    #pragma unroll
    for (int q = 0; q < 4; q++) {
        float4 f = *(const float4*)(p + q*4);
        v[q*4+0]=f.x; v[q*4+1]=f.y; v[q*4+2]=f.z; v[q*4+3]=f.w;
    }
    u32 h[8], l[8];
    #pragma unroll
    for (int q = 0; q < 8; q++)
        pack_hl(__expf(s*v[2*q]), __expf(s*v[2*q+1]), h[q], l[q]);
    u32* dh = SH + r*TS + (tid & 1)*8;
    u32* dl = SL + r*TS + (tid & 1)*8;
    *(uint4*)dh = *(uint4*)h; *((uint4*)dh+1) = *(uint4*)(h+4);
    *(uint4*)dl = *(uint4*)l; *((uint4*)dl+1) = *(uint4*)(l+4);
}

// A = exp(s*G + M)
__device__ __forceinline__ void ld_Aexpmask(const float* __restrict__ G,
                                            const float* __restrict__ Msk, size_t ld,
                                            int m0, int k0, u32* SH, u32* SL,
                                            int tid, float s) {
    int r = tid >> 1, c = (tid & 1)*16;
    size_t off = (size_t)(m0 + r)*ld + k0 + c;
    float v[16];
    #pragma unroll
    for (int q = 0; q < 4; q++) {
        float4 f = *(const float4*)(G + off + q*4);
        float4 m = *(const float4*)(Msk + off + q*4);
        v[q*4+0]=s*f.x+m.x; v[q*4+1]=s*f.y+m.y; v[q*4+2]=s*f.z+m.z; v[q*4+3]=s*f.w+m.w;
    }
    u32 h[8], l[8];
    #pragma unroll
    for (int q = 0; q < 8; q++)
        pack_hl(__expf(v[2*q]), __expf(v[2*q+1]), h[q], l[q]);
    u32* dh = SH + r*TS + (tid & 1)*8;
    u32* dl = SL + r*TS + (tid & 1)*8;
    *(uint4*)dh = *(uint4*)h; *((uint4*)dh+1) = *(uint4*)(h+4);
    *(uint4*)dl = *(uint4*)l; *((uint4*)dl+1) = *(uint4*)(l+4);
}

// ---------- warp mma over a 128x32 A tile, BN=128 ----------
__device__ __forceinline__ void mma128(const u32* AH, const u32* AL,
                                       const u32* BH, const u32* BL,
                                       float d[2][8][4],
                                       int wr0, int wc0, int qr, int qc) {
    #pragma unroll
    for (int ks = 0; ks < 2; ks++) {
        int ku = ks*8;
        u32 ah[2][4], al[2][4];
        #pragma unroll
        for (int i = 0; i < 2; i++) {
            int r = wr0 + i*16 + qr;
            ah[i][0]=AH[r*TS+ku+qc];     ah[i][1]=AH[(r+8)*TS+ku+qc];
            ah[i][2]=AH[r*TS+ku+qc+4];   ah[i][3]=AH[(r+8)*TS+ku+qc+4];
            al[i][0]=AL[r*TS+ku+qc];     al[i][1]=AL[(r+8)*TS+ku+qc];
            al[i][2]=AL[r*TS+ku+qc+4];   al[i][3]=AL[(r+8)*TS+ku+qc+4];
        }
        #pragma unroll
        for (int j = 0; j < 8; j++) {
            int n = wc0 + j*8 + qr;
            u32 bh[2] = {BH[n*TS+ku+qc], BH[n*TS+ku+qc+4]};
            u32 bl[2] = {BL[n*TS+ku+qc], BL[n*TS+ku+qc+4]};
            #pragma unroll
            for (int i = 0; i < 2; i++) {
                MMAB(d[i][j], ah[i], bh);
                MMAB(d[i][j], al[i], bh);
                MMAB(d[i][j], ah[i], bl);
            }
        }
    }
}

// ---------- warp mma, BN=64 dual B (num/den) ----------
__device__ __forceinline__ void mma64x2(const u32* AH, const u32* AL,
                                        const u32* B1H, const u32* B1L,
                                        const u32* B2H, const u32* B2L,
                                        float d1[2][4][4], float d2[2][4][4],
                                        int wr0, int wc0, int qr, int qc) {
    #pragma unroll
    for (int ks = 0; ks < 2; ks++) {
        int ku = ks*8;
        u32 ah[2][4], al[2][4];
        #pragma unroll
        for (int i = 0; i < 2; i++) {
            int r = wr0 + i*16 + qr;
            ah[i][0]=AH[r*TS+ku+qc];     ah[i][1]=AH[(r+8)*TS+ku+qc];
            ah[i][2]=AH[r*TS+ku+qc+4];   ah[i][3]=AH[(r+8)*TS+ku+qc+4];
            al[i][0]=AL[r*TS+ku+qc];     al[i][1]=AL[(r+8)*TS+ku+qc];
            al[i][2]=AL[r*TS+ku+qc+4];   al[i][3]=AL[(r+8)*TS+ku+qc+4];
        }
        #pragma unroll
        for (int j = 0; j < 4; j++) {
            int n = wc0 + j*8 + qr;
            {
                u32 bh[2] = {B1H[n*TS+ku+qc], B1H[n*TS+ku+qc+4]};
                u32 bl[2] = {B1L[n*TS+ku+qc], B1L[n*TS+ku+qc+4]};
                #pragma unroll
                for (int i = 0; i < 2; i++) {
                    MMAB(d1[i][j], ah[i], bh);
                    MMAB(d1[i][j], al[i], bh);
                    MMAB(d1[i][j], ah[i], bl);
                }
            }
            {
                u32 bh[2] = {B2H[n*TS+ku+qc], B2H[n*TS+ku+qc+4]};
                u32 bl[2] = {B2L[n*TS+ku+qc], B2L[n*TS+ku+qc+4]};
                #pragma unroll
                for (int i = 0; i < 2; i++) {
                    MMAB(d2[i][j], ah[i], bh);
                    MMAB(d2[i][j], al[i], bh);
                    MMAB(d2[i][j], ah[i], bl);
                }
            }
        }
    }
}

// =====================================================================
// weight transpose-convert: src f32 [K][N] -> dstH/dstL bf16 [N][K]
// grid (N/32, K/32), 256 threads
// =====================================================================
__global__ void wconv_kernel(const float* __restrict__ src,
                             u16* __restrict__ dH, u16* __restrict__ dL,
                             int K, int N) {
    __shared__ float t[32][33];
    int n0 = blockIdx.x*32, k0 = blockIdx.y*32;
    int tr = threadIdx.x >> 3, tc4 = (threadIdx.x & 7)*4;
    float4 v = *(const float4*)&src[(size_t)(k0+tr)*N + n0 + tc4];
    t[tc4+0][tr] = v.x; t[tc4+1][tr] = v.y;
    t[tc4+2][tr] = v.z; t[tc4+3][tr] = v.w;
    __syncthreads();
    int r = threadIdx.x >> 3, c4 = (threadIdx.x & 7)*4;
    u16 h[4], l[4];
    #pragma unroll
    for (int i = 0; i < 4; i++) cvt_hl(t[r][c4+i], h[i], l[i]);
    size_t o = (size_t)(n0+r)*K + k0 + c4;
    *(uint2*)&dH[o] = *(uint2*)h;
    *(uint2*)&dL[o] = *(uint2*)l;
}

// =====================================================================
// ek/ekv transpose-convert: src f32 [b][node][e] -> dst bf16 [b][e][node]
// grid (EE/32, NN/32, BB), 256 threads
// =====================================================================
__global__ void ekconv_kernel(const float* __restrict__ ek,
                              const float* __restrict__ ekv,
                              u16* __restrict__ ekTH, u16* __restrict__ ekTL,
                              u16* __restrict__ ekvTH, u16* __restrict__ ekvTL) {
    __shared__ float t1[32][33], t2[32][33];
    int b = blockIdx.z;
    int e0 = blockIdx.x*32, nd0 = blockIdx.y*32;
    const float* S1 = ek  + (size_t)b*NN*EE;
    const float* S2 = ekv + (size_t)b*NN*EE;
    int tr = threadIdx.x >> 3, tc4 = (threadIdx.x & 7)*4;
    size_t so = (size_t)(nd0+tr)*EE + e0 + tc4;
    float4 v1 = *(const float4*)&S1[so];
    float4 v2 = *(const float4*)&S2[so];
    t1[tc4+0][tr]=v1.x; t1[tc4+1][tr]=v1.y; t1[tc4+2][tr]=v1.z; t1[tc4+3][tr]=v1.w;
    t2[tc4+0][tr]=v2.x; t2[tc4+1][tr]=v2.y; t2[tc4+2][tr]=v2.z; t2[tc4+3][tr]=v2.w;
    __syncthreads();
    int r = threadIdx.x >> 3, c4 = (threadIdx.x & 7)*4;
    size_t o = (size_t)b*EE*NN + (size_t)(e0+r)*NN + nd0 + c4;
    u16 h[4], l[4];
    #pragma unroll
    for (int i = 0; i < 4; i++) cvt_hl(t1[r][c4+i], h[i], l[i]);
    *(uint2*)&ekTH[o] = *(uint2*)h; *(uint2*)&ekTL[o] = *(uint2*)l;
    #pragma unroll
    for (int i = 0; i < 4; i++) cvt_hl(t2[r][c4+i], h[i], l[i]);
    *(uint2*)&ekvTH[o] = *(uint2*)h; *(uint2*)&ekvTL[o] = *(uint2*)l;
}

// ---------------- embedding (also writes bf16 hi/lo) ----------------
__global__ void embed_kernel(const float* __restrict__ data,
                             const float* __restrict__ W,
                             const float* __restrict__ bias,
                             float* __restrict__ X,
                             u16* __restrict__ XH, u16* __restrict__ XL) {
    int idx = blockIdx.x;
    int e   = threadIdx.x;
    float d0 = data[idx*2+0], d1 = data[idx*2+1];
    float v = d0*W[e] + d1*W[EE+e] + bias[e];
    size_t o = (size_t)idx*EE + e;
    X[o] = v;
    u16 h, l; cvt_hl(v, h, l);
    XH[o] = h; XL[o] = l;
}

// =====================================================================
// qkv: 3 passes over preconverted A(x) and B(weightsT); BM=128, BN=128
// =====================================================================
__global__ __launch_bounds__(256) void qkv_tc(
        const u16* __restrict__ XH, const u16* __restrict__ XL,
        const u16* __restrict__ WqH, const u16* __restrict__ WqL,
        const u16* __restrict__ WkH, const u16* __restrict__ WkL,
        const u16* __restrict__ WvH, const u16* __restrict__ WvL,
        float* __restrict__ SQ, float* __restrict__ EK, float* __restrict__ EKV) {
    __shared__ u32 AH[128*TS], AL[128*TS], BH[128*TS], BL[128*TS];
    const int tid = threadIdx.x, lane = tid & 31, w = tid >> 5;
    const int wr0 = (w >> 1)*32, wc0 = (w & 1)*64;
    const int qr = lane >> 2, qc = lane & 3;
    const int m0 = blockIdx.x*128;

    for (int pass = 0; pass < 3; pass++) {
        const u16* BgH = (pass == 0) ? WqH : (pass == 1) ? WkH : WvH;
        const u16* BgL = (pass == 0) ? WqL : (pass == 1) ? WkL : WvL;
        float d[2][8][4] = {};
        for (int k0 = 0; k0 < EE; k0 += 32) {
            ld_tile128(XH, XL, EE, m0, k0, AH, AL, tid);
            ld_tile128(BgH, BgL, EE, 0, k0, BH, BL, tid);
            __syncthreads();
            mma128(AH, AL, BH, BL, d, wr0, wc0, qr, qc);
            __syncthreads();
        }
        #pragma unroll
        for (int i = 0; i < 2; i++)
            #pragma unroll
            for (int h = 0; h < 2; h++) {
                int row = m0 + wr0 + i*16 + qr + h*8;
                #pragma unroll
                for (int j = 0; j < 8; j++) {
                    int col = wc0 + j*8 + qc*2;
                    size_t o = (size_t)row*EE + col;
                    float v0 = d[i][j][h*2], v1 = d[i][j][h*2+1];
                    if (pass == 0) {
                        *(float2*)&SQ[o] = make_float2(
                            1.f/(1.f + __expf(-v0)), 1.f/(1.f + __expf(-v1)));
                    } else if (pass == 1) {
                        *(float2*)&EK[o] = make_float2(__expf(v0), __expf(v1));
                    } else {
                        float2 e = *(const float2*)&EK[o];
                        *(float2*)&EKV[o] = make_float2(e.x*v0, e.y*v1);
                    }
                }
            }
    }
}

// =====================================================================
// deckv: 2 passes
// =====================================================================
__global__ __launch_bounds__(256) void deckv_tc(
        const u16* __restrict__ XH, const u16* __restrict__ XL,
        const u16* __restrict__ WkH, const u16* __restrict__ WkL,
        const u16* __restrict__ WvH, const u16* __restrict__ WvL,
        float* __restrict__ EK, float* __restrict__ EKV) {
    __shared__ u32 AH[128*TS], AL[128*TS], BH[128*TS], BL[128*TS];
    const int tid = threadIdx.x, lane = tid & 31, w = tid >> 5;
    const int wr0 = (w >> 1)*32, wc0 = (w & 1)*64;
    const int qr = lane >> 2, qc = lane & 3;
    const int m0 = blockIdx.x*128;

    for (int pass = 0; pass < 2; pass++) {
        const u16* BgH = (pass == 0) ? WkH : WvH;
        const u16* BgL = (pass == 0) ? WkL : WvL;
        float d[2][8][4] = {};
        for (int k0 = 0; k0 < EE; k0 += 32) {
            ld_tile128(XH, XL, EE, m0, k0, AH, AL, tid);
            ld_tile128(BgH, BgL, EE, 0, k0, BH, BL, tid);
            __syncthreads();
            mma128(AH, AL, BH, BL, d, wr0, wc0, qr, qc);
            __syncthreads();
        }
        #pragma unroll
        for (int i = 0; i < 2; i++)
            #pragma unroll
            for (int h = 0; h < 2; h++) {
                int row = m0 + wr0 + i*16 + qr + h*8;
                #pragma unroll
                for (int j = 0; j < 8; j++) {
                    int col = wc0 + j*8 + qc*2;
                    size_t o = (size_t)row*EE + col;
                    float v0 = d[i][j][h*2], v1 = d[i][j][h*2+1];
                    if (pass == 0) {
                        *(float2*)&EK[o] = make_float2(__expf(v0), __expf(v1));
                    } else {
                        float2 e = *(const float2*)&EK[o];
                        *(float2*)&EKV[o] = make_float2(e.x*v0, e.y*v1);
                    }
                }
            }
    }
}

// =====================================================================
// encoder AFT: BM=128 nodes, BN=64 of E, dual accumulation, K=512, BK=32
// =====================================================================
__global__ __launch_bounds__(256) void aft_enc_tc(
        const float* __restrict__ dist,
        const float* __restrict__ ls,
        const float* __restrict__ alpha, int l,
        const u16* __restrict__ EKVTH, const u16* __restrict__ EKVTL,
        const u16* __restrict__ EKTH,  const u16* __restrict__ EKTL,
        const float* __restrict__ X,
        const float* __restrict__ SQ,
        float* __restrict__ Y) {
    __shared__ u32 AH[128*TS], AL[128*TS];
    __shared__ u32 B1H[64*TS], B1L[64*TS], B2H[64*TS], B2L[64*TS];
    const int b = blockIdx.z;
    const int m0 = blockIdx.x*128, n0 = blockIdx.y*64;
    const float s = ls[0]*alpha[l];
    const float* D = dist + (size_t)b*NN*NN;
    const u16* T1H = EKVTH + (size_t)b*EE*NN;
    const u16* T1L = EKVTL + (size_t)b*EE*NN;
    const u16* T2H = EKTH  + (size_t)b*EE*NN;
    const u16* T2L = EKTL  + (size_t)b*EE*NN;
    const int tid = threadIdx.x, lane = tid & 31, w = tid >> 5;
    const int wr0 = (w >> 1)*32, wc0 = (w & 1)*32;
    const int qr = lane >> 2, qc = lane & 3;
    float d1[2][4][4] = {}, d2[2][4][4] = {};

    for (int k0 = 0; k0 < NN; k0 += 32) {
        ld_Aexp(D, NN, m0, k0, AH, AL, tid, s);
        ld_tile64x2(T1H, T1L, T2H, T2L, NN, n0, k0, B1H, B1L, B2H, B2L, tid);
        __syncthreads();
        mma64x2(AH, AL, B1H, B1L, B2H, B2L, d1, d2, wr0, wc0, qr, qc);
        __syncthreads();
    }
    #pragma unroll
    for (int i = 0; i < 2; i++)
        #pragma unroll
        for (int h = 0; h < 2; h++) {
            int row = m0 + wr0 + i*16 + qr + h*8;
            #pragma unroll
            for (int j = 0; j < 4; j++) {
                int col = n0 + wc0 + j*8 + qc*2;
                size_t o = ((size_t)b*NN + row)*EE + col;
                float2 xv = *(const float2*)&X[o];
                float2 sv = *(const float2*)&SQ[o];
                float n0v = d1[i][j][h*2], n1v = d1[i][j][h*2+1];
                float de0 = d2[i][j][h*2], de1 = d2[i][j][h*2+1];
                *(float2*)&Y[o] = make_float2(
                    xv.x + sv.x*(n0v/de0), xv.y + sv.y*(n1v/de1));
            }
        }
}

// =====================================================================
// decoder AFT (writes aft bf16 hi/lo only)
// =====================================================================
__global__ __launch_bounds__(256) void dec_aft_tc(
        const float* __restrict__ cur_dist,
        const float* __restrict__ ninf,
        const float* __restrict__ ls,
        const float* __restrict__ dalpha,
        const u16* __restrict__ EKVTH, const u16* __restrict__ EKVTL,
        const u16* __restrict__ EKTH,  const u16* __restrict__ EKTL,
        const float* __restrict__ GQ,
        const float* __restrict__ cap,
        const float* __restrict__ dWq,
        u16* __restrict__ AFTH, u16* __restrict__ AFTL) {
    __shared__ u32 AH[128*TS], AL[128*TS];
    __shared__ u32 B1H[64*TS], B1L[64*TS], B2H[64*TS], B2L[64*TS];
    const int b = blockIdx.z;
    const int m0 = blockIdx.x*128, n0 = blockIdx.y*64;
    const float s = ls[0]*dalpha[0];
    const float* CD = cur_dist + (size_t)b*PP*NN;
    const float* NM = ninf     + (size_t)b*PP*NN;
    const u16* T1H = EKVTH + (size_t)b*EE*NN;
    const u16* T1L = EKVTL + (size_t)b*EE*NN;
    const u16* T2H = EKTH  + (size_t)b*EE*NN;
    const u16* T2L = EKTL  + (size_t)b*EE*NN;
    const int tid = threadIdx.x, lane = tid & 31, w = tid >> 5;
    const int wr0 = (w >> 1)*32, wc0 = (w & 1)*32;
    const int qr = lane >> 2, qc = lane & 3;
    float d1[2][4][4] = {}, d2[2][4][4] = {};

    for (int k0 = 0; k0 < NN; k0 += 32) {
        ld_Aexpmask(CD, NM, NN, m0, k0, AH, AL, tid, s);
        ld_tile64x2(T1H, T1L, T2H, T2L, NN, n0, k0, B1H, B1L, B2H, B2L, tid);
        __syncthreads();
        mma64x2(AH, AL, B1H, B1L, B2H, B2L, d1, d2, wr0, wc0, qr, qc);
        __syncthreads();
    }
    #pragma unroll
    for (int i = 0; i < 2; i++)
        #pragma unroll
        for (int h = 0; h < 2; h++) {
            int p = m0 + wr0 + i*16 + qr + h*8;
            float cv = cap[(size_t)b*PP + p];
            #pragma unroll
            for (int j = 0; j < 4; j++) {
                int col = n0 + wc0 + j*8 + qc*2;
                float2 gq2 = *(const float2*)&GQ[b*EE + col];
                float2 wq2 = *(const float2*)&dWq[EE*EE + col];
                float q0 = gq2.x + cv*wq2.x;
                float q1 = gq2.y + cv*wq2.y;
                float sg0 = 1.f/(1.f + __expf(-q0));
                float sg1 = 1.f/(1.f + __expf(-q1));
                float v0 = sg0*(d1[i][j][h*2]  /d2[i][j][h*2]);
                float v1 = sg1*(d1[i][j][h*2+1]/d2[i][j][h*2+1]);
                size_t o = ((size_t)b*PP + p)*EE + col;
                u32 hh, ll; pack_hl(v0, v1, hh, ll);
                *(u32*)&AFTH[o] = hh;
                *(u32*)&AFTL[o] = ll;
            }
        }
}

// =====================================================================
// FF1: hid = relu(h@W1 + b1) -> bf16 hi/lo only
// =====================================================================
__global__ __launch_bounds__(256) void ff1_tc(
        const u16* __restrict__ HH, const u16* __restrict__ HL,
        const u16* __restrict__ W1H, const u16* __restrict__ W1L,
        const float* __restrict__ b1,
        u16* __restrict__ HIDH, u16* __restrict__ HIDL) {
    __shared__ u32 AH[128*TS], AL[128*TS], BH[128*TS], BL[128*TS];
    const int tid = threadIdx.x, lane = tid & 31, w = tid >> 5;
    const int wr0 = (w >> 1)*32, wc0 = (w & 1)*64;
    const int qr = lane >> 2, qc = lane & 3;
    const int m0 = blockIdx.x*128, n0 = blockIdx.y*128;
    float d[2][8][4] = {};

    for (int k0 = 0; k0 < EE; k0 += 32) {
        ld_tile128(HH, HL, EE, m0, k0, AH, AL, tid);
        ld_tile128(W1H, W1L, EE, n0, k0, BH, BL, tid);
        __syncthreads();
        mma128(AH, AL, BH, BL, d, wr0, wc0, qr, qc);
        __syncthreads();
    }
    #pragma unroll
    for (int i = 0; i < 2; i++)
        #pragma unroll
        for (int h = 0; h < 2; h++) {
            int row = m0 + wr0 + i*16 + qr + h*8;
            #pragma unroll
            for (int j = 0; j < 8; j++) {
                int col = n0 + wc0 + j*8 + qc*2;
                float2 bb = *(const float2*)&b1[col];
                float v0 = fmaxf(d[i][j][h*2]   + bb.x, 0.f);
                float v1 = fmaxf(d[i][j][h*2+1] + bb.y, 0.f);
                size_t o = (size_t)row*FFD + col;
                u32 hh, ll; pack_hl(v0, v1, hh, ll);
                *(u32*)&HIDH[o] = hh;
                *(u32*)&HIDL[o] = ll;
            }
        }
}

// =====================================================================
// FF2: y = h + hid@W2 + b2  (K=512)
// =====================================================================
__global__ __launch_bounds__(256) void ff2_tc(
        const u16* __restrict__ HIDH, const u16* __restrict__ HIDL,
        const u16* __restrict__ W2H, const u16* __restrict__ W2L,
        const float* __restrict__ b2,
        const float* __restrict__ H,
        float* __restrict__ Y) {
    __shared__ u32 AH[128*TS], AL[128*TS], BH[128*TS], BL[128*TS];
    const int tid = threadIdx.x, lane = tid & 31, w = tid >> 5;
    const int wr0 = (w >> 1)*32, wc0 = (w & 1)*64;
    const int qr = lane >> 2, qc = lane & 3;
    const int m0 = blockIdx.x*128;
    float d[2][8][4] = {};

    for (int k0 = 0; k0 < FFD; k0 += 32) {
        ld_tile128(HIDH, HIDL, FFD, m0, k0, AH, AL, tid);
        ld_tile128(W2H, W2L, FFD, 0, k0, BH, BL, tid);
        __syncthreads();
        mma128(AH, AL, BH, BL, d, wr0, wc0, qr, qc);
        __syncthreads();
    }
    #pragma unroll
    for (int i = 0; i < 2; i++)
        #pragma unroll
        for (int h = 0; h < 2; h++) {
            int row = m0 + wr0 + i*16 + qr + h*8;
            #pragma unroll
            for (int j = 0; j < 8; j++) {
                int col = wc0 + j*8 + qc*2;
                float2 bb = *(const float2*)&b2[col];
                size_t o = (size_t)row*EE + col;
                float2 hv = *(const float2*)&H[o];
                *(float2*)&Y[o] = make_float2(
                    hv.x + d[i][j][h*2]   + bb.x,
                    hv.y + d[i][j][h*2+1] + bb.y);
            }
        }
}

// =====================================================================
// score: S = aft @ enc^T + epilogue (K=128); A=aft bf16, B=x bf16 [n][e]
// =====================================================================
__global__ __launch_bounds__(256) void score_tc(
        const u16* __restrict__ AFTH, const u16* __restrict__ AFTL,
        const u16* __restrict__ XH, const u16* __restrict__ XL,
        const float* __restrict__ cur_dist,
        const float* __restrict__ ninf,
        const float* __restrict__ ls,
        const float* __restrict__ palpha,
        float* __restrict__ OUT) {
    __shared__ u32 AH[128*TS], AL[128*TS], BH[128*TS], BL[128*TS];
    const int b = blockIdx.z;
    const int p0 = blockIdx.x*128, n0 = blockIdx.y*128;
    const float ps = ls[0]*palpha[0];
    const u16* AgH = AFTH + (size_t)b*PP*EE;
    const u16* AgL = AFTL + (size_t)b*PP*EE;
    const u16* BgH = XH + (size_t)b*NN*EE;
    const u16* BgL = XL + (size_t)b*NN*EE;
    const int tid = threadIdx.x, lane = tid & 31, w = tid >> 5;
    const int wr0 = (w >> 1)*32, wc0 = (w & 1)*64;
    const int qr = lane >> 2, qc = lane & 3;
    float d[2][8][4] = {};

    for (int k0 = 0; k0 < EE; k0 += 32) {
        ld_tile128(AgH, AgL, EE, p0, k0, AH, AL, tid);
        ld_tile128(BgH, BgL, EE, n0, k0, BH, BL, tid);
        __syncthreads();
        mma128(AH, AL, BH, BL, d, wr0, wc0, qr, qc);
        __syncthreads();
    }
    #pragma unroll
    for (int i = 0; i < 2; i++)
        #pragma unroll
        for (int h = 0; h < 2; h++) {
            int p = p0 + wr0 + i*16 + qr + h*8;
            #pragma unroll
            for (int j = 0; j < 8; j++) {
                int n = n0 + wc0 + j*8 + qc*2;
                size_t o = ((size_t)b*PP + p)*NN + n;
                float2 cd = *(const float2*)&cur_dist[o];
                float2 nm = *(const float2*)&ninf[o];
                float s0 = d[i][j][h*2]  *INV_SQRT_E + ps*cd.x;
                float s1 = d[i][j][h*2+1]*INV_SQRT_E + ps*cd.y;
                *(float2*)&OUT[o] = make_float2(
                    10.f*tanhf(s0) + nm.x, 10.f*tanhf(s1) + nm.y);
            }
        }
}

// ---------------- instance norm (also emits bf16 hi/lo) ----------------
__global__ void inorm_kernel(const float* __restrict__ src,
                             float* __restrict__ dst,
                             u16* __restrict__ dstH, u16* __restrict__ dstL,
                             const float* __restrict__ w,
                             const float* __restrict__ bias) {
    int b = blockIdx.x;
    int e = threadIdx.x;
    int c = threadIdx.y;
    const float* S = src + (size_t)b*NN*EE;
    float s = 0.f, s2 = 0.f;
    for (int n = c*64; n < c*64 + 64; n++) {
        float v = S[(size_t)n*EE + e];
        s += v; s2 += v*v;
    }
    __shared__ float ssum[8][128], ssq[8][128];
    __shared__ float smu[128], srs[128];
    ssum[c][e] = s; ssq[c][e] = s2;
    __syncthreads();
    if (c == 0) {
        float ts = 0.f, t2 = 0.f;
        #pragma unroll
        for (int i = 0; i < 8; i++) { ts += ssum[i][e]; t2 += ssq[i][e]; }
        float mu = ts*(1.f/NN);
        float var = t2*(1.f/NN) - mu*mu;
        smu[e] = mu;
        srs[e] = rsqrtf(var + EPS);
    }
    __syncthreads();
    float mu = smu[e], rs = srs[e], ww = w[e], bb = bias[e];
    size_t base = (size_t)b*NN*EE;
    for (int n = c*64; n < c*64 + 64; n++) {
        size_t o = base + (size_t)n*EE + e;
        float v = (S[(size_t)n*EE + e] - mu)*rs*ww + bb;
        dst[o - base + base] = v;  // dst offset by caller? no: dst is full array
        dst[o] = v;
        u16 h, l; cvt_hl(v, h, l);
        dstH[o] = h; dstL[o] = l;
    }
}

// ---------------- graph mean over nodes ----------------
__global__ void gmean_kernel(const float* __restrict__ X, float* __restrict__ GM) {
    int b = blockIdx.x, e = threadIdx.x, c = threadIdx.y;
    float s = 0.f;
    for (int n = c*64; n < c*64 + 64; n++)
        s += X[((size_t)b*NN + n)*EE + e];
    __shared__ float sm[8][128];
    sm[c][e] = s;
    __syncthreads();
    if (c == 0) {
        float t = 0.f;
        #pragma unroll
        for (int i = 0; i < 8; i++) t += sm[i][e];
        GM[b*EE + e] = t*(1.f/NN);
    }
}

// ---------------- gq = gmean @ dWq[0:E,:] ----------------
__global__ void gq_kernel(const float* __restrict__ GM,
                          const float* __restrict__ dWq,
                          float* __restrict__ GQ) {
    int b = blockIdx.x, e = threadIdx.x;
    float acc = 0.f;
    for (int i = 0; i < EE; i++)
        acc += GM[b*EE + i]*dWq[i*EE + e];
    GQ[b*EE + e] = acc;
}

// ---------------- row softmax over last dim (512) ----------------
__global__ void softmax_kernel(float* __restrict__ OUT) {
    float* row = OUT + (size_t)blockIdx.x*NN;
    int t = threadIdx.x;
    float v[4];
    #pragma unroll
    for (int i = 0; i < 4; i++) v[i] = row[t + i*128];
    float m = fmaxf(fmaxf(v[0], v[1]), fmaxf(v[2], v[3]));
    __shared__ float red[4];
    #pragma unroll
    for (int off = 16; off > 0; off >>= 1)
        m = fmaxf(m, __shfl_xor_sync(0xffffffff, m, off));
    if ((t & 31) == 0) red[t >> 5] = m;
    __syncthreads();
    m = fmaxf(fmaxf(red[0], red[1]), fmaxf(red[2], red[3]));
    __syncthreads();
    float s = 0.f;
    #pragma unroll
    for (int i = 0; i < 4; i++) { v[i] = __expf(v[i] - m); s += v[i]; }
    #pragma unroll
    for (int off = 16; off > 0; off >>= 1)
        s += __shfl_xor_sync(0xffffffff, s, off);
    if ((t & 31) == 0) red[t >> 5] = s;
    __syncthreads();
    s = red[0] + red[1] + red[2] + red[3];
    float inv = 1.f/s;
    #pragma unroll
    for (int i = 0; i < 4; i++) row[t + i*128] = v[i]*inv;
}

// ---------------- launch ----------------
extern "C" void kernel_launch(void* const* d_in, const int* in_sizes, int n_in,
                              void* d_out, int out_size) {
    const float* data      = (const float*)d_in[0];
    const float* dist      = (const float*)d_in[1];
    const float* cur_dist  = (const float*)d_in[2];
    const float* capacity  = (const float*)d_in[3];
    const float* ninf_mask = (const float*)d_in[4];
    const float* log_scale = (const float*)d_in[5];
    const float* emb_W     = (const float*)d_in[6];
    const float* emb_b     = (const float*)d_in[7];
    const float* Wq        = (const float*)d_in[8];
    const float* Wk        = (const float*)d_in[9];
    const float* Wv        = (const float*)d_in[10];
    const float* aft_alpha = (const float*)d_in[11];
    const float* n1_w      = (const float*)d_in[12];
    const float* n1_b      = (const float*)d_in[13];
    const float* ff_W1     = (const float*)d_in[14];
    const float* ff_b1     = (const float*)d_in[15];
    const float* ff_W2     = (const float*)d_in[16];
    const float* ff_b2     = (const float*)d_in[17];
    const float* n2_w      = (const float*)d_in[18];
    const float* n2_b      = (const float*)d_in[19];
    const float* dWq       = (const float*)d_in[20];
    const float* dWk       = (const float*)d_in[21];
    const float* dWv       = (const float*)d_in[22];
    const float* dec_alpha = (const float*)d_in[23];
    const float* p_alpha   = (const float*)d_in[24];
    float* out = (float*)d_out;

    float *x, *y, *h, *sq, *ek, *ekv, *gq, *gm;
    cudaGetSymbolAddress((void**)&x,   g_x);
    cudaGetSymbolAddress((void**)&y,   g_y);
    cudaGetSymbolAddress((void**)&h,   g_h);
    cudaGetSymbolAddress((void**)&sq,  g_sq);
    cudaGetSymbolAddress((void**)&ek,  g_ek);
    cudaGetSymbolAddress((void**)&ekv, g_ekv);
    cudaGetSymbolAddress((void**)&gq,  g_gq);
    cudaGetSymbolAddress((void**)&gm,  g_gm);

    u16 *xH,*xL,*hH,*hL,*hidH,*hidL,*aftH,*aftL;
    u16 *ekTH,*ekTL,*ekvTH,*ekvTL;
    u16 *wqTH,*wqTL,*wkTH,*wkTL,*wvTH,*wvTL,*w1TH,*w1TL,*w2TH,*w2TL;
    u16 *dkTH,*dkTL,*dvTH,*dvTL;
    cudaGetSymbolAddress((void**)&xH,   g_xH);   cudaGetSymbolAddress((void**)&xL,   g_xL);
    cudaGetSymbolAddress((void**)&hH,   g_hH);   cudaGetSymbolAddress((void**)&hL,   g_hL);
    cudaGetSymbolAddress((void**)&hidH, g_hidH); cudaGetSymbolAddress((void**)&hidL, g_hidL);
    cudaGetSymbolAddress((void**)&aftH, g_aftH); cudaGetSymbolAddress((void**)&aftL, g_aftL);
    cudaGetSymbolAddress((void**)&ekTH, g_ekTH); cudaGetSymbolAddress((void**)&ekTL, g_ekTL);
    cudaGetSymbolAddress((void**)&ekvTH,g_ekvTH);cudaGetSymbolAddress((void**)&ekvTL,g_ekvTL);
    cudaGetSymbolAddress((void**)&wqTH, g_wqTH); cudaGetSymbolAddress((void**)&wqTL, g_wqTL);
    cudaGetSymbolAddress((void**)&wkTH, g_wkTH); cudaGetSymbolAddress((void**)&wkTL, g_wkTL);
    cudaGetSymbolAddress((void**)&wvTH, g_wvTH); cudaGetSymbolAddress((void**)&wvTL, g_wvTL);
    cudaGetSymbolAddress((void**)&w1TH, g_w1TH); cudaGetSymbolAddress((void**)&w1TL, g_w1TL);
    cudaGetSymbolAddress((void**)&w2TH, g_w2TH); cudaGetSymbolAddress((void**)&w2TL, g_w2TL);
    cudaGetSymbolAddress((void**)&dkTH, g_dkTH); cudaGetSymbolAddress((void**)&dkTL, g_dkTL);
    cudaGetSymbolAddress((void**)&dvTH, g_dvTH); cudaGetSymbolAddress((void**)&dvTL, g_dvTL);

    // ---- one-time weight transpose+convert ----
    for (int l = 0; l < LLAYERS; l++) {
        wconv_kernel<<<dim3(EE/32, EE/32), 256>>>(Wq + (size_t)l*EE*EE,
            wqTH + (size_t)l*EE*EE, wqTL + (size_t)l*EE*EE, EE, EE);
        wconv_kernel<<<dim3(EE/32, EE/32), 256>>>(Wk + (size_t)l*EE*EE,
            wkTH + (size_t)l*EE*EE, wkTL + (size_t)l*EE*EE, EE, EE);
        wconv_kernel<<<dim3(EE/32, EE/32), 256>>>(Wv + (size_t)l*EE*EE,
            wvTH + (size_t)l*EE*EE, wvTL + (size_t)l*EE*EE, EE, EE);
        wconv_kernel<<<dim3(FFD/32, EE/32), 256>>>(ff_W1 + (size_t)l*EE*FFD,
            w1TH + (size_t)l*FFD*EE, w1TL + (size_t)l*FFD*EE, EE, FFD);
        wconv_kernel<<<dim3(EE/32, FFD/32), 256>>>(ff_W2 + (size_t)l*FFD*EE,
            w2TH + (size_t)l*EE*FFD, w2TL + (size_t)l*EE*FFD, FFD, EE);
    }
    wconv_kernel<<<dim3(EE/32, EE/32), 256>>>(dWk, dkTH, dkTL, EE, EE);
    wconv_kernel<<<dim3(EE/32, EE/32), 256>>>(dWv, dvTH, dvTL, EE, EE);

    embed_kernel<<<M_TOT, EE>>>(data, emb_W, emb_b, x, xH, xL);

    for (int l = 0; l < LLAYERS; l++) {
        qkv_tc<<<M_TOT/128, 256>>>(
            xH, xL,
            wqTH + (size_t)l*EE*EE, wqTL + (size_t)l*EE*EE,
            wkTH + (size_t)l*EE*EE, wkTL + (size_t)l*EE*EE,
            wvTH + (size_t)l*EE*EE, wvTL + (size_t)l*EE*EE,
            sq, ek, ekv);
        ekconv_kernel<<<dim3(EE/32, NN/32, BB), 256>>>(ek, ekv, ekTH, ekTL, ekvTH, ekvTL);
        aft_enc_tc<<<dim3(NN/128, EE/64, BB), 256>>>(
            dist, log_scale, aft_alpha, l, ekvTH, ekvTL, ekTH, ekTL, x, sq, y);
        inorm_kernel<<<BB, dim3(128, 8)>>>(y, h, hH, hL, n1_w + l*EE, n1_b + l*EE);
        ff1_tc<<<dim3(M_TOT/128, FFD/128), 256>>>(
            hH, hL, w1TH + (size_t)l*FFD*EE, w1TL + (size_t)l*FFD*EE,
            ff_b1 + l*FFD, hidH, hidL);
        ff2_tc<<<M_TOT/128, 256>>>(
            hidH, hidL, w2TH + (size_t)l*EE*FFD, w2TL + (size_t)l*EE*FFD,
            ff_b2 + l*EE, h, y);
        inorm_kernel<<<BB, dim3(128, 8)>>>(y, x, xH, xL, n2_w + l*EE, n2_b + l*EE);
    }

    // decoder
    deckv_tc<<<M_TOT/128, 256>>>(xH, xL, dkTH, dkTL, dvTH, dvTL, ek, ekv);
    ekconv_kernel<<<dim3(EE/32, NN/32, BB), 256>>>(ek, ekv, ekTH, ekTL, ekvTH, ekvTL);
    gmean_kernel<<<BB, dim3(128, 8)>>>(x, gm);
    gq_kernel<<<BB, 128>>>(gm, dWq, gq);
    dec_aft_tc<<<dim3(PP/128, EE/64, BB), 256>>>(
        cur_dist, ninf_mask, log_scale, dec_alpha,
        ekvTH, ekvTL, ekTH, ekTL, gq, capacity, dWq, aftH, aftL);
    score_tc<<<dim3(PP/128, NN/128, BB), 256>>>(
        aftH, aftL, xH, xL, cur_dist, ninf_mask, log_scale, p_alpha, out);
    softmax_kernel<<<BB*PP, 128>>>(out);
}

// round 14
// speedup vs baseline: 1.2809x; 1.2129x over previous
#include <cuda_runtime.h>
#include <cuda_bf16.h>
#include <math.h>

#define BB 64
#define PP 512
#define NN 512
#define EE 128
#define FFD 512
#define LLAYERS 6
#define M_TOT (BB*NN)
#define EPS 1e-5f
#define INV_SQRT_E 0.08838834764831845f

typedef unsigned short u16;
typedef unsigned int   u32;
typedef unsigned long long u64;

#define TS 20                 /* smem row stride in u32 (80B), conflict-free */
#define SZU (128*TS)          /* u32 per 128-row buffer */
#define SZH (64*TS)           /* u32 per 64-row buffer  */
#define SMEM_SZ (8*SZU*4)     /* 81920 B: 2 stages x (A hi/lo + B hi/lo)    */

// ---------------- f32 scratch ----------------
__device__ float g_x  [BB*NN*EE];
__device__ float g_y  [BB*NN*EE];
__device__ float g_h  [BB*NN*EE];
__device__ float g_sq [BB*NN*EE];
__device__ float g_ek [BB*NN*EE];
__device__ float g_ekv[BB*NN*EE];
__device__ float g_gq [BB*EE];
__device__ float g_gm [BB*EE];
// ---------------- bf16 hi/lo scratch ----------------
__device__ u16 g_xH  [M_TOT*EE],  g_xL  [M_TOT*EE];
__device__ u16 g_hH  [M_TOT*EE],  g_hL  [M_TOT*EE];
__device__ u16 g_hidH[M_TOT*FFD], g_hidL[M_TOT*FFD];
__device__ u16 g_aftH[BB*PP*EE],  g_aftL[BB*PP*EE];
__device__ u16 g_ekTH [BB*EE*NN], g_ekTL [BB*EE*NN];
__device__ u16 g_ekvTH[BB*EE*NN], g_ekvTL[BB*EE*NN];
// weights (transposed [n][k])
__device__ u16 g_wqTH[LLAYERS*EE*EE],  g_wqTL[LLAYERS*EE*EE];
__device__ u16 g_wkTH[LLAYERS*EE*EE],  g_wkTL[LLAYERS*EE*EE];
__device__ u16 g_wvTH[LLAYERS*EE*EE],  g_wvTL[LLAYERS*EE*EE];
__device__ u16 g_w1TH[LLAYERS*FFD*EE], g_w1TL[LLAYERS*FFD*EE];
__device__ u16 g_w2TH[LLAYERS*EE*FFD], g_w2TL[LLAYERS*EE*FFD];
__device__ u16 g_dkTH[EE*EE], g_dkTL[EE*EE];
__device__ u16 g_dvTH[EE*EE], g_dvTL[EE*EE];

// ================= helpers =================
__device__ __forceinline__ void cvt_hl(float x, u16& h, u16& l) {
    __nv_bfloat16 bh = __float2bfloat16(x);
    float hf = __bfloat162float(bh);
    __nv_bfloat16 bl = __float2bfloat16(x - hf);
    h = __bfloat16_as_ushort(bh);
    l = __bfloat16_as_ushort(bl);
}
__device__ __forceinline__ void pack_hl(float x, float y, u32& h, u32& l) {
    u16 hx, lx, hy, ly;
    cvt_hl(x, hx, lx); cvt_hl(y, hy, ly);
    h = (u32)hx | ((u32)hy << 16);
    l = (u32)lx | ((u32)ly << 16);
}
__device__ __forceinline__ u32 smem_u32(const void* p) {
    u32 a; asm("{ .reg .u64 t; cvta.to.shared.u64 t, %1; cvt.u32.u64 %0, t; }"
               : "=r"(a) : "l"(p));
    return a;
}

#define MMAB(d, a, b)                                                        \
    asm volatile("mma.sync.aligned.m16n8k16.row.col.f32.bf16.bf16.f32 "      \
        "{%0,%1,%2,%3},{%4,%5,%6,%7},{%8,%9},{%0,%1,%2,%3};"                 \
        : "+f"(d[0]), "+f"(d[1]), "+f"(d[2]), "+f"(d[3])                     \
        : "r"(a[0]), "r"(a[1]), "r"(a[2]), "r"(a[3]), "r"(b[0]), "r"(b[1]))

// cp.async
__device__ __forceinline__ void cpa16(u32 dst, const void* src) {
    asm volatile("cp.async.cg.shared.global [%0], [%1], 16;" :: "r"(dst), "l"(src));
}
#define CPA_COMMIT() asm volatile("cp.async.commit_group;" ::: "memory")
#define CPA_WAIT1()  asm volatile("cp.async.wait_group 1;" ::: "memory")
#define CPA_WAIT0()  asm volatile("cp.async.wait_group 0;" ::: "memory")

// ---------- async tile loaders (256 threads, BK=32) ----------
// 128 rows x 32 k bf16 hi/lo -> staged smem (byte addresses)
__device__ __forceinline__ void ld128_async(const u16* __restrict__ GH,
                                            const u16* __restrict__ GL, size_t ld,
                                            int r0, int k0, u32 SH, u32 SL, int tid) {
    int r = tid >> 1;
    int hb = (tid & 1)*32;            // byte half offset
    const char* pH = (const char*)(GH + (size_t)(r0 + r)*ld + k0) + hb;
    const char* pL = (const char*)(GL + (size_t)(r0 + r)*ld + k0) + hb;
    u32 dH = SH + (u32)r*(TS*4) + hb;
    u32 dL = SL + (u32)r*(TS*4) + hb;
    cpa16(dH, pH); cpa16(dH + 16, pH + 16);
    cpa16(dL, pL); cpa16(dL + 16, pL + 16);
}
// two 64-row B tiles: tid<128 -> tensor1, tid>=128 -> tensor2
__device__ __forceinline__ void ld64x2_async(const u16* __restrict__ G1H,
                                             const u16* __restrict__ G1L,
                                             const u16* __restrict__ G2H,
                                             const u16* __restrict__ G2L, size_t ld,
                                             int n0, int k0,
                                             u32 B1H, u32 B1L, u32 B2H, u32 B2L,
                                             int tid) {
    int t = tid & 127;
    int r = t >> 1;
    int hb = (t & 1)*32;
    const u16* sH; const u16* sL; u32 dH, dL;
    if (tid < 128) { sH = G1H; sL = G1L; dH = B1H; dL = B1L; }
    else           { sH = G2H; sL = G2L; dH = B2H; dL = B2L; }
    const char* pH = (const char*)(sH + (size_t)(n0 + r)*ld + k0) + hb;
    const char* pL = (const char*)(sL + (size_t)(n0 + r)*ld + k0) + hb;
    dH += (u32)r*(TS*4) + hb;
    dL += (u32)r*(TS*4) + hb;
    cpa16(dH, pH); cpa16(dH + 16, pH + 16);
    cpa16(dL, pL); cpa16(dL + 16, pL + 16);
}

// ---------- computed A tiles (STS path) ----------
__device__ __forceinline__ void ld_Aexp(const float* __restrict__ G, size_t ld,
                                        int m0, int k0, u32* SH, u32* SL,
                                        int tid, float s) {
    int r = tid >> 1, c = (tid & 1)*16;
    const float* p = G + (size_t)(m0 + r)*ld + k0 + c;
    float v[16];
    #pragma unroll
    for (int q = 0; q < 4; q++) {
        float4 f = *(const float4*)(p + q*4);
        v[q*4+0]=f.x; v[q*4+1]=f.y; v[q*4+2]=f.z; v[q*4+3]=f.w;
    }
    u32 h[8], l[8];
    #pragma unroll
    for (int q = 0; q < 8; q++)
        pack_hl(__expf(s*v[2*q]), __expf(s*v[2*q+1]), h[q], l[q]);
    u32* dh = SH + r*TS + (tid & 1)*8;
    u32* dl = SL + r*TS + (tid & 1)*8;
    *(uint4*)dh = *(uint4*)h; *((uint4*)dh+1) = *(uint4*)(h+4);
    *(uint4*)dl = *(uint4*)l; *((uint4*)dl+1) = *(uint4*)(l+4);
}
__device__ __forceinline__ void ld_Aexpmask(const float* __restrict__ G,
                                            const float* __restrict__ Msk, size_t ld,
                                            int m0, int k0, u32* SH, u32* SL,
                                            int tid, float s) {
    int r = tid >> 1, c = (tid & 1)*16;
    size_t off = (size_t)(m0 + r)*ld + k0 + c;
    float v[16];
    #pragma unroll
    for (int q = 0; q < 4; q++) {
        float4 f = *(const float4*)(G + off + q*4);
        float4 m = *(const float4*)(Msk + off + q*4);
        v[q*4+0]=s*f.x+m.x; v[q*4+1]=s*f.y+m.y; v[q*4+2]=s*f.z+m.z; v[q*4+3]=s*f.w+m.w;
    }
    u32 h[8], l[8];
    #pragma unroll
    for (int q = 0; q < 8; q++)
        pack_hl(__expf(v[2*q]), __expf(v[2*q+1]), h[q], l[q]);
    u32* dh = SH + r*TS + (tid & 1)*8;
    u32* dl = SL + r*TS + (tid & 1)*8;
    *(uint4*)dh = *(uint4*)h; *((uint4*)dh+1) = *(uint4*)(h+4);
    *(uint4*)dl = *(uint4*)l; *((uint4*)dl+1) = *(uint4*)(l+4);
}

// ---------- warp mma over a 128x32 A tile, BN=128 ----------
__device__ __forceinline__ void mma128(const u32* AH, const u32* AL,
                                       const u32* BH, const u32* BL,
                                       float d[2][8][4],
                                       int wr0, int wc0, int qr, int qc) {
    #pragma unroll
    for (int ks = 0; ks < 2; ks++) {
        int ku = ks*8;
        u32 ah[2][4], al[2][4];
        #pragma unroll
        for (int i = 0; i < 2; i++) {
            int r = wr0 + i*16 + qr;
            ah[i][0]=AH[r*TS+ku+qc];     ah[i][1]=AH[(r+8)*TS+ku+qc];
            ah[i][2]=AH[r*TS+ku+qc+4];   ah[i][3]=AH[(r+8)*TS+ku+qc+4];
            al[i][0]=AL[r*TS+ku+qc];     al[i][1]=AL[(r+8)*TS+ku+qc];
            al[i][2]=AL[r*TS+ku+qc+4];   al[i][3]=AL[(r+8)*TS+ku+qc+4];
        }
        #pragma unroll
        for (int j = 0; j < 8; j++) {
            int n = wc0 + j*8 + qr;
            u32 bh[2] = {BH[n*TS+ku+qc], BH[n*TS+ku+qc+4]};
            u32 bl[2] = {BL[n*TS+ku+qc], BL[n*TS+ku+qc+4]};
            #pragma unroll
            for (int i = 0; i < 2; i++) {
                MMAB(d[i][j], ah[i], bh);
                MMAB(d[i][j], al[i], bh);
                MMAB(d[i][j], ah[i], bl);
            }
        }
    }
}
// ---------- warp mma, BN=64 dual B (num/den) ----------
__device__ __forceinline__ void mma64x2(const u32* AH, const u32* AL,
                                        const u32* B1H, const u32* B1L,
                                        const u32* B2H, const u32* B2L,
                                        float d1[2][4][4], float d2[2][4][4],
                                        int wr0, int wc0, int qr, int qc) {
    #pragma unroll
    for (int ks = 0; ks < 2; ks++) {
        int ku = ks*8;
        u32 ah[2][4], al[2][4];
        #pragma unroll
        for (int i = 0; i < 2; i++) {
            int r = wr0 + i*16 + qr;
            ah[i][0]=AH[r*TS+ku+qc];     ah[i][1]=AH[(r+8)*TS+ku+qc];
            ah[i][2]=AH[r*TS+ku+qc+4];   ah[i][3]=AH[(r+8)*TS+ku+qc+4];
            al[i][0]=AL[r*TS+ku+qc];     al[i][1]=AL[(r+8)*TS+ku+qc];
            al[i][2]=AL[r*TS+ku+qc+4];   al[i][3]=AL[(r+8)*TS+ku+qc+4];
        }
        #pragma unroll
        for (int j = 0; j < 4; j++) {
            int n = wc0 + j*8 + qr;
            {
                u32 bh[2] = {B1H[n*TS+ku+qc], B1H[n*TS+ku+qc+4]};
                u32 bl[2] = {B1L[n*TS+ku+qc], B1L[n*TS+ku+qc+4]};
                #pragma unroll
                for (int i = 0; i < 2; i++) {
                    MMAB(d1[i][j], ah[i], bh);
                    MMAB(d1[i][j], al[i], bh);
                    MMAB(d1[i][j], ah[i], bl);
                }
            }
            {
                u32 bh[2] = {B2H[n*TS+ku+qc], B2H[n*TS+ku+qc+4]};
                u32 bl[2] = {B2L[n*TS+ku+qc], B2L[n*TS+ku+qc+4]};
                #pragma unroll
                for (int i = 0; i < 2; i++) {
                    MMAB(d2[i][j], ah[i], bh);
                    MMAB(d2[i][j], al[i], bh);
                    MMAB(d2[i][j], ah[i], bl);
                }
            }
        }
    }
}

// =====================================================================
// qkv: A=x, 3 passes (Wq->SQ, Wk->EK, Wv->EKV); 2-stage cp.async pipeline
// =====================================================================
__global__ __launch_bounds__(256) void qkv_tc(
        const u16* __restrict__ XH, const u16* __restrict__ XL,
        const u16* __restrict__ WqH, const u16* __restrict__ WqL,
        const u16* __restrict__ WkH, const u16* __restrict__ WkL,
        const u16* __restrict__ WvH, const u16* __restrict__ WvL,
        float* __restrict__ SQ, float* __restrict__ EK, float* __restrict__ EKV) {
    extern __shared__ u32 smu[];
    const u32 sb = smem_u32(smu);
    const int tid = threadIdx.x, lane = tid & 31, w = tid >> 5;
    const int wr0 = (w >> 1)*32, wc0 = (w & 1)*64;
    const int qr = lane >> 2, qc = lane & 3;
    const int m0 = blockIdx.x*128;
    const u16* BH_g[3] = {WqH, WkH, WvH};
    const u16* BL_g[3] = {WqL, WkL, WvL};

    // stage s: A at s*2*SZU, B at (4+s*2)*SZU (u32 units)
    ld128_async(XH, XL, EE, m0, 0, sb, sb + SZU*4, tid);
    ld128_async(BH_g[0], BL_g[0], EE, 0, 0, sb + 4*SZU*4, sb + 5*SZU*4, tid);
    CPA_COMMIT();
    float d[2][8][4] = {};
    for (int t = 0; t < 12; t++) {
        int s = t & 1;
        if (t + 1 < 12) {
            int s2 = 1 - s, k2 = ((t+1) & 3)*32, p2 = (t+1) >> 2;
            ld128_async(XH, XL, EE, m0, k2,
                        sb + (s2*2)*SZU*4, sb + (s2*2+1)*SZU*4, tid);
            ld128_async(BH_g[p2], BL_g[p2], EE, 0, k2,
                        sb + (4+s2*2)*SZU*4, sb + (5+s2*2)*SZU*4, tid);
            CPA_COMMIT(); CPA_WAIT1();
        } else CPA_WAIT0();
        __syncthreads();
        mma128(smu + s*2*SZU, smu + (s*2+1)*SZU,
               smu + (4+s*2)*SZU, smu + (5+s*2)*SZU, d, wr0, wc0, qr, qc);
        __syncthreads();
        if ((t & 3) == 3) {
            int pass = t >> 2;
            #pragma unroll
            for (int i = 0; i < 2; i++)
                #pragma unroll
                for (int h = 0; h < 2; h++) {
                    int row = m0 + wr0 + i*16 + qr + h*8;
                    #pragma unroll
                    for (int j = 0; j < 8; j++) {
                        int col = wc0 + j*8 + qc*2;
                        size_t o = (size_t)row*EE + col;
                        float v0 = d[i][j][h*2], v1 = d[i][j][h*2+1];
                        if (pass == 0) {
                            *(float2*)&SQ[o] = make_float2(
                                1.f/(1.f + __expf(-v0)), 1.f/(1.f + __expf(-v1)));
                        } else if (pass == 1) {
                            *(float2*)&EK[o] = make_float2(__expf(v0), __expf(v1));
                        } else {
                            float2 e = *(const float2*)&EK[o];
                            *(float2*)&EKV[o] = make_float2(e.x*v0, e.y*v1);
                        }
                    }
                }
            #pragma unroll
            for (int i = 0; i < 2; i++)
                #pragma unroll
                for (int j = 0; j < 8; j++)
                    #pragma unroll
                    for (int q = 0; q < 4; q++) d[i][j][q] = 0.f;
        }
    }
}

// =====================================================================
// deckv: 2 passes
// =====================================================================
__global__ __launch_bounds__(256) void deckv_tc(
        const u16* __restrict__ XH, const u16* __restrict__ XL,
        const u16* __restrict__ WkH, const u16* __restrict__ WkL,
        const u16* __restrict__ WvH, const u16* __restrict__ WvL,
        float* __restrict__ EK, float* __restrict__ EKV) {
    extern __shared__ u32 smu[];
    const u32 sb = smem_u32(smu);
    const int tid = threadIdx.x, lane = tid & 31, w = tid >> 5;
    const int wr0 = (w >> 1)*32, wc0 = (w & 1)*64;
    const int qr = lane >> 2, qc = lane & 3;
    const int m0 = blockIdx.x*128;
    const u16* BH_g[2] = {WkH, WvH};
    const u16* BL_g[2] = {WkL, WvL};

    ld128_async(XH, XL, EE, m0, 0, sb, sb + SZU*4, tid);
    ld128_async(BH_g[0], BL_g[0], EE, 0, 0, sb + 4*SZU*4, sb + 5*SZU*4, tid);
    CPA_COMMIT();
    float d[2][8][4] = {};
    for (int t = 0; t < 8; t++) {
        int s = t & 1;
        if (t + 1 < 8) {
            int s2 = 1 - s, k2 = ((t+1) & 3)*32, p2 = (t+1) >> 2;
            ld128_async(XH, XL, EE, m0, k2,
                        sb + (s2*2)*SZU*4, sb + (s2*2+1)*SZU*4, tid);
            ld128_async(BH_g[p2], BL_g[p2], EE, 0, k2,
                        sb + (4+s2*2)*SZU*4, sb + (5+s2*2)*SZU*4, tid);
            CPA_COMMIT(); CPA_WAIT1();
        } else CPA_WAIT0();
        __syncthreads();
        mma128(smu + s*2*SZU, smu + (s*2+1)*SZU,
               smu + (4+s*2)*SZU, smu + (5+s*2)*SZU, d, wr0, wc0, qr, qc);
        __syncthreads();
        if ((t & 3) == 3) {
            int pass = t >> 2;
            #pragma unroll
            for (int i = 0; i < 2; i++)
                #pragma unroll
                for (int h = 0; h < 2; h++) {
                    int row = m0 + wr0 + i*16 + qr + h*8;
                    #pragma unroll
                    for (int j = 0; j < 8; j++) {
                        int col = wc0 + j*8 + qc*2;
                        size_t o = (size_t)row*EE + col;
                        float v0 = d[i][j][h*2], v1 = d[i][j][h*2+1];
                        if (pass == 0) {
                            *(float2*)&EK[o] = make_float2(__expf(v0), __expf(v1));
                        } else {
                            float2 e = *(const float2*)&EK[o];
                            *(float2*)&EKV[o] = make_float2(e.x*v0, e.y*v1);
                        }
                    }
                }
            #pragma unroll
            for (int i = 0; i < 2; i++)
                #pragma unroll
                for (int j = 0; j < 8; j++)
                    #pragma unroll
                    for (int q = 0; q < 4; q++) d[i][j][q] = 0.f;
        }
    }
}

// =====================================================================
// encoder AFT: A=exp(s*dist) computed (double-buffered), dual B async
// =====================================================================
__global__ __launch_bounds__(256) void aft_enc_tc(
        const float* __restrict__ dist,
        const float* __restrict__ ls,
        const float* __restrict__ alpha, int l,
        const u16* __restrict__ EKVTH, const u16* __restrict__ EKVTL,
        const u16* __restrict__ EKTH,  const u16* __restrict__ EKTL,
        const float* __restrict__ X,
        const float* __restrict__ SQ,
        float* __restrict__ Y) {
    extern __shared__ u32 smu[];
    const u32 sb = smem_u32(smu);
    const int tid = threadIdx.x, lane = tid & 31, w = tid >> 5;
    const int wr0 = (w >> 1)*32, wc0 = (w & 1)*32;
    const int qr = lane >> 2, qc = lane & 3;
    const int b = blockIdx.z;
    const int m0 = blockIdx.x*128, n0 = blockIdx.y*64;
    const float s = ls[0]*alpha[l];
    const float* D = dist + (size_t)b*NN*NN;
    const u16* T1H = EKVTH + (size_t)b*EE*NN;
    const u16* T1L = EKVTL + (size_t)b*EE*NN;
    const u16* T2H = EKTH  + (size_t)b*EE*NN;
    const u16* T2L = EKTL  + (size_t)b*EE*NN;
    // stage s: A at s*2*SZU; B block at (4+s*2)*SZU: [B1H, B1L, B2H, B2L] (SZH each)
    ld_Aexp(D, NN, m0, 0, smu, smu + SZU, tid, s);
    ld64x2_async(T1H, T1L, T2H, T2L, NN, n0, 0,
                 sb + 4*SZU*4, sb + (4*SZU+SZH)*4,
                 sb + (4*SZU+2*SZH)*4, sb + (4*SZU+3*SZH)*4, tid);
    CPA_COMMIT();
    float d1[2][4][4] = {}, d2[2][4][4] = {};
    for (int t = 0; t < 16; t++) {
        int s1 = t & 1;
        if (t + 1 < 16) {
            int s2 = 1 - s1, k2 = (t+1)*32;
            u32 bbase = sb + (4 + s2*2)*SZU*4;
            ld64x2_async(T1H, T1L, T2H, T2L, NN, n0, k2,
                         bbase, bbase + SZH*4, bbase + 2*SZH*4, bbase + 3*SZH*4, tid);
            CPA_COMMIT();
            ld_Aexp(D, NN, m0, k2, smu + s2*2*SZU, smu + (s2*2+1)*SZU, tid, s);
            CPA_WAIT1();
        } else CPA_WAIT0();
        __syncthreads();
        u32 bo = (4 + s1*2)*SZU;
        mma64x2(smu + s1*2*SZU, smu + (s1*2+1)*SZU,
                smu + bo, smu + bo + SZH, smu + bo + 2*SZH, smu + bo + 3*SZH,
                d1, d2, wr0, wc0, qr, qc);
        __syncthreads();
    }
    #pragma unroll
    for (int i = 0; i < 2; i++)
        #pragma unroll
        for (int h = 0; h < 2; h++) {
            int row = m0 + wr0 + i*16 + qr + h*8;
            #pragma unroll
            for (int j = 0; j < 4; j++) {
                int col = n0 + wc0 + j*8 + qc*2;
                size_t o = ((size_t)b*NN + row)*EE + col;
                float2 xv = *(const float2*)&X[o];
                float2 sv = *(const float2*)&SQ[o];
                float n0v = d1[i][j][h*2], n1v = d1[i][j][h*2+1];
                float de0 = d2[i][j][h*2], de1 = d2[i][j][h*2+1];
                *(float2*)&Y[o] = make_float2(
                    xv.x + sv.x*(n0v/de0), xv.y + sv.y*(n1v/de1));
            }
        }
}

// =====================================================================
// decoder AFT
// =====================================================================
__global__ __launch_bounds__(256) void dec_aft_tc(
        const float* __restrict__ cur_dist,
        const float* __restrict__ ninf,
        const float* __restrict__ ls,
        const float* __restrict__ dalpha,
        const u16* __restrict__ EKVTH, const u16* __restrict__ EKVTL,
        const u16* __restrict__ EKTH,  const u16* __restrict__ EKTL,
        const float* __restrict__ GQ,
        const float* __restrict__ cap,
        const float* __restrict__ dWq,
        u16* __restrict__ AFTH, u16* __restrict__ AFTL) {
    extern __shared__ u32 smu[];
    const u32 sb = smem_u32(smu);
    const int tid = threadIdx.x, lane = tid & 31, w = tid >> 5;
    const int wr0 = (w >> 1)*32, wc0 = (w & 1)*32;
    const int qr = lane >> 2, qc = lane & 3;
    const int b = blockIdx.z;
    const int m0 = blockIdx.x*128, n0 = blockIdx.y*64;
    const float s = ls[0]*dalpha[0];
    const float* CD = cur_dist + (size_t)b*PP*NN;
    const float* NM = ninf     + (size_t)b*PP*NN;
    const u16* T1H = EKVTH + (size_t)b*EE*NN;
    const u16* T1L = EKVTL + (size_t)b*EE*NN;
    const u16* T2H = EKTH  + (size_t)b*EE*NN;
    const u16* T2L = EKTL  + (size_t)b*EE*NN;
    ld_Aexpmask(CD, NM, NN, m0, 0, smu, smu + SZU, tid, s);
    ld64x2_async(T1H, T1L, T2H, T2L, NN, n0, 0,
                 sb + 4*SZU*4, sb + (4*SZU+SZH)*4,
                 sb + (4*SZU+2*SZH)*4, sb + (4*SZU+3*SZH)*4, tid);
    CPA_COMMIT();
    float d1[2][4][4] = {}, d2[2][4][4] = {};
    for (int t = 0; t < 16; t++) {
        int s1 = t & 1;
        if (t + 1 < 16) {
            int s2 = 1 - s1, k2 = (t+1)*32;
            u32 bbase = sb + (4 + s2*2)*SZU*4;
            ld64x2_async(T1H, T1L, T2H, T2L, NN, n0, k2,
                         bbase, bbase + SZH*4, bbase + 2*SZH*4, bbase + 3*SZH*4, tid);
            CPA_COMMIT();
            ld_Aexpmask(CD, NM, NN, m0, k2, smu + s2*2*SZU, smu + (s2*2+1)*SZU, tid, s);
            CPA_WAIT1();
        } else CPA_WAIT0();
        __syncthreads();
        u32 bo = (4 + s1*2)*SZU;
        mma64x2(smu + s1*2*SZU, smu + (s1*2+1)*SZU,
                smu + bo, smu + bo + SZH, smu + bo + 2*SZH, smu + bo + 3*SZH,
                d1, d2, wr0, wc0, qr, qc);
        __syncthreads();
    }
    #pragma unroll
    for (int i = 0; i < 2; i++)
        #pragma unroll
        for (int h = 0; h < 2; h++) {
            int p = m0 + wr0 + i*16 + qr + h*8;
            float cv = cap[(size_t)b*PP + p];
            #pragma unroll
            for (int j = 0; j < 4; j++) {
                int col = n0 + wc0 + j*8 + qc*2;
                float2 gq2 = *(const float2*)&GQ[b*EE + col];
                float2 wq2 = *(const float2*)&dWq[EE*EE + col];
                float q0 = gq2.x + cv*wq2.x;
                float q1 = gq2.y + cv*wq2.y;
                float sg0 = 1.f/(1.f + __expf(-q0));
                float sg1 = 1.f/(1.f + __expf(-q1));
                float v0 = sg0*(d1[i][j][h*2]  /d2[i][j][h*2]);
                float v1 = sg1*(d1[i][j][h*2+1]/d2[i][j][h*2+1]);
                u32 hh, ll; pack_hl(v0, v1, hh, ll);
                size_t o = ((size_t)b*PP + p)*EE + col;
                *(u32*)&AFTH[o] = hh;
                *(u32*)&AFTL[o] = ll;
            }
        }
}

// =====================================================================
// FF1: hid = relu(h@W1 + b1) -> bf16 hi/lo
// =====================================================================
__global__ __launch_bounds__(256) void ff1_tc(
        const u16* __restrict__ HH, const u16* __restrict__ HL,
        const u16* __restrict__ W1H, const u16* __restrict__ W1L,
        const float* __restrict__ b1,
        u16* __restrict__ HIDH, u16* __restrict__ HIDL) {
    extern __shared__ u32 smu[];
    const u32 sb = smem_u32(smu);
    const int tid = threadIdx.x, lane = tid & 31, w = tid >> 5;
    const int wr0 = (w >> 1)*32, wc0 = (w & 1)*64;
    const int qr = lane >> 2, qc = lane & 3;
    const int m0 = blockIdx.x*128, n0 = blockIdx.y*128;
    ld128_async(HH, HL, EE, m0, 0, sb, sb + SZU*4, tid);
    ld128_async(W1H, W1L, EE, n0, 0, sb + 4*SZU*4, sb + 5*SZU*4, tid);
    CPA_COMMIT();
    float d[2][8][4] = {};
    for (int t = 0; t < 4; t++) {
        int s = t & 1;
        if (t + 1 < 4) {
            int s2 = 1 - s, k2 = (t+1)*32;
            ld128_async(HH, HL, EE, m0, k2,
                        sb + (s2*2)*SZU*4, sb + (s2*2+1)*SZU*4, tid);
            ld128_async(W1H, W1L, EE, n0, k2,
                        sb + (4+s2*2)*SZU*4, sb + (5+s2*2)*SZU*4, tid);
            CPA_COMMIT(); CPA_WAIT1();
        } else CPA_WAIT0();
        __syncthreads();
        mma128(smu + s*2*SZU, smu + (s*2+1)*SZU,
               smu + (4+s*2)*SZU, smu + (5+s*2)*SZU, d, wr0, wc0, qr, qc);
        __syncthreads();
    }
    #pragma unroll
    for (int i = 0; i < 2; i++)
        #pragma unroll
        for (int h = 0; h < 2; h++) {
            int row = m0 + wr0 + i*16 + qr + h*8;
            #pragma unroll
            for (int j = 0; j < 8; j++) {
                int col = n0 + wc0 + j*8 + qc*2;
                float2 bb = *(const float2*)&b1[col];
                float v0 = fmaxf(d[i][j][h*2]   + bb.x, 0.f);
                float v1 = fmaxf(d[i][j][h*2+1] + bb.y, 0.f);
                u32 hh, ll; pack_hl(v0, v1, hh, ll);
                size_t o = (size_t)row*FFD + col;
                *(u32*)&HIDH[o] = hh;
                *(u32*)&HIDL[o] = ll;
            }
        }
}

// =====================================================================
// FF2: y = h + hid@W2 + b2  (K=512, 16 chunks)
// =====================================================================
__global__ __launch_bounds__(256) void ff2_tc(
        const u16* __restrict__ HIDH, const u16* __restrict__ HIDL,
        const u16* __restrict__ W2H, const u16* __restrict__ W2L,
        const float* __restrict__ b2,
        const float* __restrict__ H,
        float* __restrict__ Y) {
    extern __shared__ u32 smu[];
    const u32 sb = smem_u32(smu);
    const int tid = threadIdx.x, lane = tid & 31, w = tid >> 5;
    const int wr0 = (w >> 1)*32, wc0 = (w & 1)*64;
    const int qr = lane >> 2, qc = lane & 3;
    const int m0 = blockIdx.x*128;
    ld128_async(HIDH, HIDL, FFD, m0, 0, sb, sb + SZU*4, tid);
    ld128_async(W2H, W2L, FFD, 0, 0, sb + 4*SZU*4, sb + 5*SZU*4, tid);
    CPA_COMMIT();
    float d[2][8][4] = {};
    for (int t = 0; t < 16; t++) {
        int s = t & 1;
        if (t + 1 < 16) {
            int s2 = 1 - s, k2 = (t+1)*32;
            ld128_async(HIDH, HIDL, FFD, m0, k2,
                        sb + (s2*2)*SZU*4, sb + (s2*2+1)*SZU*4, tid);
            ld128_async(W2H, W2L, FFD, 0, k2,
                        sb + (4+s2*2)*SZU*4, sb + (5+s2*2)*SZU*4, tid);
            CPA_COMMIT(); CPA_WAIT1();
        } else CPA_WAIT0();
        __syncthreads();
        mma128(smu + s*2*SZU, smu + (s*2+1)*SZU,
               smu + (4+s*2)*SZU, smu + (5+s*2)*SZU, d, wr0, wc0, qr, qc);
        __syncthreads();
    }
    #pragma unroll
    for (int i = 0; i < 2; i++)
        #pragma unroll
        for (int h = 0; h < 2; h++) {
            int row = m0 + wr0 + i*16 + qr + h*8;
            #pragma unroll
            for (int j = 0; j < 8; j++) {
                int col = wc0 + j*8 + qc*2;
                float2 bb = *(const float2*)&b2[col];
                size_t o = (size_t)row*EE + col;
                float2 hv = *(const float2*)&H[o];
                *(float2*)&Y[o] = make_float2(
                    hv.x + d[i][j][h*2]   + bb.x,
                    hv.y + d[i][j][h*2+1] + bb.y);
            }
        }
}

// =====================================================================
// score: S = aft @ enc^T + epilogue (K=128)
// =====================================================================
__global__ __launch_bounds__(256) void score_tc(
        const u16* __restrict__ AFTH, const u16* __restrict__ AFTL,
        const u16* __restrict__ XH, const u16* __restrict__ XL,
        const float* __restrict__ cur_dist,
        const float* __restrict__ ninf,
        const float* __restrict__ ls,
        const float* __restrict__ palpha,
        float* __restrict__ OUT) {
    extern __shared__ u32 smu[];
    const u32 sb = smem_u32(smu);
    const int tid = threadIdx.x, lane = tid & 31, w = tid >> 5;
    const int wr0 = (w >> 1)*32, wc0 = (w & 1)*64;
    const int qr = lane >> 2, qc = lane & 3;
    const int b = blockIdx.z;
    const int p0 = blockIdx.x*128, n0 = blockIdx.y*128;
    const float ps = ls[0]*palpha[0];
    const u16* AgH = AFTH + (size_t)b*PP*EE;
    const u16* AgL = AFTL + (size_t)b*PP*EE;
    const u16* BgH = XH + (size_t)b*NN*EE;
    const u16* BgL = XL + (size_t)b*NN*EE;
    ld128_async(AgH, AgL, EE, p0, 0, sb, sb + SZU*4, tid);
    ld128_async(BgH, BgL, EE, n0, 0, sb + 4*SZU*4, sb + 5*SZU*4, tid);
    CPA_COMMIT();
    float d[2][8][4] = {};
    for (int t = 0; t < 4; t++) {
        int s = t & 1;
        if (t + 1 < 4) {
            int s2 = 1 - s, k2 = (t+1)*32;
            ld128_async(AgH, AgL, EE, p0, k2,
                        sb + (s2*2)*SZU*4, sb + (s2*2+1)*SZU*4, tid);
            ld128_async(BgH, BgL, EE, n0, k2,
                        sb + (4+s2*2)*SZU*4, sb + (5+s2*2)*SZU*4, tid);
            CPA_COMMIT(); CPA_WAIT1();
        } else CPA_WAIT0();
        __syncthreads();
        mma128(smu + s*2*SZU, smu + (s*2+1)*SZU,
               smu + (4+s*2)*SZU, smu + (5+s*2)*SZU, d, wr0, wc0, qr, qc);
        __syncthreads();
    }
    #pragma unroll
    for (int i = 0; i < 2; i++)
        #pragma unroll
        for (int h = 0; h < 2; h++) {
            int p = p0 + wr0 + i*16 + qr + h*8;
            #pragma unroll
            for (int j = 0; j < 8; j++) {
                int n = n0 + wc0 + j*8 + qc*2;
                size_t o = ((size_t)b*PP + p)*NN + n;
                float2 cd = *(const float2*)&cur_dist[o];
                float2 nm = *(const float2*)&ninf[o];
                float s0 = d[i][j][h*2]  *INV_SQRT_E + ps*cd.x;
                float s1 = d[i][j][h*2+1]*INV_SQRT_E + ps*cd.y;
                *(float2*)&OUT[o] = make_float2(
                    10.f*tanhf(s0) + nm.x, 10.f*tanhf(s1) + nm.y);
            }
        }
}

// =====================================================================
// weight transpose-convert (batched)
// =====================================================================
__device__ __forceinline__ void wconv_body(const float* __restrict__ src,
                                           u16* __restrict__ dH, u16* __restrict__ dL,
                                           int K, int N) {
    __shared__ float t[32][33];
    int n0 = blockIdx.x*32, k0 = blockIdx.y*32;
    int tr = threadIdx.x >> 3, tc4 = (threadIdx.x & 7)*4;
    float4 v = *(const float4*)&src[(size_t)(k0+tr)*N + n0 + tc4];
    t[tc4+0][tr] = v.x; t[tc4+1][tr] = v.y;
    t[tc4+2][tr] = v.z; t[tc4+3][tr] = v.w;
    __syncthreads();
    int r = threadIdx.x >> 3, c4 = (threadIdx.x & 7)*4;
    u16 h[4], l[4];
    #pragma unroll
    for (int i = 0; i < 4; i++) cvt_hl(t[r][c4+i], h[i], l[i]);
    size_t o = (size_t)(n0+r)*K + k0 + c4;
    *(uint2*)&dH[o] = *(uint2*)h;
    *(uint2*)&dL[o] = *(uint2*)l;
}
__global__ void wconv_sq(const float* __restrict__ Wq, const float* __restrict__ Wk,
                         const float* __restrict__ Wv,
                         const float* __restrict__ dWk, const float* __restrict__ dWv,
                         u16* qH, u16* qL, u16* kH, u16* kL, u16* vH, u16* vL,
                         u16* dkH, u16* dkL, u16* dvH, u16* dvL) {
    int z = blockIdx.z;
    const float* src; u16 *dH, *dL;
    size_t off = (size_t)(z % 6)*EE*EE;
    if (z < 6)       { src = Wq + off; dH = qH + off; dL = qL + off; }
    else if (z < 12) { src = Wk + off; dH = kH + off; dL = kL + off; }
    else if (z < 18) { src = Wv + off; dH = vH + off; dL = vL + off; }
    else if (z == 18){ src = dWk; dH = dkH; dL = dkL; }
    else             { src = dWv; dH = dvH; dL = dvL; }
    wconv_body(src, dH, dL, EE, EE);
}
__global__ void wconv_w1(const float* __restrict__ W1, u16* dH, u16* dL) {
    int l = blockIdx.z;
    wconv_body(W1 + (size_t)l*EE*FFD, dH + (size_t)l*FFD*EE, dL + (size_t)l*FFD*EE,
               EE, FFD);
}
__global__ void wconv_w2(const float* __restrict__ W2, u16* dH, u16* dL) {
    int l = blockIdx.z;
    wconv_body(W2 + (size_t)l*FFD*EE, dH + (size_t)l*EE*FFD, dL + (size_t)l*EE*FFD,
               FFD, EE);
}

// =====================================================================
// ek/ekv transpose-convert: f32 [b][node][e] -> bf16 [b][e][node]
// =====================================================================
__global__ void ekconv_kernel(const float* __restrict__ ek,
                              const float* __restrict__ ekv,
                              u16* __restrict__ ekTH, u16* __restrict__ ekTL,
                              u16* __restrict__ ekvTH, u16* __restrict__ ekvTL) {
    __shared__ float t1[32][33], t2[32][33];
    int b = blockIdx.z;
    int e0 = blockIdx.x*32, nd0 = blockIdx.y*32;
    const float* S1 = ek  + (size_t)b*NN*EE;
    const float* S2 = ekv + (size_t)b*NN*EE;
    int tr = threadIdx.x >> 3, tc4 = (threadIdx.x & 7)*4;
    size_t so = (size_t)(nd0+tr)*EE + e0 + tc4;
    float4 v1 = *(const float4*)&S1[so];
    float4 v2 = *(const float4*)&S2[so];
    t1[tc4+0][tr]=v1.x; t1[tc4+1][tr]=v1.y; t1[tc4+2][tr]=v1.z; t1[tc4+3][tr]=v1.w;
    t2[tc4+0][tr]=v2.x; t2[tc4+1][tr]=v2.y; t2[tc4+2][tr]=v2.z; t2[tc4+3][tr]=v2.w;
    __syncthreads();
    int r = threadIdx.x >> 3, c4 = (threadIdx.x & 7)*4;
    size_t o = (size_t)b*EE*NN + (size_t)(e0+r)*NN + nd0 + c4;
    u16 h[4], l[4];
    #pragma unroll
    for (int i = 0; i < 4; i++) cvt_hl(t1[r][c4+i], h[i], l[i]);
    *(uint2*)&ekTH[o] = *(uint2*)h; *(uint2*)&ekTL[o] = *(uint2*)l;
    #pragma unroll
    for (int i = 0; i < 4; i++) cvt_hl(t2[r][c4+i], h[i], l[i]);
    *(uint2*)&ekvTH[o] = *(uint2*)h; *(uint2*)&ekvTL[o] = *(uint2*)l;
}

// ---------------- embedding (also writes bf16 hi/lo) ----------------
__global__ void embed_kernel(const float* __restrict__ data,
                             const float* __restrict__ W,
                             const float* __restrict__ bias,
                             float* __restrict__ X,
                             u16* __restrict__ XH, u16* __restrict__ XL) {
    int idx = blockIdx.x;
    int e   = threadIdx.x;
    float d0 = data[idx*2+0], d1 = data[idx*2+1];
    float v = d0*W[e] + d1*W[EE+e] + bias[e];
    size_t o = (size_t)idx*EE + e;
    X[o] = v;
    u16 h, l; cvt_hl(v, h, l);
    XH[o] = h; XL[o] = l;
}

// ---------------- instance norm (also emits bf16 hi/lo) ----------------
__global__ void inorm_kernel(const float* __restrict__ src,
                             float* __restrict__ dst,
                             u16* __restrict__ dstH, u16* __restrict__ dstL,
                             const float* __restrict__ w,
                             const float* __restrict__ bias) {
    int b = blockIdx.x;
    int e = threadIdx.x;
    int c = threadIdx.y;
    const float* S = src + (size_t)b*NN*EE;
    float s = 0.f, s2 = 0.f;
    for (int n = c*64; n < c*64 + 64; n++) {
        float v = S[(size_t)n*EE + e];
        s += v; s2 += v*v;
    }
    __shared__ float ssum[8][128], ssq[8][128];
    __shared__ float smu2[128], srs[128];
    ssum[c][e] = s; ssq[c][e] = s2;
    __syncthreads();
    if (c == 0) {
        float ts = 0.f, t2 = 0.f;
        #pragma unroll
        for (int i = 0; i < 8; i++) { ts += ssum[i][e]; t2 += ssq[i][e]; }
        float mu = ts*(1.f/NN);
        float var = t2*(1.f/NN) - mu*mu;
        smu2[e] = mu;
        srs[e] = rsqrtf(var + EPS);
    }
    __syncthreads();
    float mu = smu2[e], rs = srs[e], ww = w[e], bb = bias[e];
    size_t base = (size_t)b*NN*EE;
    for (int n = c*64; n < c*64 + 64; n++) {
        size_t o = base + (size_t)n*EE + e;
        float v = (S[(size_t)n*EE + e] - mu)*rs*ww + bb;
        dst[o] = v;
        u16 h, l; cvt_hl(v, h, l);
        dstH[o] = h; dstL[o] = l;
    }
}

// ---------------- graph mean over nodes ----------------
__global__ void gmean_kernel(const float* __restrict__ X, float* __restrict__ GM) {
    int b = blockIdx.x, e = threadIdx.x, c = threadIdx.y;
    float s = 0.f;
    for (int n = c*64; n < c*64 + 64; n++)
        s += X[((size_t)b*NN + n)*EE + e];
    __shared__ float sm[8][128];
    sm[c][e] = s;
    __syncthreads();
    if (c == 0) {
        float t = 0.f;
        #pragma unroll
        for (int i = 0; i < 8; i++) t += sm[i][e];
        GM[b*EE + e] = t*(1.f/NN);
    }
}

// ---------------- gq = gmean @ dWq[0:E,:] ----------------
__global__ void gq_kernel(const float* __restrict__ GM,
                          const float* __restrict__ dWq,
                          float* __restrict__ GQ) {
    int b = blockIdx.x, e = threadIdx.x;
    float acc = 0.f;
    for (int i = 0; i < EE; i++)
        acc += GM[b*EE + i]*dWq[i*EE + e];
    GQ[b*EE + e] = acc;
}

// ---------------- row softmax over last dim (512) ----------------
__global__ void softmax_kernel(float* __restrict__ OUT) {
    float* row = OUT + (size_t)blockIdx.x*NN;
    int t = threadIdx.x;
    float v[4];
    #pragma unroll
    for (int i = 0; i < 4; i++) v[i] = row[t + i*128];
    float m = fmaxf(fmaxf(v[0], v[1]), fmaxf(v[2], v[3]));
    __shared__ float red[4];
    #pragma unroll
    for (int off = 16; off > 0; off >>= 1)
        m = fmaxf(m, __shfl_xor_sync(0xffffffff, m, off));
    if ((t & 31) == 0) red[t >> 5] = m;
    __syncthreads();
    m = fmaxf(fmaxf(red[0], red[1]), fmaxf(red[2], red[3]));
    __syncthreads();
    float s = 0.f;
    #pragma unroll
    for (int i = 0; i < 4; i++) { v[i] = __expf(v[i] - m); s += v[i]; }
    #pragma unroll
    for (int off = 16; off > 0; off >>= 1)
        s += __shfl_xor_sync(0xffffffff, s, off);
    if ((t & 31) == 0) red[t >> 5] = s;
    __syncthreads();
    s = red[0] + red[1] + red[2] + red[3];
    float inv = 1.f/s;
    #pragma unroll
    for (int i = 0; i < 4; i++) row[t + i*128] = v[i]*inv;
}

// ---------------- launch ----------------
extern "C" void kernel_launch(void* const* d_in, const int* in_sizes, int n_in,
                              void* d_out, int out_size) {
    const float* data      = (const float*)d_in[0];
    const float* dist      = (const float*)d_in[1];
    const float* cur_dist  = (const float*)d_in[2];
    const float* capacity  = (const float*)d_in[3];
    const float* ninf_mask = (const float*)d_in[4];
    const float* log_scale = (const float*)d_in[5];
    const float* emb_W     = (const float*)d_in[6];
    const float* emb_b     = (const float*)d_in[7];
    const float* Wq        = (const float*)d_in[8];
    const float* Wk        = (const float*)d_in[9];
    const float* Wv        = (const float*)d_in[10];
    const float* aft_alpha = (const float*)d_in[11];
    const float* n1_w      = (const float*)d_in[12];
    const float* n1_b      = (const float*)d_in[13];
    const float* ff_W1     = (const float*)d_in[14];
    const float* ff_b1     = (const float*)d_in[15];
    const float* ff_W2     = (const float*)d_in[16];
    const float* ff_b2     = (const float*)d_in[17];
    const float* n2_w      = (const float*)d_in[18];
    const float* n2_b      = (const float*)d_in[19];
    const float* dWq       = (const float*)d_in[20];
    const float* dWk       = (const float*)d_in[21];
    const float* dWv       = (const float*)d_in[22];
    const float* dec_alpha = (const float*)d_in[23];
    const float* p_alpha   = (const float*)d_in[24];
    float* out = (float*)d_out;

    float *x, *y, *h, *sq, *ek, *ekv, *gq, *gm;
    cudaGetSymbolAddress((void**)&x,   g_x);
    cudaGetSymbolAddress((void**)&y,   g_y);
    cudaGetSymbolAddress((void**)&h,   g_h);
    cudaGetSymbolAddress((void**)&sq,  g_sq);
    cudaGetSymbolAddress((void**)&ek,  g_ek);
    cudaGetSymbolAddress((void**)&ekv, g_ekv);
    cudaGetSymbolAddress((void**)&gq,  g_gq);
    cudaGetSymbolAddress((void**)&gm,  g_gm);

    u16 *xH,*xL,*hH,*hL,*hidH,*hidL,*aftH,*aftL;
    u16 *ekTH,*ekTL,*ekvTH,*ekvTL;
    u16 *wqTH,*wqTL,*wkTH,*wkTL,*wvTH,*wvTL,*w1TH,*w1TL,*w2TH,*w2TL;
    u16 *dkTH,*dkTL,*dvTH,*dvTL;
    cudaGetSymbolAddress((void**)&xH,   g_xH);   cudaGetSymbolAddress((void**)&xL,   g_xL);
    cudaGetSymbolAddress((void**)&hH,   g_hH);   cudaGetSymbolAddress((void**)&hL,   g_hL);
    cudaGetSymbolAddress((void**)&hidH, g_hidH); cudaGetSymbolAddress((void**)&hidL, g_hidL);
    cudaGetSymbolAddress((void**)&aftH, g_aftH); cudaGetSymbolAddress((void**)&aftL, g_aftL);
    cudaGetSymbolAddress((void**)&ekTH, g_ekTH); cudaGetSymbolAddress((void**)&ekTL, g_ekTL);
    cudaGetSymbolAddress((void**)&ekvTH,g_ekvTH);cudaGetSymbolAddress((void**)&ekvTL,g_ekvTL);
    cudaGetSymbolAddress((void**)&wqTH, g_wqTH); cudaGetSymbolAddress((void**)&wqTL, g_wqTL);
    cudaGetSymbolAddress((void**)&wkTH, g_wkTH); cudaGetSymbolAddress((void**)&wkTL, g_wkTL);
    cudaGetSymbolAddress((void**)&wvTH, g_wvTH); cudaGetSymbolAddress((void**)&wvTL, g_wvTL);
    cudaGetSymbolAddress((void**)&w1TH, g_w1TH); cudaGetSymbolAddress((void**)&w1TL, g_w1TL);
    cudaGetSymbolAddress((void**)&w2TH, g_w2TH); cudaGetSymbolAddress((void**)&w2TL, g_w2TL);
    cudaGetSymbolAddress((void**)&dkTH, g_dkTH); cudaGetSymbolAddress((void**)&dkTL, g_dkTL);
    cudaGetSymbolAddress((void**)&dvTH, g_dvTH); cudaGetSymbolAddress((void**)&dvTL, g_dvTL);

    cudaFuncSetAttribute(qkv_tc,     cudaFuncAttributeMaxDynamicSharedMemorySize, SMEM_SZ);
    cudaFuncSetAttribute(deckv_tc,   cudaFuncAttributeMaxDynamicSharedMemorySize, SMEM_SZ);
    cudaFuncSetAttribute(aft_enc_tc, cudaFuncAttributeMaxDynamicSharedMemorySize, SMEM_SZ);
    cudaFuncSetAttribute(dec_aft_tc, cudaFuncAttributeMaxDynamicSharedMemorySize, SMEM_SZ);
    cudaFuncSetAttribute(ff1_tc,     cudaFuncAttributeMaxDynamicSharedMemorySize, SMEM_SZ);
    cudaFuncSetAttribute(ff2_tc,     cudaFuncAttributeMaxDynamicSharedMemorySize, SMEM_SZ);
    cudaFuncSetAttribute(score_tc,   cudaFuncAttributeMaxDynamicSharedMemorySize, SMEM_SZ);

    // ---- batched weight transpose+convert (3 launches) ----
    wconv_sq<<<dim3(EE/32, EE/32, 20), 256>>>(Wq, Wk, Wv, dWk, dWv,
        wqTH, wqTL, wkTH, wkTL, wvTH, wvTL, dkTH, dkTL, dvTH, dvTL);
    wconv_w1<<<dim3(FFD/32, EE/32, LLAYERS), 256>>>(ff_W1, w1TH, w1TL);
    wconv_w2<<<dim3(EE/32, FFD/32, LLAYERS), 256>>>(ff_W2, w2TH, w2TL);

    embed_kernel<<<M_TOT, EE>>>(data, emb_W, emb_b, x, xH, xL);

    for (int l = 0; l < LLAYERS; l++) {
        qkv_tc<<<M_TOT/128, 256, SMEM_SZ>>>(
            xH, xL,
            wqTH + (size_t)l*EE*EE, wqTL + (size_t)l*EE*EE,
            wkTH + (size_t)l*EE*EE, wkTL + (size_t)l*EE*EE,
            wvTH + (size_t)l*EE*EE, wvTL + (size_t)l*EE*EE,
            sq, ek, ekv);
        ekconv_kernel<<<dim3(EE/32, NN/32, BB), 256>>>(ek, ekv, ekTH, ekTL, ekvTH, ekvTL);
        aft_enc_tc<<<dim3(NN/128, EE/64, BB), 256, SMEM_SZ>>>(
            dist, log_scale, aft_alpha, l, ekvTH, ekvTL, ekTH, ekTL, x, sq, y);
        inorm_kernel<<<BB, dim3(128, 8)>>>(y, h, hH, hL, n1_w + l*EE, n1_b + l*EE);
        ff1_tc<<<dim3(M_TOT/128, FFD/128), 256, SMEM_SZ>>>(
            hH, hL, w1TH + (size_t)l*FFD*EE, w1TL + (size_t)l*FFD*EE,
            ff_b1 + l*FFD, hidH, hidL);
        ff2_tc<<<M_TOT/128, 256, SMEM_SZ>>>(
            hidH, hidL, w2TH + (size_t)l*EE*FFD, w2TL + (size_t)l*EE*FFD,
            ff_b2 + l*EE, h, y);
        inorm_kernel<<<BB, dim3(128, 8)>>>(y, x, xH, xL, n2_w + l*EE, n2_b + l*EE);
    }

    // decoder
    deckv_tc<<<M_TOT/128, 256, SMEM_SZ>>>(xH, xL, dkTH, dkTL, dvTH, dvTL, ek, ekv);
    ekconv_kernel<<<dim3(EE/32, NN/32, BB), 256>>>(ek, ekv, ekTH, ekTL, ekvTH, ekvTL);
    gmean_kernel<<<BB, dim3(128, 8)>>>(x, gm);
    gq_kernel<<<BB, 128>>>(gm, dWq, gq);
    dec_aft_tc<<<dim3(PP/128, EE/64, BB), 256, SMEM_SZ>>>(
        cur_dist, ninf_mask, log_scale, dec_alpha,
        ekvTH, ekvTL, ekTH, ekTL, gq, capacity, dWq, aftH, aftL);
    score_tc<<<dim3(PP/128, NN/128, BB), 256, SMEM_SZ>>>(
        aftH, aftL, xH, xL, cur_dist, ninf_mask, log_scale, p_alpha, out);
    softmax_kernel<<<BB*PP, 128>>>(out);
}

// round 15
// speedup vs baseline: 2.0188x; 1.5761x over previous
#include <cuda_runtime.h>
#include <cuda_bf16.h>
#include <math.h>

#define BB 64
#define PP 512
#define NN 512
#define EE 128
#define FFD 512
#define LLAYERS 6
#define M_TOT (BB*NN)
#define EPS 1e-5f
#define INV_SQRT_E 0.08838834764831845f

typedef unsigned short u16;
typedef unsigned int   u32;
typedef unsigned long long u64;

#define TS 20                 /* smem row stride in u32 (80B), conflict-free */
#define SZU (128*TS)          /* u32 per 128-row buffer */
#define SZH (64*TS)           /* u32 per 64-row buffer  */
#define SMEM_SZ (8*SZU*4)     /* 81920 B: 2 stages x (A hi/lo + B hi/lo)    */

// ---------------- f32 scratch ----------------
__device__ float g_x  [BB*NN*EE];
__device__ float g_y  [BB*NN*EE];
__device__ float g_h  [BB*NN*EE];
__device__ float g_sq [BB*NN*EE];
__device__ float g_ek [BB*NN*EE];
__device__ float g_ekv[BB*NN*EE];
__device__ float g_gq [BB*EE];
__device__ float g_gm [BB*EE];
// ---------------- bf16 hi/lo scratch ----------------
__device__ u16 g_xH  [M_TOT*EE],  g_xL  [M_TOT*EE];
__device__ u16 g_hH  [M_TOT*EE],  g_hL  [M_TOT*EE];
__device__ u16 g_hidH[M_TOT*FFD], g_hidL[M_TOT*FFD];
__device__ u16 g_aftH[BB*PP*EE],  g_aftL[BB*PP*EE];
__device__ u16 g_ekTH [BB*EE*NN], g_ekTL [BB*EE*NN];
__device__ u16 g_ekvTH[BB*EE*NN], g_ekvTL[BB*EE*NN];
// weights (transposed [n][k])
__device__ u16 g_wqTH[LLAYERS*EE*EE],  g_wqTL[LLAYERS*EE*EE];
__device__ u16 g_wkTH[LLAYERS*EE*EE],  g_wkTL[LLAYERS*EE*EE];
__device__ u16 g_wvTH[LLAYERS*EE*EE],  g_wvTL[LLAYERS*EE*EE];
__device__ u16 g_w1TH[LLAYERS*FFD*EE], g_w1TL[LLAYERS*FFD*EE];
__device__ u16 g_w2TH[LLAYERS*EE*FFD], g_w2TL[LLAYERS*EE*FFD];
__device__ u16 g_dkTH[EE*EE], g_dkTL[EE*EE];
__device__ u16 g_dvTH[EE*EE], g_dvTL[EE*EE];

// ================= helpers =================
__device__ __forceinline__ void cvt_hl(float x, u16& h, u16& l) {
    __nv_bfloat16 bh = __float2bfloat16(x);
    float hf = __bfloat162float(bh);
    __nv_bfloat16 bl = __float2bfloat16(x - hf);
    h = __bfloat16_as_ushort(bh);
    l = __bfloat16_as_ushort(bl);
}
__device__ __forceinline__ void pack_hl(float x, float y, u32& h, u32& l) {
    u16 hx, lx, hy, ly;
    cvt_hl(x, hx, lx); cvt_hl(y, hy, ly);
    h = (u32)hx | ((u32)hy << 16);
    l = (u32)lx | ((u32)ly << 16);
}
__device__ __forceinline__ u32 smem_u32(const void* p) {
    u32 a; asm("{ .reg .u64 t; cvta.to.shared.u64 t, %1; cvt.u32.u64 %0, t; }"
               : "=r"(a) : "l"(p));
    return a;
}

#define MMAB(d, a, b)                                                        \
    asm volatile("mma.sync.aligned.m16n8k16.row.col.f32.bf16.bf16.f32 "      \
        "{%0,%1,%2,%3},{%4,%5,%6,%7},{%8,%9},{%0,%1,%2,%3};"                 \
        : "+f"(d[0]), "+f"(d[1]), "+f"(d[2]), "+f"(d[3])                     \
        : "r"(a[0]), "r"(a[1]), "r"(a[2]), "r"(a[3]), "r"(b[0]), "r"(b[1]))

// cp.async
__device__ __forceinline__ void cpa16(u32 dst, const void* src) {
    asm volatile("cp.async.cg.shared.global [%0], [%1], 16;" :: "r"(dst), "l"(src));
}
#define CPA_COMMIT() asm volatile("cp.async.commit_group;" ::: "memory")
#define CPA_WAIT0()  asm volatile("cp.async.wait_group 0;" ::: "memory")

// ---------- async tile loaders (256 threads, BK=32) ----------
__device__ __forceinline__ void ld128_async(const u16* __restrict__ GH,
                                            const u16* __restrict__ GL, size_t ld,
                                            int r0, int k0, u32 SH, u32 SL, int tid) {
    int r = tid >> 1;
    int hb = (tid & 1)*32;
    const char* pH = (const char*)(GH + (size_t)(r0 + r)*ld + k0) + hb;
    const char* pL = (const char*)(GL + (size_t)(r0 + r)*ld + k0) + hb;
    u32 dH = SH + (u32)r*(TS*4) + hb;
    u32 dL = SL + (u32)r*(TS*4) + hb;
    cpa16(dH, pH); cpa16(dH + 16, pH + 16);
    cpa16(dL, pL); cpa16(dL + 16, pL + 16);
}
__device__ __forceinline__ void ld64x2_async(const u16* __restrict__ G1H,
                                             const u16* __restrict__ G1L,
                                             const u16* __restrict__ G2H,
                                             const u16* __restrict__ G2L, size_t ld,
                                             int n0, int k0,
                                             u32 B1H, u32 B1L, u32 B2H, u32 B2L,
                                             int tid) {
    int t = tid & 127;
    int r = t >> 1;
    int hb = (t & 1)*32;
    const u16* sH; const u16* sL; u32 dH, dL;
    if (tid < 128) { sH = G1H; sL = G1L; dH = B1H; dL = B1L; }
    else           { sH = G2H; sL = G2L; dH = B2H; dL = B2L; }
    const char* pH = (const char*)(sH + (size_t)(n0 + r)*ld + k0) + hb;
    const char* pL = (const char*)(sL + (size_t)(n0 + r)*ld + k0) + hb;
    dH += (u32)r*(TS*4) + hb;
    dL += (u32)r*(TS*4) + hb;
    cpa16(dH, pH); cpa16(dH + 16, pH + 16);
    cpa16(dL, pL); cpa16(dL + 16, pL + 16);
}

// ---------- computed A tiles (STS path) ----------
__device__ __forceinline__ void ld_Aexp(const float* __restrict__ G, size_t ld,
                                        int m0, int k0, u32* SH, u32* SL,
                                        int tid, float s) {
    int r = tid >> 1, c = (tid & 1)*16;
    const float* p = G + (size_t)(m0 + r)*ld + k0 + c;
    float v[16];
    #pragma unroll
    for (int q = 0; q < 4; q++) {
        float4 f = *(const float4*)(p + q*4);
        v[q*4+0]=f.x; v[q*4+1]=f.y; v[q*4+2]=f.z; v[q*4+3]=f.w;
    }
    u32 h[8], l[8];
    #pragma unroll
    for (int q = 0; q < 8; q++)
        pack_hl(__expf(s*v[2*q]), __expf(s*v[2*q+1]), h[q], l[q]);
    u32* dh = SH + r*TS + (tid & 1)*8;
    u32* dl = SL + r*TS + (tid & 1)*8;
    *(uint4*)dh = *(uint4*)h; *((uint4*)dh+1) = *(uint4*)(h+4);
    *(uint4*)dl = *(uint4*)l; *((uint4*)dl+1) = *(uint4*)(l+4);
}
__device__ __forceinline__ void ld_Aexpmask(const float* __restrict__ G,
                                            const float* __restrict__ Msk, size_t ld,
                                            int m0, int k0, u32* SH, u32* SL,
                                            int tid, float s) {
    int r = tid >> 1, c = (tid & 1)*16;
    size_t off = (size_t)(m0 + r)*ld + k0 + c;
    float v[16];
    #pragma unroll
    for (int q = 0; q < 4; q++) {
        float4 f = *(const float4*)(G + off + q*4);
        float4 m = *(const float4*)(Msk + off + q*4);
        v[q*4+0]=s*f.x+m.x; v[q*4+1]=s*f.y+m.y; v[q*4+2]=s*f.z+m.z; v[q*4+3]=s*f.w+m.w;
    }
    u32 h[8], l[8];
    #pragma unroll
    for (int q = 0; q < 8; q++)
        pack_hl(__expf(v[2*q]), __expf(v[2*q+1]), h[q], l[q]);
    u32* dh = SH + r*TS + (tid & 1)*8;
    u32* dl = SL + r*TS + (tid & 1)*8;
    *(uint4*)dh = *(uint4*)h; *((uint4*)dh+1) = *(uint4*)(h+4);
    *(uint4*)dl = *(uint4*)l; *((uint4*)dl+1) = *(uint4*)(l+4);
}

// ---------- warp mma over a 128x32 A tile, BN=128 ----------
__device__ __forceinline__ void mma128(const u32* AH, const u32* AL,
                                       const u32* BH, const u32* BL,
                                       float d[2][8][4],
                                       int wr0, int wc0, int qr, int qc) {
    #pragma unroll
    for (int ks = 0; ks < 2; ks++) {
        int ku = ks*8;
        u32 ah[2][4], al[2][4];
        #pragma unroll
        for (int i = 0; i < 2; i++) {
            int r = wr0 + i*16 + qr;
            ah[i][0]=AH[r*TS+ku+qc];     ah[i][1]=AH[(r+8)*TS+ku+qc];
            ah[i][2]=AH[r*TS+ku+qc+4];   ah[i][3]=AH[(r+8)*TS+ku+qc+4];
            al[i][0]=AL[r*TS+ku+qc];     al[i][1]=AL[(r+8)*TS+ku+qc];
            al[i][2]=AL[r*TS+ku+qc+4];   al[i][3]=AL[(r+8)*TS+ku+qc+4];
        }
        #pragma unroll
        for (int j = 0; j < 8; j++) {
            int n = wc0 + j*8 + qr;
            u32 bh[2] = {BH[n*TS+ku+qc], BH[n*TS+ku+qc+4]};
            u32 bl[2] = {BL[n*TS+ku+qc], BL[n*TS+ku+qc+4]};
            #pragma unroll
            for (int i = 0; i < 2; i++) {
                MMAB(d[i][j], ah[i], bh);
                MMAB(d[i][j], al[i], bh);
                MMAB(d[i][j], ah[i], bl);
            }
        }
    }
}
// ---------- warp mma, BN=64 dual B (num/den) ----------
__device__ __forceinline__ void mma64x2(const u32* AH, const u32* AL,
                                        const u32* B1H, const u32* B1L,
                                        const u32* B2H, const u32* B2L,
                                        float d1[2][4][4], float d2[2][4][4],
                                        int wr0, int wc0, int qr, int qc) {
    #pragma unroll
    for (int ks = 0; ks < 2; ks++) {
        int ku = ks*8;
        u32 ah[2][4], al[2][4];
        #pragma unroll
        for (int i = 0; i < 2; i++) {
            int r = wr0 + i*16 + qr;
            ah[i][0]=AH[r*TS+ku+qc];     ah[i][1]=AH[(r+8)*TS+ku+qc];
            ah[i][2]=AH[r*TS+ku+qc+4];   ah[i][3]=AH[(r+8)*TS+ku+qc+4];
            al[i][0]=AL[r*TS+ku+qc];     al[i][1]=AL[(r+8)*TS+ku+qc];
            al[i][2]=AL[r*TS+ku+qc+4];   al[i][3]=AL[(r+8)*TS+ku+qc+4];
        }
        #pragma unroll
        for (int j = 0; j < 4; j++) {
            int n = wc0 + j*8 + qr;
            {
                u32 bh[2] = {B1H[n*TS+ku+qc], B1H[n*TS+ku+qc+4]};
                u32 bl[2] = {B1L[n*TS+ku+qc], B1L[n*TS+ku+qc+4]};
                #pragma unroll
                for (int i = 0; i < 2; i++) {
                    MMAB(d1[i][j], ah[i], bh);
                    MMAB(d1[i][j], al[i], bh);
                    MMAB(d1[i][j], ah[i], bl);
                }
            }
            {
                u32 bh[2] = {B2H[n*TS+ku+qc], B2H[n*TS+ku+qc+4]};
                u32 bl[2] = {B2L[n*TS+ku+qc], B2L[n*TS+ku+qc+4]};
                #pragma unroll
                for (int i = 0; i < 2; i++) {
                    MMAB(d2[i][j], ah[i], bh);
                    MMAB(d2[i][j], al[i], bh);
                    MMAB(d2[i][j], ah[i], bl);
                }
            }
        }
    }
}

// =====================================================================
// qkv (pass-parallel): grid.y+pbase selects pass.
// pass0 -> SQ=sigmoid(q), pass1 -> EK=exp(k), pass2 -> V raw
// =====================================================================
__global__ __launch_bounds__(256, 2) void qkv_tc(
        const u16* __restrict__ XH, const u16* __restrict__ XL,
        const u16* __restrict__ W0H, const u16* __restrict__ W0L,
        const u16* __restrict__ W1H_, const u16* __restrict__ W1L_,
        const u16* __restrict__ W2H_, const u16* __restrict__ W2L_,
        float* __restrict__ SQ, float* __restrict__ EK, float* __restrict__ V,
        int pbase) {
    extern __shared__ u32 smu[];
    const u32 sb = smem_u32(smu);
    const int tid = threadIdx.x, lane = tid & 31, w = tid >> 5;
    const int wr0 = (w >> 1)*32, wc0 = (w & 1)*64;
    const int qr = lane >> 2, qc = lane & 3;
    const int m0 = blockIdx.x*128;
    const int pass = blockIdx.y + pbase;
    const u16* BgH = (pass == 0) ? W0H : (pass == 1) ? W1H_ : W2H_;
    const u16* BgL = (pass == 0) ? W0L : (pass == 1) ? W1L_ : W2L_;

    ld128_async(XH, XL, EE, m0, 0, sb, sb + SZU*4, tid);
    ld128_async(BgH, BgL, EE, 0, 0, sb + 4*SZU*4, sb + 5*SZU*4, tid);
    CPA_COMMIT();
    float d[2][8][4] = {};
    for (int t = 0; t < 4; t++) {
        CPA_WAIT0();
        __syncthreads();
        if (t + 1 < 4) {
            int s2 = (t+1) & 1, k2 = (t+1)*32;
            ld128_async(XH, XL, EE, m0, k2,
                        sb + (s2*2)*SZU*4, sb + (s2*2+1)*SZU*4, tid);
            ld128_async(BgH, BgL, EE, 0, k2,
                        sb + (4+s2*2)*SZU*4, sb + (5+s2*2)*SZU*4, tid);
            CPA_COMMIT();
        }
        int s = t & 1;
        mma128(smu + s*2*SZU, smu + (s*2+1)*SZU,
               smu + (4+s*2)*SZU, smu + (5+s*2)*SZU, d, wr0, wc0, qr, qc);
    }
    #pragma unroll
    for (int i = 0; i < 2; i++)
        #pragma unroll
        for (int h = 0; h < 2; h++) {
            int row = m0 + wr0 + i*16 + qr + h*8;
            #pragma unroll
            for (int j = 0; j < 8; j++) {
                int col = wc0 + j*8 + qc*2;
                size_t o = (size_t)row*EE + col;
                float v0 = d[i][j][h*2], v1 = d[i][j][h*2+1];
                if (pass == 0) {
                    *(float2*)&SQ[o] = make_float2(
                        1.f/(1.f + __expf(-v0)), 1.f/(1.f + __expf(-v1)));
                } else if (pass == 1) {
                    *(float2*)&EK[o] = make_float2(__expf(v0), __expf(v1));
                } else {
                    *(float2*)&V[o] = make_float2(v0, v1);
                }
            }
        }
}

// =====================================================================
// encoder AFT: A=exp(s*dist) computed, dual B async; single-sync loop
// =====================================================================
__global__ __launch_bounds__(256, 2) void aft_enc_tc(
        const float* __restrict__ dist,
        const float* __restrict__ ls,
        const float* __restrict__ alpha, int l,
        const u16* __restrict__ EKVTH, const u16* __restrict__ EKVTL,
        const u16* __restrict__ EKTH,  const u16* __restrict__ EKTL,
        const float* __restrict__ X,
        const float* __restrict__ SQ,
        float* __restrict__ Y) {
    extern __shared__ u32 smu[];
    const u32 sb = smem_u32(smu);
    const int tid = threadIdx.x, lane = tid & 31, w = tid >> 5;
    const int wr0 = (w >> 1)*32, wc0 = (w & 1)*32;
    const int qr = lane >> 2, qc = lane & 3;
    const int b = blockIdx.z;
    const int m0 = blockIdx.x*128, n0 = blockIdx.y*64;
    const float s = ls[0]*alpha[l];
    const float* D = dist + (size_t)b*NN*NN;
    const u16* T1H = EKVTH + (size_t)b*EE*NN;
    const u16* T1L = EKVTL + (size_t)b*EE*NN;
    const u16* T2H = EKTH  + (size_t)b*EE*NN;
    const u16* T2L = EKTL  + (size_t)b*EE*NN;
    ld_Aexp(D, NN, m0, 0, smu, smu + SZU, tid, s);
    ld64x2_async(T1H, T1L, T2H, T2L, NN, n0, 0,
                 sb + 4*SZU*4, sb + (4*SZU+SZH)*4,
                 sb + (4*SZU+2*SZH)*4, sb + (4*SZU+3*SZH)*4, tid);
    CPA_COMMIT();
    float d1[2][4][4] = {}, d2[2][4][4] = {};
    for (int t = 0; t < 16; t++) {
        CPA_WAIT0();
        __syncthreads();
        if (t + 1 < 16) {
            int s2 = (t+1) & 1, k2 = (t+1)*32;
            u32 bbase = sb + (4 + s2*2)*SZU*4;
            ld64x2_async(T1H, T1L, T2H, T2L, NN, n0, k2,
                         bbase, bbase + SZH*4, bbase + 2*SZH*4, bbase + 3*SZH*4, tid);
            CPA_COMMIT();
        }
        int s1 = t & 1;
        u32 bo = (4 + s1*2)*SZU;
        mma64x2(smu + s1*2*SZU, smu + (s1*2+1)*SZU,
                smu + bo, smu + bo + SZH, smu + bo + 2*SZH, smu + bo + 3*SZH,
                d1, d2, wr0, wc0, qr, qc);
        if (t + 1 < 16) {
            int s2 = (t+1) & 1;
            ld_Aexp(D, NN, m0, (t+1)*32, smu + s2*2*SZU, smu + (s2*2+1)*SZU, tid, s);
        }
    }
    #pragma unroll
    for (int i = 0; i < 2; i++)
        #pragma unroll
        for (int h = 0; h < 2; h++) {
            int row = m0 + wr0 + i*16 + qr + h*8;
            #pragma unroll
            for (int j = 0; j < 4; j++) {
                int col = n0 + wc0 + j*8 + qc*2;
                size_t o = ((size_t)b*NN + row)*EE + col;
                float2 xv = *(const float2*)&X[o];
                float2 sv = *(const float2*)&SQ[o];
                float n0v = d1[i][j][h*2], n1v = d1[i][j][h*2+1];
                float de0 = d2[i][j][h*2], de1 = d2[i][j][h*2+1];
                *(float2*)&Y[o] = make_float2(
                    xv.x + sv.x*(n0v/de0), xv.y + sv.y*(n1v/de1));
            }
        }
}

// =====================================================================
// decoder AFT
// =====================================================================
__global__ __launch_bounds__(256, 2) void dec_aft_tc(
        const float* __restrict__ cur_dist,
        const float* __restrict__ ninf,
        const float* __restrict__ ls,
        const float* __restrict__ dalpha,
        const u16* __restrict__ EKVTH, const u16* __restrict__ EKVTL,
        const u16* __restrict__ EKTH,  const u16* __restrict__ EKTL,
        const float* __restrict__ GQ,
        const float* __restrict__ cap,
        const float* __restrict__ dWq,
        u16* __restrict__ AFTH, u16* __restrict__ AFTL) {
    extern __shared__ u32 smu[];
    const u32 sb = smem_u32(smu);
    const int tid = threadIdx.x, lane = tid & 31, w = tid >> 5;
    const int wr0 = (w >> 1)*32, wc0 = (w & 1)*32;
    const int qr = lane >> 2, qc = lane & 3;
    const int b = blockIdx.z;
    const int m0 = blockIdx.x*128, n0 = blockIdx.y*64;
    const float s = ls[0]*dalpha[0];
    const float* CD = cur_dist + (size_t)b*PP*NN;
    const float* NM = ninf     + (size_t)b*PP*NN;
    const u16* T1H = EKVTH + (size_t)b*EE*NN;
    const u16* T1L = EKVTL + (size_t)b*EE*NN;
    const u16* T2H = EKTH  + (size_t)b*EE*NN;
    const u16* T2L = EKTL  + (size_t)b*EE*NN;
    ld_Aexpmask(CD, NM, NN, m0, 0, smu, smu + SZU, tid, s);
    ld64x2_async(T1H, T1L, T2H, T2L, NN, n0, 0,
                 sb + 4*SZU*4, sb + (4*SZU+SZH)*4,
                 sb + (4*SZU+2*SZH)*4, sb + (4*SZU+3*SZH)*4, tid);
    CPA_COMMIT();
    float d1[2][4][4] = {}, d2[2][4][4] = {};
    for (int t = 0; t < 16; t++) {
        CPA_WAIT0();
        __syncthreads();
        if (t + 1 < 16) {
            int s2 = (t+1) & 1, k2 = (t+1)*32;
            u32 bbase = sb + (4 + s2*2)*SZU*4;
            ld64x2_async(T1H, T1L, T2H, T2L, NN, n0, k2,
                         bbase, bbase + SZH*4, bbase + 2*SZH*4, bbase + 3*SZH*4, tid);
            CPA_COMMIT();
        }
        int s1 = t & 1;
        u32 bo = (4 + s1*2)*SZU;
        mma64x2(smu + s1*2*SZU, smu + (s1*2+1)*SZU,
                smu + bo, smu + bo + SZH, smu + bo + 2*SZH, smu + bo + 3*SZH,
                d1, d2, wr0, wc0, qr, qc);
        if (t + 1 < 16) {
            int s2 = (t+1) & 1;
            ld_Aexpmask(CD, NM, NN, m0, (t+1)*32,
                        smu + s2*2*SZU, smu + (s2*2+1)*SZU, tid, s);
        }
    }
    #pragma unroll
    for (int i = 0; i < 2; i++)
        #pragma unroll
        for (int h = 0; h < 2; h++) {
            int p = m0 + wr0 + i*16 + qr + h*8;
            float cv = cap[(size_t)b*PP + p];
            #pragma unroll
            for (int j = 0; j < 4; j++) {
                int col = n0 + wc0 + j*8 + qc*2;
                float2 gq2 = *(const float2*)&GQ[b*EE + col];
                float2 wq2 = *(const float2*)&dWq[EE*EE + col];
                float q0 = gq2.x + cv*wq2.x;
                float q1 = gq2.y + cv*wq2.y;
                float sg0 = 1.f/(1.f + __expf(-q0));
                float sg1 = 1.f/(1.f + __expf(-q1));
                float v0 = sg0*(d1[i][j][h*2]  /d2[i][j][h*2]);
                float v1 = sg1*(d1[i][j][h*2+1]/d2[i][j][h*2+1]);
                u32 hh, ll; pack_hl(v0, v1, hh, ll);
                size_t o = ((size_t)b*PP + p)*EE + col;
                *(u32*)&AFTH[o] = hh;
                *(u32*)&AFTL[o] = ll;
            }
        }
}

// =====================================================================
// FF1: hid = relu(h@W1 + b1) -> bf16 hi/lo
// =====================================================================
__global__ __launch_bounds__(256, 2) void ff1_tc(
        const u16* __restrict__ HH, const u16* __restrict__ HL,
        const u16* __restrict__ W1H, const u16* __restrict__ W1L,
        const float* __restrict__ b1,
        u16* __restrict__ HIDH, u16* __restrict__ HIDL) {
    extern __shared__ u32 smu[];
    const u32 sb = smem_u32(smu);
    const int tid = threadIdx.x, lane = tid & 31, w = tid >> 5;
    const int wr0 = (w >> 1)*32, wc0 = (w & 1)*64;
    const int qr = lane >> 2, qc = lane & 3;
    const int m0 = blockIdx.x*128, n0 = blockIdx.y*128;
    ld128_async(HH, HL, EE, m0, 0, sb, sb + SZU*4, tid);
    ld128_async(W1H, W1L, EE, n0, 0, sb + 4*SZU*4, sb + 5*SZU*4, tid);
    CPA_COMMIT();
    float d[2][8][4] = {};
    for (int t = 0; t < 4; t++) {
        CPA_WAIT0();
        __syncthreads();
        if (t + 1 < 4) {
            int s2 = (t+1) & 1, k2 = (t+1)*32;
            ld128_async(HH, HL, EE, m0, k2,
                        sb + (s2*2)*SZU*4, sb + (s2*2+1)*SZU*4, tid);
            ld128_async(W1H, W1L, EE, n0, k2,
                        sb + (4+s2*2)*SZU*4, sb + (5+s2*2)*SZU*4, tid);
            CPA_COMMIT();
        }
        int s = t & 1;
        mma128(smu + s*2*SZU, smu + (s*2+1)*SZU,
               smu + (4+s*2)*SZU, smu + (5+s*2)*SZU, d, wr0, wc0, qr, qc);
    }
    #pragma unroll
    for (int i = 0; i < 2; i++)
        #pragma unroll
        for (int h = 0; h < 2; h++) {
            int row = m0 + wr0 + i*16 + qr + h*8;
            #pragma unroll
            for (int j = 0; j < 8; j++) {
                int col = n0 + wc0 + j*8 + qc*2;
                float2 bb = *(const float2*)&b1[col];
                float v0 = fmaxf(d[i][j][h*2]   + bb.x, 0.f);
                float v1 = fmaxf(d[i][j][h*2+1] + bb.y, 0.f);
                u32 hh, ll; pack_hl(v0, v1, hh, ll);
                size_t o = (size_t)row*FFD + col;
                *(u32*)&HIDH[o] = hh;
                *(u32*)&HIDL[o] = ll;
            }
        }
}

// =====================================================================
// FF2: y = h + hid@W2 + b2  (K=512, 16 chunks)
// =====================================================================
__global__ __launch_bounds__(256, 2) void ff2_tc(
        const u16* __restrict__ HIDH, const u16* __restrict__ HIDL,
        const u16* __restrict__ W2H, const u16* __restrict__ W2L,
        const float* __restrict__ b2,
        const float* __restrict__ H,
        float* __restrict__ Y) {
    extern __shared__ u32 smu[];
    const u32 sb = smem_u32(smu);
    const int tid = threadIdx.x, lane = tid & 31, w = tid >> 5;
    const int wr0 = (w >> 1)*32, wc0 = (w & 1)*64;
    const int qr = lane >> 2, qc = lane & 3;
    const int m0 = blockIdx.x*128;
    ld128_async(HIDH, HIDL, FFD, m0, 0, sb, sb + SZU*4, tid);
    ld128_async(W2H, W2L, FFD, 0, 0, sb + 4*SZU*4, sb + 5*SZU*4, tid);
    CPA_COMMIT();
    float d[2][8][4] = {};
    for (int t = 0; t < 16; t++) {
        CPA_WAIT0();
        __syncthreads();
        if (t + 1 < 16) {
            int s2 = (t+1) & 1, k2 = (t+1)*32;
            ld128_async(HIDH, HIDL, FFD, m0, k2,
                        sb + (s2*2)*SZU*4, sb + (s2*2+1)*SZU*4, tid);
            ld128_async(W2H, W2L, FFD, 0, k2,
                        sb + (4+s2*2)*SZU*4, sb + (5+s2*2)*SZU*4, tid);
            CPA_COMMIT();
        }
        int s = t & 1;
        mma128(smu + s*2*SZU, smu + (s*2+1)*SZU,
               smu + (4+s*2)*SZU, smu + (5+s*2)*SZU, d, wr0, wc0, qr, qc);
    }
    #pragma unroll
    for (int i = 0; i < 2; i++)
        #pragma unroll
        for (int h = 0; h < 2; h++) {
            int row = m0 + wr0 + i*16 + qr + h*8;
            #pragma unroll
            for (int j = 0; j < 8; j++) {
                int col = wc0 + j*8 + qc*2;
                float2 bb = *(const float2*)&b2[col];
                size_t o = (size_t)row*EE + col;
                float2 hv = *(const float2*)&H[o];
                *(float2*)&Y[o] = make_float2(
                    hv.x + d[i][j][h*2]   + bb.x,
                    hv.y + d[i][j][h*2+1] + bb.y);
            }
        }
}

// =====================================================================
// score: S = aft @ enc^T + epilogue (K=128)
// =====================================================================
__global__ __launch_bounds__(256, 2) void score_tc(
        const u16* __restrict__ AFTH, const u16* __restrict__ AFTL,
        const u16* __restrict__ XH, const u16* __restrict__ XL,
        const float* __restrict__ cur_dist,
        const float* __restrict__ ninf,
        const float* __restrict__ ls,
        const float* __restrict__ palpha,
        float* __restrict__ OUT) {
    extern __shared__ u32 smu[];
    const u32 sb = smem_u32(smu);
    const int tid = threadIdx.x, lane = tid & 31, w = tid >> 5;
    const int wr0 = (w >> 1)*32, wc0 = (w & 1)*64;
    const int qr = lane >> 2, qc = lane & 3;
    const int b = blockIdx.z;
    const int p0 = blockIdx.x*128, n0 = blockIdx.y*128;
    const float ps = ls[0]*palpha[0];
    const u16* AgH = AFTH + (size_t)b*PP*EE;
    const u16* AgL = AFTL + (size_t)b*PP*EE;
    const u16* BgH = XH + (size_t)b*NN*EE;
    const u16* BgL = XL + (size_t)b*NN*EE;
    ld128_async(AgH, AgL, EE, p0, 0, sb, sb + SZU*4, tid);
    ld128_async(BgH, BgL, EE, n0, 0, sb + 4*SZU*4, sb + 5*SZU*4, tid);
    CPA_COMMIT();
    float d[2][8][4] = {};
    for (int t = 0; t < 4; t++) {
        CPA_WAIT0();
        __syncthreads();
        if (t + 1 < 4) {
            int s2 = (t+1) & 1, k2 = (t+1)*32;
            ld128_async(AgH, AgL, EE, p0, k2,
                        sb + (s2*2)*SZU*4, sb + (s2*2+1)*SZU*4, tid);
            ld128_async(BgH, BgL, EE, n0, k2,
                        sb + (4+s2*2)*SZU*4, sb + (5+s2*2)*SZU*4, tid);
            CPA_COMMIT();
        }
        int s = t & 1;
        mma128(smu + s*2*SZU, smu + (s*2+1)*SZU,
               smu + (4+s*2)*SZU, smu + (5+s*2)*SZU, d, wr0, wc0, qr, qc);
    }
    #pragma unroll
    for (int i = 0; i < 2; i++)
        #pragma unroll
        for (int h = 0; h < 2; h++) {
            int p = p0 + wr0 + i*16 + qr + h*8;
            #pragma unroll
            for (int j = 0; j < 8; j++) {
                int n = n0 + wc0 + j*8 + qc*2;
                size_t o = ((size_t)b*PP + p)*NN + n;
                float2 cd = *(const float2*)&cur_dist[o];
                float2 nm = *(const float2*)&ninf[o];
                float s0 = d[i][j][h*2]  *INV_SQRT_E + ps*cd.x;
                float s1 = d[i][j][h*2+1]*INV_SQRT_E + ps*cd.y;
                *(float2*)&OUT[o] = make_float2(
                    10.f*tanhf(s0) + nm.x, 10.f*tanhf(s1) + nm.y);
            }
        }
}

// =====================================================================
// weight transpose-convert (batched)
// =====================================================================
__device__ __forceinline__ void wconv_body(const float* __restrict__ src,
                                           u16* __restrict__ dH, u16* __restrict__ dL,
                                           int K, int N) {
    __shared__ float t[32][33];
    int n0 = blockIdx.x*32, k0 = blockIdx.y*32;
    int tr = threadIdx.x >> 3, tc4 = (threadIdx.x & 7)*4;
    float4 v = *(const float4*)&src[(size_t)(k0+tr)*N + n0 + tc4];
    t[tc4+0][tr] = v.x; t[tc4+1][tr] = v.y;
    t[tc4+2][tr] = v.z; t[tc4+3][tr] = v.w;
    __syncthreads();
    int r = threadIdx.x >> 3, c4 = (threadIdx.x & 7)*4;
    u16 h[4], l[4];
    #pragma unroll
    for (int i = 0; i < 4; i++) cvt_hl(t[r][c4+i], h[i], l[i]);
    size_t o = (size_t)(n0+r)*K + k0 + c4;
    *(uint2*)&dH[o] = *(uint2*)h;
    *(uint2*)&dL[o] = *(uint2*)l;
}
__global__ void wconv_sq(const float* __restrict__ Wq, const float* __restrict__ Wk,
                         const float* __restrict__ Wv,
                         const float* __restrict__ dWk, const float* __restrict__ dWv,
                         u16* qH, u16* qL, u16* kH, u16* kL, u16* vH, u16* vL,
                         u16* dkH, u16* dkL, u16* dvH, u16* dvL) {
    int z = blockIdx.z;
    const float* src; u16 *dH, *dL;
    size_t off = (size_t)(z % 6)*EE*EE;
    if (z < 6)       { src = Wq + off; dH = qH + off; dL = qL + off; }
    else if (z < 12) { src = Wk + off; dH = kH + off; dL = kL + off; }
    else if (z < 18) { src = Wv + off; dH = vH + off; dL = vL + off; }
    else if (z == 18){ src = dWk; dH = dkH; dL = dkL; }
    else             { src = dWv; dH = dvH; dL = dvL; }
    wconv_body(src, dH, dL, EE, EE);
}
__global__ void wconv_w1(const float* __restrict__ W1, u16* dH, u16* dL) {
    int l = blockIdx.z;
    wconv_body(W1 + (size_t)l*EE*FFD, dH + (size_t)l*FFD*EE, dL + (size_t)l*FFD*EE,
               EE, FFD);
}
__global__ void wconv_w2(const float* __restrict__ W2, u16* dH, u16* dL) {
    int l = blockIdx.z;
    wconv_body(W2 + (size_t)l*FFD*EE, dH + (size_t)l*EE*FFD, dL + (size_t)l*EE*FFD,
               FFD, EE);
}

// =====================================================================
// ek/v transpose-convert: ekT = bf16(ek), ekvT = bf16(ek * v_raw)
// =====================================================================
__global__ void ekconv_kernel(const float* __restrict__ ek,
                              const float* __restrict__ vraw,
                              u16* __restrict__ ekTH, u16* __restrict__ ekTL,
                              u16* __restrict__ ekvTH, u16* __restrict__ ekvTL) {
    __shared__ float t1[32][33], t2[32][33];
    int b = blockIdx.z;
    int e0 = blockIdx.x*32, nd0 = blockIdx.y*32;
    const float* S1 = ek   + (size_t)b*NN*EE;
    const float* S2 = vraw + (size_t)b*NN*EE;
    int tr = threadIdx.x >> 3, tc4 = (threadIdx.x & 7)*4;
    size_t so = (size_t)(nd0+tr)*EE + e0 + tc4;
    float4 v1 = *(const float4*)&S1[so];
    float4 v2 = *(const float4*)&S2[so];
    t1[tc4+0][tr]=v1.x; t1[tc4+1][tr]=v1.y; t1[tc4+2][tr]=v1.z; t1[tc4+3][tr]=v1.w;
    t2[tc4+0][tr]=v2.x; t2[tc4+1][tr]=v2.y; t2[tc4+2][tr]=v2.z; t2[tc4+3][tr]=v2.w;
    __syncthreads();
    int r = threadIdx.x >> 3, c4 = (threadIdx.x & 7)*4;
    size_t o = (size_t)b*EE*NN + (size_t)(e0+r)*NN + nd0 + c4;
    u16 h[4], l[4];
    #pragma unroll
    for (int i = 0; i < 4; i++) cvt_hl(t1[r][c4+i], h[i], l[i]);
    *(uint2*)&ekTH[o] = *(uint2*)h; *(uint2*)&ekTL[o] = *(uint2*)l;
    #pragma unroll
    for (int i = 0; i < 4; i++) cvt_hl(t1[r][c4+i]*t2[r][c4+i], h[i], l[i]);
    *(uint2*)&ekvTH[o] = *(uint2*)h; *(uint2*)&ekvTL[o] = *(uint2*)l;
}

// ---------------- embedding (also writes bf16 hi/lo) ----------------
__global__ void embed_kernel(const float* __restrict__ data,
                             const float* __restrict__ W,
                             const float* __restrict__ bias,
                             float* __restrict__ X,
                             u16* __restrict__ XH, u16* __restrict__ XL) {
    int idx = blockIdx.x;
    int e   = threadIdx.x;
    float d0 = data[idx*2+0], d1 = data[idx*2+1];
    float v = d0*W[e] + d1*W[EE+e] + bias[e];
    size_t o = (size_t)idx*EE + e;
    X[o] = v;
    u16 h, l; cvt_hl(v, h, l);
    XH[o] = h; XL[o] = l;
}

// ---------------- instance norm (also emits bf16 hi/lo) ----------------
__global__ void inorm_kernel(const float* __restrict__ src,
                             float* __restrict__ dst,
                             u16* __restrict__ dstH, u16* __restrict__ dstL,
                             const float* __restrict__ w,
                             const float* __restrict__ bias) {
    int b = blockIdx.x;
    int e = threadIdx.x;
    int c = threadIdx.y;
    const float* S = src + (size_t)b*NN*EE;
    float s = 0.f, s2 = 0.f;
    for (int n = c*64; n < c*64 + 64; n++) {
        float v = S[(size_t)n*EE + e];
        s += v; s2 += v*v;
    }
    __shared__ float ssum[8][128], ssq[8][128];
    __shared__ float smu2[128], srs[128];
    ssum[c][e] = s; ssq[c][e] = s2;
    __syncthreads();
    if (c == 0) {
        float ts = 0.f, t2 = 0.f;
        #pragma unroll
        for (int i = 0; i < 8; i++) { ts += ssum[i][e]; t2 += ssq[i][e]; }
        float mu = ts*(1.f/NN);
        float var = t2*(1.f/NN) - mu*mu;
        smu2[e] = mu;
        srs[e] = rsqrtf(var + EPS);
    }
    __syncthreads();
    float mu = smu2[e], rs = srs[e], ww = w[e], bb = bias[e];
    size_t base = (size_t)b*NN*EE;
    for (int n = c*64; n < c*64 + 64; n++) {
        size_t o = base + (size_t)n*EE + e;
        float v = (S[(size_t)n*EE + e] - mu)*rs*ww + bb;
        dst[o] = v;
        u16 h, l; cvt_hl(v, h, l);
        dstH[o] = h; dstL[o] = l;
    }
}

// ---------------- graph mean over nodes ----------------
__global__ void gmean_kernel(const float* __restrict__ X, float* __restrict__ GM) {
    int b = blockIdx.x, e = threadIdx.x, c = threadIdx.y;
    float s = 0.f;
    for (int n = c*64; n < c*64 + 64; n++)
        s += X[((size_t)b*NN + n)*EE + e];
    __shared__ float sm[8][128];
    sm[c][e] = s;
    __syncthreads();
    if (c == 0) {
        float t = 0.f;
        #pragma unroll
        for (int i = 0; i < 8; i++) t += sm[i][e];
        GM[b*EE + e] = t*(1.f/NN);
    }
}

// ---------------- gq = gmean @ dWq[0:E,:] ----------------
__global__ void gq_kernel(const float* __restrict__ GM,
                          const float* __restrict__ dWq,
                          float* __restrict__ GQ) {
    int b = blockIdx.x, e = threadIdx.x;
    float acc = 0.f;
    for (int i = 0; i < EE; i++)
        acc += GM[b*EE + i]*dWq[i*EE + e];
    GQ[b*EE + e] = acc;
}

// ---------------- row softmax over last dim (512) ----------------
__global__ void softmax_kernel(float* __restrict__ OUT) {
    float* row = OUT + (size_t)blockIdx.x*NN;
    int t = threadIdx.x;
    float v[4];
    #pragma unroll
    for (int i = 0; i < 4; i++) v[i] = row[t + i*128];
    float m = fmaxf(fmaxf(v[0], v[1]), fmaxf(v[2], v[3]));
    __shared__ float red[4];
    #pragma unroll
    for (int off = 16; off > 0; off >>= 1)
        m = fmaxf(m, __shfl_xor_sync(0xffffffff, m, off));
    if ((t & 31) == 0) red[t >> 5] = m;
    __syncthreads();
    m = fmaxf(fmaxf(red[0], red[1]), fmaxf(red[2], red[3]));
    __syncthreads();
    float s = 0.f;
    #pragma unroll
    for (int i = 0; i < 4; i++) { v[i] = __expf(v[i] - m); s += v[i]; }
    #pragma unroll
    for (int off = 16; off > 0; off >>= 1)
        s += __shfl_xor_sync(0xffffffff, s, off);
    if ((t & 31) == 0) red[t >> 5] = s;
    __syncthreads();
    s = red[0] + red[1] + red[2] + red[3];
    float inv = 1.f/s;
    #pragma unroll
    for (int i = 0; i < 4; i++) row[t + i*128] = v[i]*inv;
}

// ---------------- launch ----------------
extern "C" void kernel_launch(void* const* d_in, const int* in_sizes, int n_in,
                              void* d_out, int out_size) {
    const float* data      = (const float*)d_in[0];
    const float* dist      = (const float*)d_in[1];
    const float* cur_dist  = (const float*)d_in[2];
    const float* capacity  = (const float*)d_in[3];
    const float* ninf_mask = (const float*)d_in[4];
    const float* log_scale = (const float*)d_in[5];
    const float* emb_W     = (const float*)d_in[6];
    const float* emb_b     = (const float*)d_in[7];
    const float* Wq        = (const float*)d_in[8];
    const float* Wk        = (const float*)d_in[9];
    const float* Wv        = (const float*)d_in[10];
    const float* aft_alpha = (const float*)d_in[11];
    const float* n1_w      = (const float*)d_in[12];
    const float* n1_b      = (const float*)d_in[13];
    const float* ff_W1     = (const float*)d_in[14];
    const float* ff_b1     = (const float*)d_in[15];
    const float* ff_W2     = (const float*)d_in[16];
    const float* ff_b2     = (const float*)d_in[17];
    const float* n2_w      = (const float*)d_in[18];
    const float* n2_b      = (const float*)d_in[19];
    const float* dWq       = (const float*)d_in[20];
    const float* dWk       = (const float*)d_in[21];
    const float* dWv       = (const float*)d_in[22];
    const float* dec_alpha = (const float*)d_in[23];
    const float* p_alpha   = (const float*)d_in[24];
    float* out = (float*)d_out;

    float *x, *y, *h, *sq, *ek, *ekv, *gq, *gm;
    cudaGetSymbolAddress((void**)&x,   g_x);
    cudaGetSymbolAddress((void**)&y,   g_y);
    cudaGetSymbolAddress((void**)&h,   g_h);
    cudaGetSymbolAddress((void**)&sq,  g_sq);
    cudaGetSymbolAddress((void**)&ek,  g_ek);
    cudaGetSymbolAddress((void**)&ekv, g_ekv);
    cudaGetSymbolAddress((void**)&gq,  g_gq);
    cudaGetSymbolAddress((void**)&gm,  g_gm);

    u16 *xH,*xL,*hH,*hL,*hidH,*hidL,*aftH,*aftL;
    u16 *ekTH,*ekTL,*ekvTH,*ekvTL;
    u16 *wqTH,*wqTL,*wkTH,*wkTL,*wvTH,*wvTL,*w1TH,*w1TL,*w2TH,*w2TL;
    u16 *dkTH,*dkTL,*dvTH,*dvTL;
    cudaGetSymbolAddress((void**)&xH,   g_xH);   cudaGetSymbolAddress((void**)&xL,   g_xL);
    cudaGetSymbolAddress((void**)&hH,   g_hH);   cudaGetSymbolAddress((void**)&hL,   g_hL);
    cudaGetSymbolAddress((void**)&hidH, g_hidH); cudaGetSymbolAddress((void**)&hidL, g_hidL);
    cudaGetSymbolAddress((void**)&aftH, g_aftH); cudaGetSymbolAddress((void**)&aftL, g_aftL);
    cudaGetSymbolAddress((void**)&ekTH, g_ekTH); cudaGetSymbolAddress((void**)&ekTL, g_ekTL);
    cudaGetSymbolAddress((void**)&ekvTH,g_ekvTH);cudaGetSymbolAddress((void**)&ekvTL,g_ekvTL);
    cudaGetSymbolAddress((void**)&wqTH, g_wqTH); cudaGetSymbolAddress((void**)&wqTL, g_wqTL);
    cudaGetSymbolAddress((void**)&wkTH, g_wkTH); cudaGetSymbolAddress((void**)&wkTL, g_wkTL);
    cudaGetSymbolAddress((void**)&wvTH, g_wvTH); cudaGetSymbolAddress((void**)&wvTL, g_wvTL);
    cudaGetSymbolAddress((void**)&w1TH, g_w1TH); cudaGetSymbolAddress((void**)&w1TL, g_w1TL);
    cudaGetSymbolAddress((void**)&w2TH, g_w2TH); cudaGetSymbolAddress((void**)&w2TL, g_w2TL);
    cudaGetSymbolAddress((void**)&dkTH, g_dkTH); cudaGetSymbolAddress((void**)&dkTL, g_dkTL);
    cudaGetSymbolAddress((void**)&dvTH, g_dvTH); cudaGetSymbolAddress((void**)&dvTL, g_dvTL);

    cudaFuncSetAttribute(qkv_tc,     cudaFuncAttributeMaxDynamicSharedMemorySize, SMEM_SZ);
    cudaFuncSetAttribute(aft_enc_tc, cudaFuncAttributeMaxDynamicSharedMemorySize, SMEM_SZ);
    cudaFuncSetAttribute(dec_aft_tc, cudaFuncAttributeMaxDynamicSharedMemorySize, SMEM_SZ);
    cudaFuncSetAttribute(ff1_tc,     cudaFuncAttributeMaxDynamicSharedMemorySize, SMEM_SZ);
    cudaFuncSetAttribute(ff2_tc,     cudaFuncAttributeMaxDynamicSharedMemorySize, SMEM_SZ);
    cudaFuncSetAttribute(score_tc,   cudaFuncAttributeMaxDynamicSharedMemorySize, SMEM_SZ);

    // ---- batched weight transpose+convert (3 launches) ----
    wconv_sq<<<dim3(EE/32, EE/32, 20), 256>>>(Wq, Wk, Wv, dWk, dWv,
        wqTH, wqTL, wkTH, wkTL, wvTH, wvTL, dkTH, dkTL, dvTH, dvTL);
    wconv_w1<<<dim3(FFD/32, EE/32, LLAYERS), 256>>>(ff_W1, w1TH, w1TL);
    wconv_w2<<<dim3(EE/32, FFD/32, LLAYERS), 256>>>(ff_W2, w2TH, w2TL);

    embed_kernel<<<M_TOT, EE>>>(data, emb_W, emb_b, x, xH, xL);

    for (int l = 0; l < LLAYERS; l++) {
        // 3 independent passes: q->SQ, k->EK, v->Vraw(in ekv buffer)
        qkv_tc<<<dim3(M_TOT/128, 3), 256, SMEM_SZ>>>(
            xH, xL,
            wqTH + (size_t)l*EE*EE, wqTL + (size_t)l*EE*EE,
            wkTH + (size_t)l*EE*EE, wkTL + (size_t)l*EE*EE,
            wvTH + (size_t)l*EE*EE, wvTL + (size_t)l*EE*EE,
            sq, ek, ekv, 0);
        ekconv_kernel<<<dim3(EE/32, NN/32, BB), 256>>>(ek, ekv, ekTH, ekTL, ekvTH, ekvTL);
        aft_enc_tc<<<dim3(NN/128, EE/64, BB), 256, SMEM_SZ>>>(
            dist, log_scale, aft_alpha, l, ekvTH, ekvTL, ekTH, ekTL, x, sq, y);
        inorm_kernel<<<BB, dim3(128, 8)>>>(y, h, hH, hL, n1_w + l*EE, n1_b + l*EE);
        ff1_tc<<<dim3(M_TOT/128, FFD/128), 256, SMEM_SZ>>>(
            hH, hL, w1TH + (size_t)l*FFD*EE, w1TL + (size_t)l*FFD*EE,
            ff_b1 + l*FFD, hidH, hidL);
        ff2_tc<<<M_TOT/128, 256, SMEM_SZ>>>(
            hidH, hidL, w2TH + (size_t)l*EE*FFD, w2TL + (size_t)l*EE*FFD,
            ff_b2 + l*EE, h, y);
        inorm_kernel<<<BB, dim3(128, 8)>>>(y, x, xH, xL, n2_w + l*EE, n2_b + l*EE);
    }

    // decoder: passes 1,2 of qkv_tc (k->EK, v->Vraw)
    qkv_tc<<<dim3(M_TOT/128, 2), 256, SMEM_SZ>>>(
        xH, xL,
        dkTH, dkTL,       /* unused slot (pass 0 never taken) */
        dkTH, dkTL,       /* pass 1: dWk */
        dvTH, dvTL,       /* pass 2: dWv */
        sq, ek, ekv, 1);
    ekconv_kernel<<<dim3(EE/32, NN/32, BB), 256>>>(ek, ekv, ekTH, ekTL, ekvTH, ekvTL);
    gmean_kernel<<<BB, dim3(128, 8)>>>(x, gm);
    gq_kernel<<<BB, 128>>>(gm, dWq, gq);
    dec_aft_tc<<<dim3(PP/128, EE/64, BB), 256, SMEM_SZ>>>(
        cur_dist, ninf_mask, log_scale, dec_alpha,
        ekvTH, ekvTL, ekTH, ekTL, gq, capacity, dWq, aftH, aftL);
    score_tc<<<dim3(PP/128, NN/128, BB), 256, SMEM_SZ>>>(
        aftH, aftL, xH, xL, cur_dist, ninf_mask, log_scale, p_alpha, out);
    softmax_kernel<<<BB*PP, 128>>>(out);
}

// round 16
// speedup vs baseline: 2.5000x; 1.2383x over previous
#include <cuda_runtime.h>
#include <cuda_fp16.h>
#include <math.h>

#define BB 64
#define PP 512
#define NN 512
#define EE 128
#define FFD 512
#define LLAYERS 6
#define M_TOT (BB*NN)
#define EPS 1e-5f
#define INV_SQRT_E 0.08838834764831845f

typedef unsigned short u16;
typedef unsigned int   u32;
typedef unsigned long long u64;

#define TS 20                 /* smem row stride in u32 (80B), conflict-free */
#define SZU (128*TS)          /* u32 per 128-row buffer */
#define SZH (64*TS)           /* u32 per 64-row buffer  */
#define SMEM_SZ (6*SZU*4)     /* 61440 B: 2 stages x (A hi + A lo + B hi)   */

// ---------------- f32 scratch ----------------
__device__ float g_x  [BB*NN*EE];
__device__ float g_y  [BB*NN*EE];
__device__ float g_h  [BB*NN*EE];
__device__ float g_sq [BB*NN*EE];
__device__ float g_ek [BB*NN*EE];
__device__ float g_ekv[BB*NN*EE];
__device__ float g_gq [BB*EE];
__device__ float g_gm [BB*EE];
// ---------------- fp16 hi/lo scratch ----------------
__device__ u16 g_xH  [M_TOT*EE],  g_xL  [M_TOT*EE];
__device__ u16 g_hH  [M_TOT*EE],  g_hL  [M_TOT*EE];
__device__ u16 g_hidH[M_TOT*FFD], g_hidL[M_TOT*FFD];
__device__ u16 g_aftH[BB*PP*EE],  g_aftL[BB*PP*EE];
__device__ u16 g_ekTH [BB*EE*NN];
__device__ u16 g_ekvTH[BB*EE*NN];
// weights (transposed [n][k]) — B role only: hi only
__device__ u16 g_wqTH[LLAYERS*EE*EE];
__device__ u16 g_wkTH[LLAYERS*EE*EE];
__device__ u16 g_wvTH[LLAYERS*EE*EE];
__device__ u16 g_w1TH[LLAYERS*FFD*EE];
__device__ u16 g_w2TH[LLAYERS*EE*FFD];
__device__ u16 g_dkTH[EE*EE];
__device__ u16 g_dvTH[EE*EE];

// ================= helpers =================
__device__ __forceinline__ void cvt_hl(float x, u16& h, u16& l) {
    __half hh = __float2half_rn(x);
    float hf = __half2float(hh);
    __half ll = __float2half_rn(x - hf);
    h = __half_as_ushort(hh);
    l = __half_as_ushort(ll);
}
__device__ __forceinline__ u16 cvt_h(float x) {
    return __half_as_ushort(__float2half_rn(x));
}
__device__ __forceinline__ void pack_hl(float x, float y, u32& h, u32& l) {
    u16 hx, lx, hy, ly;
    cvt_hl(x, hx, lx); cvt_hl(y, hy, ly);
    h = (u32)hx | ((u32)hy << 16);
    l = (u32)lx | ((u32)ly << 16);
}
__device__ __forceinline__ u32 smem_u32(const void* p) {
    u32 a; asm("{ .reg .u64 t; cvta.to.shared.u64 t, %1; cvt.u32.u64 %0, t; }"
               : "=r"(a) : "l"(p));
    return a;
}

#define MMAB(d, a, b)                                                        \
    asm volatile("mma.sync.aligned.m16n8k16.row.col.f32.f16.f16.f32 "        \
        "{%0,%1,%2,%3},{%4,%5,%6,%7},{%8,%9},{%0,%1,%2,%3};"                 \
        : "+f"(d[0]), "+f"(d[1]), "+f"(d[2]), "+f"(d[3])                     \
        : "r"(a[0]), "r"(a[1]), "r"(a[2]), "r"(a[3]), "r"(b[0]), "r"(b[1]))

// cp.async
__device__ __forceinline__ void cpa16(u32 dst, const void* src) {
    asm volatile("cp.async.cg.shared.global [%0], [%1], 16;" :: "r"(dst), "l"(src));
}
#define CPA_COMMIT() asm volatile("cp.async.commit_group;" ::: "memory")
#define CPA_WAIT0()  asm volatile("cp.async.wait_group 0;" ::: "memory")

// ---------- async tile loaders (256 threads, BK=32) ----------
// A: hi + lo
__device__ __forceinline__ void ldA128_async(const u16* __restrict__ GH,
                                             const u16* __restrict__ GL, size_t ld,
                                             int r0, int k0, u32 SH, u32 SL, int tid) {
    int r = tid >> 1;
    int hb = (tid & 1)*32;
    const char* pH = (const char*)(GH + (size_t)(r0 + r)*ld + k0) + hb;
    const char* pL = (const char*)(GL + (size_t)(r0 + r)*ld + k0) + hb;
    u32 dH = SH + (u32)r*(TS*4) + hb;
    u32 dL = SL + (u32)r*(TS*4) + hb;
    cpa16(dH, pH); cpa16(dH + 16, pH + 16);
    cpa16(dL, pL); cpa16(dL + 16, pL + 16);
}
// B: hi only
__device__ __forceinline__ void ldB128_async(const u16* __restrict__ GH, size_t ld,
                                             int r0, int k0, u32 SH, int tid) {
    int r = tid >> 1;
    int hb = (tid & 1)*32;
    const char* pH = (const char*)(GH + (size_t)(r0 + r)*ld + k0) + hb;
    u32 dH = SH + (u32)r*(TS*4) + hb;
    cpa16(dH, pH); cpa16(dH + 16, pH + 16);
}
// two 64-row B tiles (hi only): tid<128 -> tensor1, tid>=128 -> tensor2
__device__ __forceinline__ void ldB64x2_async(const u16* __restrict__ G1H,
                                              const u16* __restrict__ G2H, size_t ld,
                                              int n0, int k0,
                                              u32 B1H, u32 B2H, int tid) {
    int t = tid & 127;
    int r = t >> 1;
    int hb = (t & 1)*32;
    const u16* sH; u32 dH;
    if (tid < 128) { sH = G1H; dH = B1H; }
    else           { sH = G2H; dH = B2H; }
    const char* pH = (const char*)(sH + (size_t)(n0 + r)*ld + k0) + hb;
    dH += (u32)r*(TS*4) + hb;
    cpa16(dH, pH); cpa16(dH + 16, pH + 16);
}

// ---------- computed A tiles (STS path, hi/lo) ----------
__device__ __forceinline__ void ld_Aexp(const float* __restrict__ G, size_t ld,
                                        int m0, int k0, u32* SH, u32* SL,
                                        int tid, float s) {
    int r = tid >> 1, c = (tid & 1)*16;
    const float* p = G + (size_t)(m0 + r)*ld + k0 + c;
    float v[16];
    #pragma unroll
    for (int q = 0; q < 4; q++) {
        float4 f = *(const float4*)(p + q*4);
        v[q*4+0]=f.x; v[q*4+1]=f.y; v[q*4+2]=f.z; v[q*4+3]=f.w;
    }
    u32 h[8], l[8];
    #pragma unroll
    for (int q = 0; q < 8; q++)
        pack_hl(__expf(s*v[2*q]), __expf(s*v[2*q+1]), h[q], l[q]);
    u32* dh = SH + r*TS + (tid & 1)*8;
    u32* dl = SL + r*TS + (tid & 1)*8;
    *(uint4*)dh = *(uint4*)h; *((uint4*)dh+1) = *(uint4*)(h+4);
    *(uint4*)dl = *(uint4*)l; *((uint4*)dl+1) = *(uint4*)(l+4);
}
__device__ __forceinline__ void ld_Aexpmask(const float* __restrict__ G,
                                            const float* __restrict__ Msk, size_t ld,
                                            int m0, int k0, u32* SH, u32* SL,
                                            int tid, float s) {
    int r = tid >> 1, c = (tid & 1)*16;
    size_t off = (size_t)(m0 + r)*ld + k0 + c;
    float v[16];
    #pragma unroll
    for (int q = 0; q < 4; q++) {
        float4 f = *(const float4*)(G + off + q*4);
        float4 m = *(const float4*)(Msk + off + q*4);
        v[q*4+0]=s*f.x+m.x; v[q*4+1]=s*f.y+m.y; v[q*4+2]=s*f.z+m.z; v[q*4+3]=s*f.w+m.w;
    }
    u32 h[8], l[8];
    #pragma unroll
    for (int q = 0; q < 8; q++)
        pack_hl(__expf(v[2*q]), __expf(v[2*q+1]), h[q], l[q]);
    u32* dh = SH + r*TS + (tid & 1)*8;
    u32* dl = SL + r*TS + (tid & 1)*8;
    *(uint4*)dh = *(uint4*)h; *((uint4*)dh+1) = *(uint4*)(h+4);
    *(uint4*)dl = *(uint4*)l; *((uint4*)dl+1) = *(uint4*)(l+4);
}

// ---------- warp mma over a 128x32 A tile, BN=128, 2-term ----------
__device__ __forceinline__ void mma128(const u32* AH, const u32* AL,
                                       const u32* BH,
                                       float d[2][8][4],
                                       int wr0, int wc0, int qr, int qc) {
    #pragma unroll
    for (int ks = 0; ks < 2; ks++) {
        int ku = ks*8;
        u32 ah[2][4], al[2][4];
        #pragma unroll
        for (int i = 0; i < 2; i++) {
            int r = wr0 + i*16 + qr;
            ah[i][0]=AH[r*TS+ku+qc];     ah[i][1]=AH[(r+8)*TS+ku+qc];
            ah[i][2]=AH[r*TS+ku+qc+4];   ah[i][3]=AH[(r+8)*TS+ku+qc+4];
            al[i][0]=AL[r*TS+ku+qc];     al[i][1]=AL[(r+8)*TS+ku+qc];
            al[i][2]=AL[r*TS+ku+qc+4];   al[i][3]=AL[(r+8)*TS+ku+qc+4];
        }
        #pragma unroll
        for (int j = 0; j < 8; j++) {
            int n = wc0 + j*8 + qr;
            u32 bh[2] = {BH[n*TS+ku+qc], BH[n*TS+ku+qc+4]};
            #pragma unroll
            for (int i = 0; i < 2; i++) {
                MMAB(d[i][j], ah[i], bh);
                MMAB(d[i][j], al[i], bh);
            }
        }
    }
}
// ---------- warp mma, BN=64 dual B (num/den), 2-term ----------
__device__ __forceinline__ void mma64x2(const u32* AH, const u32* AL,
                                        const u32* B1H, const u32* B2H,
                                        float d1[2][4][4], float d2[2][4][4],
                                        int wr0, int wc0, int qr, int qc) {
    #pragma unroll
    for (int ks = 0; ks < 2; ks++) {
        int ku = ks*8;
        u32 ah[2][4], al[2][4];
        #pragma unroll
        for (int i = 0; i < 2; i++) {
            int r = wr0 + i*16 + qr;
            ah[i][0]=AH[r*TS+ku+qc];     ah[i][1]=AH[(r+8)*TS+ku+qc];
            ah[i][2]=AH[r*TS+ku+qc+4];   ah[i][3]=AH[(r+8)*TS+ku+qc+4];
            al[i][0]=AL[r*TS+ku+qc];     al[i][1]=AL[(r+8)*TS+ku+qc];
            al[i][2]=AL[r*TS+ku+qc+4];   al[i][3]=AL[(r+8)*TS+ku+qc+4];
        }
        #pragma unroll
        for (int j = 0; j < 4; j++) {
            int n = wc0 + j*8 + qr;
            {
                u32 bh[2] = {B1H[n*TS+ku+qc], B1H[n*TS+ku+qc+4]};
                #pragma unroll
                for (int i = 0; i < 2; i++) {
                    MMAB(d1[i][j], ah[i], bh);
                    MMAB(d1[i][j], al[i], bh);
                }
            }
            {
                u32 bh[2] = {B2H[n*TS+ku+qc], B2H[n*TS+ku+qc+4]};
                #pragma unroll
                for (int i = 0; i < 2; i++) {
                    MMAB(d2[i][j], ah[i], bh);
                    MMAB(d2[i][j], al[i], bh);
                }
            }
        }
    }
}

// =====================================================================
// qkv (pass-parallel): grid.y+pbase selects pass.
// pass0 -> SQ=sigmoid(q), pass1 -> EK=exp(k), pass2 -> V raw
// stage s: AH at 3s*SZU, AL at (3s+1)*SZU, BH at (3s+2)*SZU
// =====================================================================
__global__ __launch_bounds__(256, 2) void qkv_tc(
        const u16* __restrict__ XH, const u16* __restrict__ XL,
        const u16* __restrict__ W0H,
        const u16* __restrict__ W1H_,
        const u16* __restrict__ W2H_,
        float* __restrict__ SQ, float* __restrict__ EK, float* __restrict__ V,
        int pbase) {
    extern __shared__ u32 smu[];
    const u32 sb = smem_u32(smu);
    const int tid = threadIdx.x, lane = tid & 31, w = tid >> 5;
    const int wr0 = (w >> 1)*32, wc0 = (w & 1)*64;
    const int qr = lane >> 2, qc = lane & 3;
    const int m0 = blockIdx.x*128;
    const int pass = blockIdx.y + pbase;
    const u16* BgH = (pass == 0) ? W0H : (pass == 1) ? W1H_ : W2H_;

    ldA128_async(XH, XL, EE, m0, 0, sb, sb + SZU*4, tid);
    ldB128_async(BgH, EE, 0, 0, sb + 2*SZU*4, tid);
    CPA_COMMIT();
    float d[2][8][4] = {};
    for (int t = 0; t < 4; t++) {
        CPA_WAIT0();
        __syncthreads();
        if (t + 1 < 4) {
            int s2 = (t+1) & 1, k2 = (t+1)*32;
            ldA128_async(XH, XL, EE, m0, k2,
                         sb + (3*s2)*SZU*4, sb + (3*s2+1)*SZU*4, tid);
            ldB128_async(BgH, EE, 0, k2, sb + (3*s2+2)*SZU*4, tid);
            CPA_COMMIT();
        }
        int s = t & 1;
        mma128(smu + 3*s*SZU, smu + (3*s+1)*SZU, smu + (3*s+2)*SZU,
               d, wr0, wc0, qr, qc);
    }
    #pragma unroll
    for (int i = 0; i < 2; i++)
        #pragma unroll
        for (int h = 0; h < 2; h++) {
            int row = m0 + wr0 + i*16 + qr + h*8;
            #pragma unroll
            for (int j = 0; j < 8; j++) {
                int col = wc0 + j*8 + qc*2;
                size_t o = (size_t)row*EE + col;
                float v0 = d[i][j][h*2], v1 = d[i][j][h*2+1];
                if (pass == 0) {
                    *(float2*)&SQ[o] = make_float2(
                        1.f/(1.f + __expf(-v0)), 1.f/(1.f + __expf(-v1)));
                } else if (pass == 1) {
                    *(float2*)&EK[o] = make_float2(__expf(v0), __expf(v1));
                } else {
                    *(float2*)&V[o] = make_float2(v0, v1);
                }
            }
        }
}

// =====================================================================
// encoder AFT: A=exp(s*dist) computed, dual B hi async; single-sync loop
// stage s: AH 3s*SZU, AL (3s+1)*SZU, B1H (3s+2)*SZU, B2H (3s+2)*SZU+SZH
// =====================================================================
__global__ __launch_bounds__(256, 2) void aft_enc_tc(
        const float* __restrict__ dist,
        const float* __restrict__ ls,
        const float* __restrict__ alpha, int l,
        const u16* __restrict__ EKVTH,
        const u16* __restrict__ EKTH,
        const float* __restrict__ X,
        const float* __restrict__ SQ,
        float* __restrict__ Y) {
    extern __shared__ u32 smu[];
    const u32 sb = smem_u32(smu);
    const int tid = threadIdx.x, lane = tid & 31, w = tid >> 5;
    const int wr0 = (w >> 1)*32, wc0 = (w & 1)*32;
    const int qr = lane >> 2, qc = lane & 3;
    const int b = blockIdx.z;
    const int m0 = blockIdx.x*128, n0 = blockIdx.y*64;
    const float s = ls[0]*alpha[l];
    const float* D = dist + (size_t)b*NN*NN;
    const u16* T1H = EKVTH + (size_t)b*EE*NN;
    const u16* T2H = EKTH  + (size_t)b*EE*NN;
    ld_Aexp(D, NN, m0, 0, smu, smu + SZU, tid, s);
    ldB64x2_async(T1H, T2H, NN, n0, 0,
                  sb + 2*SZU*4, sb + (2*SZU+SZH)*4, tid);
    CPA_COMMIT();
    float d1[2][4][4] = {}, d2[2][4][4] = {};
    for (int t = 0; t < 16; t++) {
        CPA_WAIT0();
        __syncthreads();
        if (t + 1 < 16) {
            int s2 = (t+1) & 1, k2 = (t+1)*32;
            u32 bbase = sb + (3*s2+2)*SZU*4;
            ldB64x2_async(T1H, T2H, NN, n0, k2, bbase, bbase + SZH*4, tid);
            CPA_COMMIT();
        }
        int s1 = t & 1;
        u32 bo = (3*s1+2)*SZU;
        mma64x2(smu + 3*s1*SZU, smu + (3*s1+1)*SZU,
                smu + bo, smu + bo + SZH,
                d1, d2, wr0, wc0, qr, qc);
        if (t + 1 < 16) {
            int s2 = (t+1) & 1;
            ld_Aexp(D, NN, m0, (t+1)*32, smu + 3*s2*SZU, smu + (3*s2+1)*SZU, tid, s);
        }
    }
    #pragma unroll
    for (int i = 0; i < 2; i++)
        #pragma unroll
        for (int h = 0; h < 2; h++) {
            int row = m0 + wr0 + i*16 + qr + h*8;
            #pragma unroll
            for (int j = 0; j < 4; j++) {
                int col = n0 + wc0 + j*8 + qc*2;
                size_t o = ((size_t)b*NN + row)*EE + col;
                float2 xv = *(const float2*)&X[o];
                float2 sv = *(const float2*)&SQ[o];
                float n0v = d1[i][j][h*2], n1v = d1[i][j][h*2+1];
                float de0 = d2[i][j][h*2], de1 = d2[i][j][h*2+1];
                *(float2*)&Y[o] = make_float2(
                    xv.x + sv.x*(n0v/de0), xv.y + sv.y*(n1v/de1));
            }
        }
}

// =====================================================================
// decoder AFT
// =====================================================================
__global__ __launch_bounds__(256, 2) void dec_aft_tc(
        const float* __restrict__ cur_dist,
        const float* __restrict__ ninf,
        const float* __restrict__ ls,
        const float* __restrict__ dalpha,
        const u16* __restrict__ EKVTH,
        const u16* __restrict__ EKTH,
        const float* __restrict__ GQ,
        const float* __restrict__ cap,
        const float* __restrict__ dWq,
        u16* __restrict__ AFTH, u16* __restrict__ AFTL) {
    extern __shared__ u32 smu[];
    const u32 sb = smem_u32(smu);
    const int tid = threadIdx.x, lane = tid & 31, w = tid >> 5;
    const int wr0 = (w >> 1)*32, wc0 = (w & 1)*32;
    const int qr = lane >> 2, qc = lane & 3;
    const int b = blockIdx.z;
    const int m0 = blockIdx.x*128, n0 = blockIdx.y*64;
    const float s = ls[0]*dalpha[0];
    const float* CD = cur_dist + (size_t)b*PP*NN;
    const float* NM = ninf     + (size_t)b*PP*NN;
    const u16* T1H = EKVTH + (size_t)b*EE*NN;
    const u16* T2H = EKTH  + (size_t)b*EE*NN;
    ld_Aexpmask(CD, NM, NN, m0, 0, smu, smu + SZU, tid, s);
    ldB64x2_async(T1H, T2H, NN, n0, 0,
                  sb + 2*SZU*4, sb + (2*SZU+SZH)*4, tid);
    CPA_COMMIT();
    float d1[2][4][4] = {}, d2[2][4][4] = {};
    for (int t = 0; t < 16; t++) {
        CPA_WAIT0();
        __syncthreads();
        if (t + 1 < 16) {
            int s2 = (t+1) & 1, k2 = (t+1)*32;
            u32 bbase = sb + (3*s2+2)*SZU*4;
            ldB64x2_async(T1H, T2H, NN, n0, k2, bbase, bbase + SZH*4, tid);
            CPA_COMMIT();
        }
        int s1 = t & 1;
        u32 bo = (3*s1+2)*SZU;
        mma64x2(smu + 3*s1*SZU, smu + (3*s1+1)*SZU,
                smu + bo, smu + bo + SZH,
                d1, d2, wr0, wc0, qr, qc);
        if (t + 1 < 16) {
            int s2 = (t+1) & 1;
            ld_Aexpmask(CD, NM, NN, m0, (t+1)*32,
                        smu + 3*s2*SZU, smu + (3*s2+1)*SZU, tid, s);
        }
    }
    #pragma unroll
    for (int i = 0; i < 2; i++)
        #pragma unroll
        for (int h = 0; h < 2; h++) {
            int p = m0 + wr0 + i*16 + qr + h*8;
            float cv = cap[(size_t)b*PP + p];
            #pragma unroll
            for (int j = 0; j < 4; j++) {
                int col = n0 + wc0 + j*8 + qc*2;
                float2 gq2 = *(const float2*)&GQ[b*EE + col];
                float2 wq2 = *(const float2*)&dWq[EE*EE + col];
                float q0 = gq2.x + cv*wq2.x;
                float q1 = gq2.y + cv*wq2.y;
                float sg0 = 1.f/(1.f + __expf(-q0));
                float sg1 = 1.f/(1.f + __expf(-q1));
                float v0 = sg0*(d1[i][j][h*2]  /d2[i][j][h*2]);
                float v1 = sg1*(d1[i][j][h*2+1]/d2[i][j][h*2+1]);
                u32 hh, ll; pack_hl(v0, v1, hh, ll);
                size_t o = ((size_t)b*PP + p)*EE + col;
                *(u32*)&AFTH[o] = hh;
                *(u32*)&AFTL[o] = ll;
            }
        }
}

// =====================================================================
// FF1: hid = relu(h@W1 + b1) -> fp16 hi/lo
// =====================================================================
__global__ __launch_bounds__(256, 2) void ff1_tc(
        const u16* __restrict__ HH, const u16* __restrict__ HL,
        const u16* __restrict__ W1H,
        const float* __restrict__ b1,
        u16* __restrict__ HIDH, u16* __restrict__ HIDL) {
    extern __shared__ u32 smu[];
    const u32 sb = smem_u32(smu);
    const int tid = threadIdx.x, lane = tid & 31, w = tid >> 5;
    const int wr0 = (w >> 1)*32, wc0 = (w & 1)*64;
    const int qr = lane >> 2, qc = lane & 3;
    const int m0 = blockIdx.x*128, n0 = blockIdx.y*128;
    ldA128_async(HH, HL, EE, m0, 0, sb, sb + SZU*4, tid);
    ldB128_async(W1H, EE, n0, 0, sb + 2*SZU*4, tid);
    CPA_COMMIT();
    float d[2][8][4] = {};
    for (int t = 0; t < 4; t++) {
        CPA_WAIT0();
        __syncthreads();
        if (t + 1 < 4) {
            int s2 = (t+1) & 1, k2 = (t+1)*32;
            ldA128_async(HH, HL, EE, m0, k2,
                         sb + (3*s2)*SZU*4, sb + (3*s2+1)*SZU*4, tid);
            ldB128_async(W1H, EE, n0, k2, sb + (3*s2+2)*SZU*4, tid);
            CPA_COMMIT();
        }
        int s = t & 1;
        mma128(smu + 3*s*SZU, smu + (3*s+1)*SZU, smu + (3*s+2)*SZU,
               d, wr0, wc0, qr, qc);
    }
    #pragma unroll
    for (int i = 0; i < 2; i++)
        #pragma unroll
        for (int h = 0; h < 2; h++) {
            int row = m0 + wr0 + i*16 + qr + h*8;
            #pragma unroll
            for (int j = 0; j < 8; j++) {
                int col = n0 + wc0 + j*8 + qc*2;
                float2 bb = *(const float2*)&b1[col];
                float v0 = fmaxf(d[i][j][h*2]   + bb.x, 0.f);
                float v1 = fmaxf(d[i][j][h*2+1] + bb.y, 0.f);
                u32 hh, ll; pack_hl(v0, v1, hh, ll);
                size_t o = (size_t)row*FFD + col;
                *(u32*)&HIDH[o] = hh;
                *(u32*)&HIDL[o] = ll;
            }
        }
}

// =====================================================================
// FF2: y = h + hid@W2 + b2  (K=512, 16 chunks)
// =====================================================================
__global__ __launch_bounds__(256, 2) void ff2_tc(
        const u16* __restrict__ HIDH, const u16* __restrict__ HIDL,
        const u16* __restrict__ W2H,
        const float* __restrict__ b2,
        const float* __restrict__ H,
        float* __restrict__ Y) {
    extern __shared__ u32 smu[];
    const u32 sb = smem_u32(smu);
    const int tid = threadIdx.x, lane = tid & 31, w = tid >> 5;
    const int wr0 = (w >> 1)*32, wc0 = (w & 1)*64;
    const int qr = lane >> 2, qc = lane & 3;
    const int m0 = blockIdx.x*128;
    ldA128_async(HIDH, HIDL, FFD, m0, 0, sb, sb + SZU*4, tid);
    ldB128_async(W2H, FFD, 0, 0, sb + 2*SZU*4, tid);
    CPA_COMMIT();
    float d[2][8][4] = {};
    for (int t = 0; t < 16; t++) {
        CPA_WAIT0();
        __syncthreads();
        if (t + 1 < 16) {
            int s2 = (t+1) & 1, k2 = (t+1)*32;
            ldA128_async(HIDH, HIDL, FFD, m0, k2,
                         sb + (3*s2)*SZU*4, sb + (3*s2+1)*SZU*4, tid);
            ldB128_async(W2H, FFD, 0, k2, sb + (3*s2+2)*SZU*4, tid);
            CPA_COMMIT();
        }
        int s = t & 1;
        mma128(smu + 3*s*SZU, smu + (3*s+1)*SZU, smu + (3*s+2)*SZU,
               d, wr0, wc0, qr, qc);
    }
    #pragma unroll
    for (int i = 0; i < 2; i++)
        #pragma unroll
        for (int h = 0; h < 2; h++) {
            int row = m0 + wr0 + i*16 + qr + h*8;
            #pragma unroll
            for (int j = 0; j < 8; j++) {
                int col = wc0 + j*8 + qc*2;
                float2 bb = *(const float2*)&b2[col];
                size_t o = (size_t)row*EE + col;
                float2 hv = *(const float2*)&H[o];
                *(float2*)&Y[o] = make_float2(
                    hv.x + d[i][j][h*2]   + bb.x,
                    hv.y + d[i][j][h*2+1] + bb.y);
            }
        }
}

// =====================================================================
// score: S = aft @ enc^T + epilogue (K=128)
// =====================================================================
__global__ __launch_bounds__(256, 2) void score_tc(
        const u16* __restrict__ AFTH, const u16* __restrict__ AFTL,
        const u16* __restrict__ XH,
        const float* __restrict__ cur_dist,
        const float* __restrict__ ninf,
        const float* __restrict__ ls,
        const float* __restrict__ palpha,
        float* __restrict__ OUT) {
    extern __shared__ u32 smu[];
    const u32 sb = smem_u32(smu);
    const int tid = threadIdx.x, lane = tid & 31, w = tid >> 5;
    const int wr0 = (w >> 1)*32, wc0 = (w & 1)*64;
    const int qr = lane >> 2, qc = lane & 3;
    const int b = blockIdx.z;
    const int p0 = blockIdx.x*128, n0 = blockIdx.y*128;
    const float ps = ls[0]*palpha[0];
    const u16* AgH = AFTH + (size_t)b*PP*EE;
    const u16* AgL = AFTL + (size_t)b*PP*EE;
    const u16* BgH = XH + (size_t)b*NN*EE;
    ldA128_async(AgH, AgL, EE, p0, 0, sb, sb + SZU*4, tid);
    ldB128_async(BgH, EE, n0, 0, sb + 2*SZU*4, tid);
    CPA_COMMIT();
    float d[2][8][4] = {};
    for (int t = 0; t < 4; t++) {
        CPA_WAIT0();
        __syncthreads();
        if (t + 1 < 4) {
            int s2 = (t+1) & 1, k2 = (t+1)*32;
            ldA128_async(AgH, AgL, EE, p0, k2,
                         sb + (3*s2)*SZU*4, sb + (3*s2+1)*SZU*4, tid);
            ldB128_async(BgH, EE, n0, k2, sb + (3*s2+2)*SZU*4, tid);
            CPA_COMMIT();
        }
        int s = t & 1;
        mma128(smu + 3*s*SZU, smu + (3*s+1)*SZU, smu + (3*s+2)*SZU,
               d, wr0, wc0, qr, qc);
    }
    #pragma unroll
    for (int i = 0; i < 2; i++)
        #pragma unroll
        for (int h = 0; h < 2; h++) {
            int p = p0 + wr0 + i*16 + qr + h*8;
            #pragma unroll
            for (int j = 0; j < 8; j++) {
                int n = n0 + wc0 + j*8 + qc*2;
                size_t o = ((size_t)b*PP + p)*NN + n;
                float2 cd = *(const float2*)&cur_dist[o];
                float2 nm = *(const float2*)&ninf[o];
                float s0 = d[i][j][h*2]  *INV_SQRT_E + ps*cd.x;
                float s1 = d[i][j][h*2+1]*INV_SQRT_E + ps*cd.y;
                *(float2*)&OUT[o] = make_float2(
                    10.f*tanhf(s0) + nm.x, 10.f*tanhf(s1) + nm.y);
            }
        }
}

// =====================================================================
// weight transpose-convert (batched; hi only)
// =====================================================================
__device__ __forceinline__ void wconv_body(const float* __restrict__ src,
                                           u16* __restrict__ dH,
                                           int K, int N) {
    __shared__ float t[32][33];
    int n0 = blockIdx.x*32, k0 = blockIdx.y*32;
    int tr = threadIdx.x >> 3, tc4 = (threadIdx.x & 7)*4;
    float4 v = *(const float4*)&src[(size_t)(k0+tr)*N + n0 + tc4];
    t[tc4+0][tr] = v.x; t[tc4+1][tr] = v.y;
    t[tc4+2][tr] = v.z; t[tc4+3][tr] = v.w;
    __syncthreads();
    int r = threadIdx.x >> 3, c4 = (threadIdx.x & 7)*4;
    u16 h[4];
    #pragma unroll
    for (int i = 0; i < 4; i++) h[i] = cvt_h(t[r][c4+i]);
    size_t o = (size_t)(n0+r)*K + k0 + c4;
    *(uint2*)&dH[o] = *(uint2*)h;
}
__global__ void wconv_sq(const float* __restrict__ Wq, const float* __restrict__ Wk,
                         const float* __restrict__ Wv,
                         const float* __restrict__ dWk, const float* __restrict__ dWv,
                         u16* qH, u16* kH, u16* vH, u16* dkH, u16* dvH) {
    int z = blockIdx.z;
    const float* src; u16 *dH;
    size_t off = (size_t)(z % 6)*EE*EE;
    if (z < 6)       { src = Wq + off; dH = qH + off; }
    else if (z < 12) { src = Wk + off; dH = kH + off; }
    else if (z < 18) { src = Wv + off; dH = vH + off; }
    else if (z == 18){ src = dWk; dH = dkH; }
    else             { src = dWv; dH = dvH; }
    wconv_body(src, dH, EE, EE);
}
__global__ void wconv_w1(const float* __restrict__ W1, u16* dH) {
    int l = blockIdx.z;
    wconv_body(W1 + (size_t)l*EE*FFD, dH + (size_t)l*FFD*EE, EE, FFD);
}
__global__ void wconv_w2(const float* __restrict__ W2, u16* dH) {
    int l = blockIdx.z;
    wconv_body(W2 + (size_t)l*FFD*EE, dH + (size_t)l*EE*FFD, FFD, EE);
}

// =====================================================================
// ek/v transpose-convert: ekT = fp16(ek), ekvT = fp16(ek * v_raw), hi only
// =====================================================================
__global__ void ekconv_kernel(const float* __restrict__ ek,
                              const float* __restrict__ vraw,
                              u16* __restrict__ ekTH,
                              u16* __restrict__ ekvTH) {
    __shared__ float t1[32][33], t2[32][33];
    int b = blockIdx.z;
    int e0 = blockIdx.x*32, nd0 = blockIdx.y*32;
    const float* S1 = ek   + (size_t)b*NN*EE;
    const float* S2 = vraw + (size_t)b*NN*EE;
    int tr = threadIdx.x >> 3, tc4 = (threadIdx.x & 7)*4;
    size_t so = (size_t)(nd0+tr)*EE + e0 + tc4;
    float4 v1 = *(const float4*)&S1[so];
    float4 v2 = *(const float4*)&S2[so];
    t1[tc4+0][tr]=v1.x; t1[tc4+1][tr]=v1.y; t1[tc4+2][tr]=v1.z; t1[tc4+3][tr]=v1.w;
    t2[tc4+0][tr]=v2.x; t2[tc4+1][tr]=v2.y; t2[tc4+2][tr]=v2.z; t2[tc4+3][tr]=v2.w;
    __syncthreads();
    int r = threadIdx.x >> 3, c4 = (threadIdx.x & 7)*4;
    size_t o = (size_t)b*EE*NN + (size_t)(e0+r)*NN + nd0 + c4;
    u16 h[4];
    #pragma unroll
    for (int i = 0; i < 4; i++) h[i] = cvt_h(t1[r][c4+i]);
    *(uint2*)&ekTH[o] = *(uint2*)h;
    #pragma unroll
    for (int i = 0; i < 4; i++) h[i] = cvt_h(t1[r][c4+i]*t2[r][c4+i]);
    *(uint2*)&ekvTH[o] = *(uint2*)h;
}

// ---------------- embedding (also writes fp16 hi/lo) ----------------
__global__ void embed_kernel(const float* __restrict__ data,
                             const float* __restrict__ W,
                             const float* __restrict__ bias,
                             float* __restrict__ X,
                             u16* __restrict__ XH, u16* __restrict__ XL) {
    int idx = blockIdx.x;
    int e   = threadIdx.x;
    float d0 = data[idx*2+0], d1 = data[idx*2+1];
    float v = d0*W[e] + d1*W[EE+e] + bias[e];
    size_t o = (size_t)idx*EE + e;
    X[o] = v;
    u16 h, l; cvt_hl(v, h, l);
    XH[o] = h; XL[o] = l;
}

// ---------------- instance norm (also emits fp16 hi/lo) ----------------
__global__ void inorm_kernel(const float* __restrict__ src,
                             float* __restrict__ dst,
                             u16* __restrict__ dstH, u16* __restrict__ dstL,
                             const float* __restrict__ w,
                             const float* __restrict__ bias) {
    int b = blockIdx.x;
    int e = threadIdx.x;
    int c = threadIdx.y;
    const float* S = src + (size_t)b*NN*EE;
    float s = 0.f, s2 = 0.f;
    for (int n = c*64; n < c*64 + 64; n++) {
        float v = S[(size_t)n*EE + e];
        s += v; s2 += v*v;
    }
    __shared__ float ssum[8][128], ssq[8][128];
    __shared__ float smu2[128], srs[128];
    ssum[c][e] = s; ssq[c][e] = s2;
    __syncthreads();
    if (c == 0) {
        float ts = 0.f, t2 = 0.f;
        #pragma unroll
        for (int i = 0; i < 8; i++) { ts += ssum[i][e]; t2 += ssq[i][e]; }
        float mu = ts*(1.f/NN);
        float var = t2*(1.f/NN) - mu*mu;
        smu2[e] = mu;
        srs[e] = rsqrtf(var + EPS);
    }
    __syncthreads();
    float mu = smu2[e], rs = srs[e], ww = w[e], bb = bias[e];
    size_t base = (size_t)b*NN*EE;
    for (int n = c*64; n < c*64 + 64; n++) {
        size_t o = base + (size_t)n*EE + e;
        float v = (S[(size_t)n*EE + e] - mu)*rs*ww + bb;
        dst[o] = v;
        u16 h, l; cvt_hl(v, h, l);
        dstH[o] = h; dstL[o] = l;
    }
}

// ---------------- graph mean over nodes ----------------
__global__ void gmean_kernel(const float* __restrict__ X, float* __restrict__ GM) {
    int b = blockIdx.x, e = threadIdx.x, c = threadIdx.y;
    float s = 0.f;
    for (int n = c*64; n < c*64 + 64; n++)
        s += X[((size_t)b*NN + n)*EE + e];
    __shared__ float sm[8][128];
    sm[c][e] = s;
    __syncthreads();
    if (c == 0) {
        float t = 0.f;
        #pragma unroll
        for (int i = 0; i < 8; i++) t += sm[i][e];
        GM[b*EE + e] = t*(1.f/NN);
    }
}

// ---------------- gq = gmean @ dWq[0:E,:] ----------------
__global__ void gq_kernel(const float* __restrict__ GM,
                          const float* __restrict__ dWq,
                          float* __restrict__ GQ) {
    int b = blockIdx.x, e = threadIdx.x;
    float acc = 0.f;
    for (int i = 0; i < EE; i++)
        acc += GM[b*EE + i]*dWq[i*EE + e];
    GQ[b*EE + e] = acc;
}

// ---------------- row softmax over last dim (512) ----------------
__global__ void softmax_kernel(float* __restrict__ OUT) {
    float* row = OUT + (size_t)blockIdx.x*NN;
    int t = threadIdx.x;
    float v[4];
    #pragma unroll
    for (int i = 0; i < 4; i++) v[i] = row[t + i*128];
    float m = fmaxf(fmaxf(v[0], v[1]), fmaxf(v[2], v[3]));
    __shared__ float red[4];
    #pragma unroll
    for (int off = 16; off > 0; off >>= 1)
        m = fmaxf(m, __shfl_xor_sync(0xffffffff, m, off));
    if ((t & 31) == 0) red[t >> 5] = m;
    __syncthreads();
    m = fmaxf(fmaxf(red[0], red[1]), fmaxf(red[2], red[3]));
    __syncthreads();
    float s = 0.f;
    #pragma unroll
    for (int i = 0; i < 4; i++) { v[i] = __expf(v[i] - m); s += v[i]; }
    #pragma unroll
    for (int off = 16; off > 0; off >>= 1)
        s += __shfl_xor_sync(0xffffffff, s, off);
    if ((t & 31) == 0) red[t >> 5] = s;
    __syncthreads();
    s = red[0] + red[1] + red[2] + red[3];
    float inv = 1.f/s;
    #pragma unroll
    for (int i = 0; i < 4; i++) row[t + i*128] = v[i]*inv;
}

// ---------------- launch ----------------
extern "C" void kernel_launch(void* const* d_in, const int* in_sizes, int n_in,
                              void* d_out, int out_size) {
    const float* data      = (const float*)d_in[0];
    const float* dist      = (const float*)d_in[1];
    const float* cur_dist  = (const float*)d_in[2];
    const float* capacity  = (const float*)d_in[3];
    const float* ninf_mask = (const float*)d_in[4];
    const float* log_scale = (const float*)d_in[5];
    const float* emb_W     = (const float*)d_in[6];
    const float* emb_b     = (const float*)d_in[7];
    const float* Wq        = (const float*)d_in[8];
    const float* Wk        = (const float*)d_in[9];
    const float* Wv        = (const float*)d_in[10];
    const float* aft_alpha = (const float*)d_in[11];
    const float* n1_w      = (const float*)d_in[12];
    const float* n1_b      = (const float*)d_in[13];
    const float* ff_W1     = (const float*)d_in[14];
    const float* ff_b1     = (const float*)d_in[15];
    const float* ff_W2     = (const float*)d_in[16];
    const float* ff_b2     = (const float*)d_in[17];
    const float* n2_w      = (const float*)d_in[18];
    const float* n2_b      = (const float*)d_in[19];
    const float* dWq       = (const float*)d_in[20];
    const float* dWk       = (const float*)d_in[21];
    const float* dWv       = (const float*)d_in[22];
    const float* dec_alpha = (const float*)d_in[23];
    const float* p_alpha   = (const float*)d_in[24];
    float* out = (float*)d_out;

    float *x, *y, *h, *sq, *ek, *ekv, *gq, *gm;
    cudaGetSymbolAddress((void**)&x,   g_x);
    cudaGetSymbolAddress((void**)&y,   g_y);
    cudaGetSymbolAddress((void**)&h,   g_h);
    cudaGetSymbolAddress((void**)&sq,  g_sq);
    cudaGetSymbolAddress((void**)&ek,  g_ek);
    cudaGetSymbolAddress((void**)&ekv, g_ekv);
    cudaGetSymbolAddress((void**)&gq,  g_gq);
    cudaGetSymbolAddress((void**)&gm,  g_gm);

    u16 *xH,*xL,*hH,*hL,*hidH,*hidL,*aftH,*aftL;
    u16 *ekTH,*ekvTH;
    u16 *wqTH,*wkTH,*wvTH,*w1TH,*w2TH,*dkTH,*dvTH;
    cudaGetSymbolAddress((void**)&xH,   g_xH);   cudaGetSymbolAddress((void**)&xL,   g_xL);
    cudaGetSymbolAddress((void**)&hH,   g_hH);   cudaGetSymbolAddress((void**)&hL,   g_hL);
    cudaGetSymbolAddress((void**)&hidH, g_hidH); cudaGetSymbolAddress((void**)&hidL, g_hidL);
    cudaGetSymbolAddress((void**)&aftH, g_aftH); cudaGetSymbolAddress((void**)&aftL, g_aftL);
    cudaGetSymbolAddress((void**)&ekTH, g_ekTH);
    cudaGetSymbolAddress((void**)&ekvTH,g_ekvTH);
    cudaGetSymbolAddress((void**)&wqTH, g_wqTH);
    cudaGetSymbolAddress((void**)&wkTH, g_wkTH);
    cudaGetSymbolAddress((void**)&wvTH, g_wvTH);
    cudaGetSymbolAddress((void**)&w1TH, g_w1TH);
    cudaGetSymbolAddress((void**)&w2TH, g_w2TH);
    cudaGetSymbolAddress((void**)&dkTH, g_dkTH);
    cudaGetSymbolAddress((void**)&dvTH, g_dvTH);

    cudaFuncSetAttribute(qkv_tc,     cudaFuncAttributeMaxDynamicSharedMemorySize, SMEM_SZ);
    cudaFuncSetAttribute(aft_enc_tc, cudaFuncAttributeMaxDynamicSharedMemorySize, SMEM_SZ);
    cudaFuncSetAttribute(dec_aft_tc, cudaFuncAttributeMaxDynamicSharedMemorySize, SMEM_SZ);
    cudaFuncSetAttribute(ff1_tc,     cudaFuncAttributeMaxDynamicSharedMemorySize, SMEM_SZ);
    cudaFuncSetAttribute(ff2_tc,     cudaFuncAttributeMaxDynamicSharedMemorySize, SMEM_SZ);
    cudaFuncSetAttribute(score_tc,   cudaFuncAttributeMaxDynamicSharedMemorySize, SMEM_SZ);

    // ---- batched weight transpose+convert (3 launches) ----
    wconv_sq<<<dim3(EE/32, EE/32, 20), 256>>>(Wq, Wk, Wv, dWk, dWv,
        wqTH, wkTH, wvTH, dkTH, dvTH);
    wconv_w1<<<dim3(FFD/32, EE/32, LLAYERS), 256>>>(ff_W1, w1TH);
    wconv_w2<<<dim3(EE/32, FFD/32, LLAYERS), 256>>>(ff_W2, w2TH);

    embed_kernel<<<M_TOT, EE>>>(data, emb_W, emb_b, x, xH, xL);

    for (int l = 0; l < LLAYERS; l++) {
        // 3 independent passes: q->SQ, k->EK, v->Vraw(in ekv buffer)
        qkv_tc<<<dim3(M_TOT/128, 3), 256, SMEM_SZ>>>(
            xH, xL,
            wqTH + (size_t)l*EE*EE,
            wkTH + (size_t)l*EE*EE,
            wvTH + (size_t)l*EE*EE,
            sq, ek, ekv, 0);
        ekconv_kernel<<<dim3(EE/32, NN/32, BB), 256>>>(ek, ekv, ekTH, ekvTH);
        aft_enc_tc<<<dim3(NN/128, EE/64, BB), 256, SMEM_SZ>>>(
            dist, log_scale, aft_alpha, l, ekvTH, ekTH, x, sq, y);
        inorm_kernel<<<BB, dim3(128, 8)>>>(y, h, hH, hL, n1_w + l*EE, n1_b + l*EE);
        ff1_tc<<<dim3(M_TOT/128, FFD/128), 256, SMEM_SZ>>>(
            hH, hL, w1TH + (size_t)l*FFD*EE, ff_b1 + l*FFD, hidH, hidL);
        ff2_tc<<<M_TOT/128, 256, SMEM_SZ>>>(
            hidH, hidL, w2TH + (size_t)l*EE*FFD, ff_b2 + l*EE, h, y);
        inorm_kernel<<<BB, dim3(128, 8)>>>(y, x, xH, xL, n2_w + l*EE, n2_b + l*EE);
    }

    // decoder: passes 1,2 of qkv_tc (k->EK, v->Vraw)
    qkv_tc<<<dim3(M_TOT/128, 2), 256, SMEM_SZ>>>(
        xH, xL,
        dkTH,            /* unused slot (pass 0 never taken) */
        dkTH,            /* pass 1: dWk */
        dvTH,            /* pass 2: dWv */
        sq, ek, ekv, 1);
    ekconv_kernel<<<dim3(EE/32, NN/32, BB), 256>>>(ek, ekv, ekTH, ekvTH);
    gmean_kernel<<<BB, dim3(128, 8)>>>(x, gm);
    gq_kernel<<<BB, 128>>>(gm, dWq, gq);
    dec_aft_tc<<<dim3(PP/128, EE/64, BB), 256, SMEM_SZ>>>(
        cur_dist, ninf_mask, log_scale, dec_alpha,
        ekvTH, ekTH, gq, capacity, dWq, aftH, aftL);
    score_tc<<<dim3(PP/128, NN/128, BB), 256, SMEM_SZ>>>(
        aftH, aftL, xH, cur_dist, ninf_mask, log_scale, p_alpha, out);
    softmax_kernel<<<BB*PP, 128>>>(out);
}

// round 17
// speedup vs baseline: 2.5723x; 1.0289x over previous
#include <cuda_runtime.h>
#include <cuda_fp16.h>
#include <math.h>

#define BB 64
#define PP 512
#define NN 512
#define EE 128
#define FFD 512
#define LLAYERS 6
#define M_TOT (BB*NN)
#define EPS 1e-5f
#define INV_SQRT_E 0.08838834764831845f

typedef unsigned short u16;
typedef unsigned int   u32;
typedef unsigned long long u64;

#define TS 20                 /* smem row stride in u32 (80B), conflict-free */
#define SZU (128*TS)          /* u32 per 128-row buffer */
#define SZH (64*TS)           /* u32 per 64-row buffer  */
#define SMEM_SZ (6*SZU*4)     /* 61440 B: 2 stages x (A hi + A lo + B hi)   */

// ---------------- f32 scratch ----------------
__device__ float g_x  [BB*NN*EE];
__device__ float g_y  [BB*NN*EE];
__device__ float g_h  [BB*NN*EE];
__device__ float g_sq [BB*NN*EE];
__device__ float g_ek [BB*NN*EE];
__device__ float g_ekv[BB*NN*EE];
__device__ float g_gq [BB*EE];
// ---------------- fp16 hi/lo scratch ----------------
__device__ u16 g_xH  [M_TOT*EE],  g_xL  [M_TOT*EE];
__device__ u16 g_hH  [M_TOT*EE],  g_hL  [M_TOT*EE];
__device__ u16 g_hidH[M_TOT*FFD], g_hidL[M_TOT*FFD];
__device__ u16 g_aftH[BB*PP*EE],  g_aftL[BB*PP*EE];
__device__ u16 g_ekTH [BB*EE*NN];
__device__ u16 g_ekvTH[BB*EE*NN];
// weights (transposed [n][k]) — B role only: hi only
__device__ u16 g_wqTH[LLAYERS*EE*EE];
__device__ u16 g_wkTH[LLAYERS*EE*EE];
__device__ u16 g_wvTH[LLAYERS*EE*EE];
__device__ u16 g_w1TH[LLAYERS*FFD*EE];
__device__ u16 g_w2TH[LLAYERS*EE*FFD];
__device__ u16 g_dkTH[EE*EE];
__device__ u16 g_dvTH[EE*EE];

// ================= helpers =================
__device__ __forceinline__ void cvt_hl(float x, u16& h, u16& l) {
    __half hh = __float2half_rn(x);
    float hf = __half2float(hh);
    __half ll = __float2half_rn(x - hf);
    h = __half_as_ushort(hh);
    l = __half_as_ushort(ll);
}
__device__ __forceinline__ u16 cvt_h(float x) {
    return __half_as_ushort(__float2half_rn(x));
}
__device__ __forceinline__ void pack_hl(float x, float y, u32& h, u32& l) {
    u16 hx, lx, hy, ly;
    cvt_hl(x, hx, lx); cvt_hl(y, hy, ly);
    h = (u32)hx | ((u32)hy << 16);
    l = (u32)lx | ((u32)ly << 16);
}
__device__ __forceinline__ u32 smem_u32(const void* p) {
    u32 a; asm("{ .reg .u64 t; cvta.to.shared.u64 t, %1; cvt.u32.u64 %0, t; }"
               : "=r"(a) : "l"(p));
    return a;
}

#define MMAB(d, a, b)                                                        \
    asm volatile("mma.sync.aligned.m16n8k16.row.col.f32.f16.f16.f32 "        \
        "{%0,%1,%2,%3},{%4,%5,%6,%7},{%8,%9},{%0,%1,%2,%3};"                 \
        : "+f"(d[0]), "+f"(d[1]), "+f"(d[2]), "+f"(d[3])                     \
        : "r"(a[0]), "r"(a[1]), "r"(a[2]), "r"(a[3]), "r"(b[0]), "r"(b[1]))

// cp.async
__device__ __forceinline__ void cpa16(u32 dst, const void* src) {
    asm volatile("cp.async.cg.shared.global [%0], [%1], 16;" :: "r"(dst), "l"(src));
}
#define CPA_COMMIT() asm volatile("cp.async.commit_group;" ::: "memory")
#define CPA_WAIT0()  asm volatile("cp.async.wait_group 0;" ::: "memory")

// ---------- async tile loaders (256 threads, BK=32) ----------
// A: hi + lo
__device__ __forceinline__ void ldA128_async(const u16* __restrict__ GH,
                                             const u16* __restrict__ GL, size_t ld,
                                             int r0, int k0, u32 SH, u32 SL, int tid) {
    int r = tid >> 1;
    int hb = (tid & 1)*32;
    const char* pH = (const char*)(GH + (size_t)(r0 + r)*ld + k0) + hb;
    const char* pL = (const char*)(GL + (size_t)(r0 + r)*ld + k0) + hb;
    u32 dH = SH + (u32)r*(TS*4) + hb;
    u32 dL = SL + (u32)r*(TS*4) + hb;
    cpa16(dH, pH); cpa16(dH + 16, pH + 16);
    cpa16(dL, pL); cpa16(dL + 16, pL + 16);
}
// B: hi only
__device__ __forceinline__ void ldB128_async(const u16* __restrict__ GH, size_t ld,
                                             int r0, int k0, u32 SH, int tid) {
    int r = tid >> 1;
    int hb = (tid & 1)*32;
    const char* pH = (const char*)(GH + (size_t)(r0 + r)*ld + k0) + hb;
    u32 dH = SH + (u32)r*(TS*4) + hb;
    cpa16(dH, pH); cpa16(dH + 16, pH + 16);
}
// two 64-row B tiles (hi only): tid<128 -> tensor1, tid>=128 -> tensor2
__device__ __forceinline__ void ldB64x2_async(const u16* __restrict__ G1H,
                                              const u16* __restrict__ G2H, size_t ld,
                                              int n0, int k0,
                                              u32 B1H, u32 B2H, int tid) {
    int t = tid & 127;
    int r = t >> 1;
    int hb = (t & 1)*32;
    const u16* sH; u32 dH;
    if (tid < 128) { sH = G1H; dH = B1H; }
    else           { sH = G2H; dH = B2H; }
    const char* pH = (const char*)(sH + (size_t)(n0 + r)*ld + k0) + hb;
    dH += (u32)r*(TS*4) + hb;
    cpa16(dH, pH); cpa16(dH + 16, pH + 16);
}

// ---------- computed A tiles (STS path, hi/lo) ----------
__device__ __forceinline__ void ld_Aexp(const float* __restrict__ G, size_t ld,
                                        int m0, int k0, u32* SH, u32* SL,
                                        int tid, float s) {
    int r = tid >> 1, c = (tid & 1)*16;
    const float* p = G + (size_t)(m0 + r)*ld + k0 + c;
    float v[16];
    #pragma unroll
    for (int q = 0; q < 4; q++) {
        float4 f = *(const float4*)(p + q*4);
        v[q*4+0]=f.x; v[q*4+1]=f.y; v[q*4+2]=f.z; v[q*4+3]=f.w;
    }
    u32 h[8], l[8];
    #pragma unroll
    for (int q = 0; q < 8; q++)
        pack_hl(__expf(s*v[2*q]), __expf(s*v[2*q+1]), h[q], l[q]);
    u32* dh = SH + r*TS + (tid & 1)*8;
    u32* dl = SL + r*TS + (tid & 1)*8;
    *(uint4*)dh = *(uint4*)h; *((uint4*)dh+1) = *(uint4*)(h+4);
    *(uint4*)dl = *(uint4*)l; *((uint4*)dl+1) = *(uint4*)(l+4);
}
__device__ __forceinline__ void ld_Aexpmask(const float* __restrict__ G,
                                            const float* __restrict__ Msk, size_t ld,
                                            int m0, int k0, u32* SH, u32* SL,
                                            int tid, float s) {
    int r = tid >> 1, c = (tid & 1)*16;
    size_t off = (size_t)(m0 + r)*ld + k0 + c;
    float v[16];
    #pragma unroll
    for (int q = 0; q < 4; q++) {
        float4 f = *(const float4*)(G + off + q*4);
        float4 m = *(const float4*)(Msk + off + q*4);
        v[q*4+0]=s*f.x+m.x; v[q*4+1]=s*f.y+m.y; v[q*4+2]=s*f.z+m.z; v[q*4+3]=s*f.w+m.w;
    }
    u32 h[8], l[8];
    #pragma unroll
    for (int q = 0; q < 8; q++)
        pack_hl(__expf(v[2*q]), __expf(v[2*q+1]), h[q], l[q]);
    u32* dh = SH + r*TS + (tid & 1)*8;
    u32* dl = SL + r*TS + (tid & 1)*8;
    *(uint4*)dh = *(uint4*)h; *((uint4*)dh+1) = *(uint4*)(h+4);
    *(uint4*)dl = *(uint4*)l; *((uint4*)dl+1) = *(uint4*)(l+4);
}

// ---------- warp mma over a 128x32 A tile, BN=128, 2-term ----------
__device__ __forceinline__ void mma128(const u32* AH, const u32* AL,
                                       const u32* BH,
                                       float d[2][8][4],
                                       int wr0, int wc0, int qr, int qc) {
    #pragma unroll
    for (int ks = 0; ks < 2; ks++) {
        int ku = ks*8;
        u32 ah[2][4], al[2][4];
        #pragma unroll
        for (int i = 0; i < 2; i++) {
            int r = wr0 + i*16 + qr;
            ah[i][0]=AH[r*TS+ku+qc];     ah[i][1]=AH[(r+8)*TS+ku+qc];
            ah[i][2]=AH[r*TS+ku+qc+4];   ah[i][3]=AH[(r+8)*TS+ku+qc+4];
            al[i][0]=AL[r*TS+ku+qc];     al[i][1]=AL[(r+8)*TS+ku+qc];
            al[i][2]=AL[r*TS+ku+qc+4];   al[i][3]=AL[(r+8)*TS+ku+qc+4];
        }
        #pragma unroll
        for (int j = 0; j < 8; j++) {
            int n = wc0 + j*8 + qr;
            u32 bh[2] = {BH[n*TS+ku+qc], BH[n*TS+ku+qc+4]};
            #pragma unroll
            for (int i = 0; i < 2; i++) {
                MMAB(d[i][j], ah[i], bh);
                MMAB(d[i][j], al[i], bh);
            }
        }
    }
}
// ---------- warp mma, BN=64 dual B (num/den), 2-term ----------
__device__ __forceinline__ void mma64x2(const u32* AH, const u32* AL,
                                        const u32* B1H, const u32* B2H,
                                        float d1[2][4][4], float d2[2][4][4],
                                        int wr0, int wc0, int qr, int qc) {
    #pragma unroll
    for (int ks = 0; ks < 2; ks++) {
        int ku = ks*8;
        u32 ah[2][4], al[2][4];
        #pragma unroll
        for (int i = 0; i < 2; i++) {
            int r = wr0 + i*16 + qr;
            ah[i][0]=AH[r*TS+ku+qc];     ah[i][1]=AH[(r+8)*TS+ku+qc];
            ah[i][2]=AH[r*TS+ku+qc+4];   ah[i][3]=AH[(r+8)*TS+ku+qc+4];
            al[i][0]=AL[r*TS+ku+qc];     al[i][1]=AL[(r+8)*TS+ku+qc];
            al[i][2]=AL[r*TS+ku+qc+4];   al[i][3]=AL[(r+8)*TS+ku+qc+4];
        }
        #pragma unroll
        for (int j = 0; j < 4; j++) {
            int n = wc0 + j*8 + qr;
            {
                u32 bh[2] = {B1H[n*TS+ku+qc], B1H[n*TS+ku+qc+4]};
                #pragma unroll
                for (int i = 0; i < 2; i++) {
                    MMAB(d1[i][j], ah[i], bh);
                    MMAB(d1[i][j], al[i], bh);
                }
            }
            {
                u32 bh[2] = {B2H[n*TS+ku+qc], B2H[n*TS+ku+qc+4]};
                #pragma unroll
                for (int i = 0; i < 2; i++) {
                    MMAB(d2[i][j], ah[i], bh);
                    MMAB(d2[i][j], al[i], bh);
                }
            }
        }
    }
}

// =====================================================================
// qkv (pass-parallel): grid.y+pbase selects pass.
// pass0 -> SQ=sigmoid(q), pass1 -> EK=exp(k), pass2 -> V raw
// =====================================================================
__global__ __launch_bounds__(256, 2) void qkv_tc(
        const u16* __restrict__ XH, const u16* __restrict__ XL,
        const u16* __restrict__ W0H,
        const u16* __restrict__ W1H_,
        const u16* __restrict__ W2H_,
        float* __restrict__ SQ, float* __restrict__ EK, float* __restrict__ V,
        int pbase) {
    extern __shared__ u32 smu[];
    const u32 sb = smem_u32(smu);
    const int tid = threadIdx.x, lane = tid & 31, w = tid >> 5;
    const int wr0 = (w >> 1)*32, wc0 = (w & 1)*64;
    const int qr = lane >> 2, qc = lane & 3;
    const int m0 = blockIdx.x*128;
    const int pass = blockIdx.y + pbase;
    const u16* BgH = (pass == 0) ? W0H : (pass == 1) ? W1H_ : W2H_;

    ldA128_async(XH, XL, EE, m0, 0, sb, sb + SZU*4, tid);
    ldB128_async(BgH, EE, 0, 0, sb + 2*SZU*4, tid);
    CPA_COMMIT();
    float d[2][8][4] = {};
    for (int t = 0; t < 4; t++) {
        CPA_WAIT0();
        __syncthreads();
        if (t + 1 < 4) {
            int s2 = (t+1) & 1, k2 = (t+1)*32;
            ldA128_async(XH, XL, EE, m0, k2,
                         sb + (3*s2)*SZU*4, sb + (3*s2+1)*SZU*4, tid);
            ldB128_async(BgH, EE, 0, k2, sb + (3*s2+2)*SZU*4, tid);
            CPA_COMMIT();
        }
        int s = t & 1;
        mma128(smu + 3*s*SZU, smu + (3*s+1)*SZU, smu + (3*s+2)*SZU,
               d, wr0, wc0, qr, qc);
    }
    #pragma unroll
    for (int i = 0; i < 2; i++)
        #pragma unroll
        for (int h = 0; h < 2; h++) {
            int row = m0 + wr0 + i*16 + qr + h*8;
            #pragma unroll
            for (int j = 0; j < 8; j++) {
                int col = wc0 + j*8 + qc*2;
                size_t o = (size_t)row*EE + col;
                float v0 = d[i][j][h*2], v1 = d[i][j][h*2+1];
                if (pass == 0) {
                    *(float2*)&SQ[o] = make_float2(
                        1.f/(1.f + __expf(-v0)), 1.f/(1.f + __expf(-v1)));
                } else if (pass == 1) {
                    *(float2*)&EK[o] = make_float2(__expf(v0), __expf(v1));
                } else {
                    *(float2*)&V[o] = make_float2(v0, v1);
                }
            }
        }
}

// =====================================================================
// encoder AFT: A=exp(s*dist) computed, dual B hi async; single-sync loop
// =====================================================================
__global__ __launch_bounds__(256, 2) void aft_enc_tc(
        const float* __restrict__ dist,
        const float* __restrict__ ls,
        const float* __restrict__ alpha, int l,
        const u16* __restrict__ EKVTH,
        const u16* __restrict__ EKTH,
        const float* __restrict__ X,
        const float* __restrict__ SQ,
        float* __restrict__ Y) {
    extern __shared__ u32 smu[];
    const u32 sb = smem_u32(smu);
    const int tid = threadIdx.x, lane = tid & 31, w = tid >> 5;
    const int wr0 = (w >> 1)*32, wc0 = (w & 1)*32;
    const int qr = lane >> 2, qc = lane & 3;
    const int b = blockIdx.z;
    const int m0 = blockIdx.x*128, n0 = blockIdx.y*64;
    const float s = ls[0]*alpha[l];
    const float* D = dist + (size_t)b*NN*NN;
    const u16* T1H = EKVTH + (size_t)b*EE*NN;
    const u16* T2H = EKTH  + (size_t)b*EE*NN;
    ld_Aexp(D, NN, m0, 0, smu, smu + SZU, tid, s);
    ldB64x2_async(T1H, T2H, NN, n0, 0,
                  sb + 2*SZU*4, sb + (2*SZU+SZH)*4, tid);
    CPA_COMMIT();
    float d1[2][4][4] = {}, d2[2][4][4] = {};
    for (int t = 0; t < 16; t++) {
        CPA_WAIT0();
        __syncthreads();
        if (t + 1 < 16) {
            int s2 = (t+1) & 1, k2 = (t+1)*32;
            u32 bbase = sb + (3*s2+2)*SZU*4;
            ldB64x2_async(T1H, T2H, NN, n0, k2, bbase, bbase + SZH*4, tid);
            CPA_COMMIT();
        }
        int s1 = t & 1;
        u32 bo = (3*s1+2)*SZU;
        mma64x2(smu + 3*s1*SZU, smu + (3*s1+1)*SZU,
                smu + bo, smu + bo + SZH,
                d1, d2, wr0, wc0, qr, qc);
        if (t + 1 < 16) {
            int s2 = (t+1) & 1;
            ld_Aexp(D, NN, m0, (t+1)*32, smu + 3*s2*SZU, smu + (3*s2+1)*SZU, tid, s);
        }
    }
    #pragma unroll
    for (int i = 0; i < 2; i++)
        #pragma unroll
        for (int h = 0; h < 2; h++) {
            int row = m0 + wr0 + i*16 + qr + h*8;
            #pragma unroll
            for (int j = 0; j < 4; j++) {
                int col = n0 + wc0 + j*8 + qc*2;
                size_t o = ((size_t)b*NN + row)*EE + col;
                float2 xv = *(const float2*)&X[o];
                float2 sv = *(const float2*)&SQ[o];
                float n0v = d1[i][j][h*2], n1v = d1[i][j][h*2+1];
                float de0 = d2[i][j][h*2], de1 = d2[i][j][h*2+1];
                *(float2*)&Y[o] = make_float2(
                    xv.x + sv.x*(n0v/de0), xv.y + sv.y*(n1v/de1));
            }
        }
}

// =====================================================================
// decoder AFT
// =====================================================================
__global__ __launch_bounds__(256, 2) void dec_aft_tc(
        const float* __restrict__ cur_dist,
        const float* __restrict__ ninf,
        const float* __restrict__ ls,
        const float* __restrict__ dalpha,
        const u16* __restrict__ EKVTH,
        const u16* __restrict__ EKTH,
        const float* __restrict__ GQ,
        const float* __restrict__ cap,
        const float* __restrict__ dWq,
        u16* __restrict__ AFTH, u16* __restrict__ AFTL) {
    extern __shared__ u32 smu[];
    const u32 sb = smem_u32(smu);
    const int tid = threadIdx.x, lane = tid & 31, w = tid >> 5;
    const int wr0 = (w >> 1)*32, wc0 = (w & 1)*32;
    const int qr = lane >> 2, qc = lane & 3;
    const int b = blockIdx.z;
    const int m0 = blockIdx.x*128, n0 = blockIdx.y*64;
    const float s = ls[0]*dalpha[0];
    const float* CD = cur_dist + (size_t)b*PP*NN;
    const float* NM = ninf     + (size_t)b*PP*NN;
    const u16* T1H = EKVTH + (size_t)b*EE*NN;
    const u16* T2H = EKTH  + (size_t)b*EE*NN;
    ld_Aexpmask(CD, NM, NN, m0, 0, smu, smu + SZU, tid, s);
    ldB64x2_async(T1H, T2H, NN, n0, 0,
                  sb + 2*SZU*4, sb + (2*SZU+SZH)*4, tid);
    CPA_COMMIT();
    float d1[2][4][4] = {}, d2[2][4][4] = {};
    for (int t = 0; t < 16; t++) {
        CPA_WAIT0();
        __syncthreads();
        if (t + 1 < 16) {
            int s2 = (t+1) & 1, k2 = (t+1)*32;
            u32 bbase = sb + (3*s2+2)*SZU*4;
            ldB64x2_async(T1H, T2H, NN, n0, k2, bbase, bbase + SZH*4, tid);
            CPA_COMMIT();
        }
        int s1 = t & 1;
        u32 bo = (3*s1+2)*SZU;
        mma64x2(smu + 3*s1*SZU, smu + (3*s1+1)*SZU,
                smu + bo, smu + bo + SZH,
                d1, d2, wr0, wc0, qr, qc);
        if (t + 1 < 16) {
            int s2 = (t+1) & 1;
            ld_Aexpmask(CD, NM, NN, m0, (t+1)*32,
                        smu + 3*s2*SZU, smu + (3*s2+1)*SZU, tid, s);
        }
    }
    #pragma unroll
    for (int i = 0; i < 2; i++)
        #pragma unroll
        for (int h = 0; h < 2; h++) {
            int p = m0 + wr0 + i*16 + qr + h*8;
            float cv = cap[(size_t)b*PP + p];
            #pragma unroll
            for (int j = 0; j < 4; j++) {
                int col = n0 + wc0 + j*8 + qc*2;
                float2 gq2 = *(const float2*)&GQ[b*EE + col];
                float2 wq2 = *(const float2*)&dWq[EE*EE + col];
                float q0 = gq2.x + cv*wq2.x;
                float q1 = gq2.y + cv*wq2.y;
                float sg0 = 1.f/(1.f + __expf(-q0));
                float sg1 = 1.f/(1.f + __expf(-q1));
                float v0 = sg0*(d1[i][j][h*2]  /d2[i][j][h*2]);
                float v1 = sg1*(d1[i][j][h*2+1]/d2[i][j][h*2+1]);
                u32 hh, ll; pack_hl(v0, v1, hh, ll);
                size_t o = ((size_t)b*PP + p)*EE + col;
                *(u32*)&AFTH[o] = hh;
                *(u32*)&AFTL[o] = ll;
            }
        }
}

// =====================================================================
// FF1: hid = relu(h@W1 + b1) -> fp16 hi/lo
// =====================================================================
__global__ __launch_bounds__(256, 2) void ff1_tc(
        const u16* __restrict__ HH, const u16* __restrict__ HL,
        const u16* __restrict__ W1H,
        const float* __restrict__ b1,
        u16* __restrict__ HIDH, u16* __restrict__ HIDL) {
    extern __shared__ u32 smu[];
    const u32 sb = smem_u32(smu);
    const int tid = threadIdx.x, lane = tid & 31, w = tid >> 5;
    const int wr0 = (w >> 1)*32, wc0 = (w & 1)*64;
    const int qr = lane >> 2, qc = lane & 3;
    const int m0 = blockIdx.x*128, n0 = blockIdx.y*128;
    ldA128_async(HH, HL, EE, m0, 0, sb, sb + SZU*4, tid);
    ldB128_async(W1H, EE, n0, 0, sb + 2*SZU*4, tid);
    CPA_COMMIT();
    float d[2][8][4] = {};
    for (int t = 0; t < 4; t++) {
        CPA_WAIT0();
        __syncthreads();
        if (t + 1 < 4) {
            int s2 = (t+1) & 1, k2 = (t+1)*32;
            ldA128_async(HH, HL, EE, m0, k2,
                         sb + (3*s2)*SZU*4, sb + (3*s2+1)*SZU*4, tid);
            ldB128_async(W1H, EE, n0, k2, sb + (3*s2+2)*SZU*4, tid);
            CPA_COMMIT();
        }
        int s = t & 1;
        mma128(smu + 3*s*SZU, smu + (3*s+1)*SZU, smu + (3*s+2)*SZU,
               d, wr0, wc0, qr, qc);
    }
    #pragma unroll
    for (int i = 0; i < 2; i++)
        #pragma unroll
        for (int h = 0; h < 2; h++) {
            int row = m0 + wr0 + i*16 + qr + h*8;
            #pragma unroll
            for (int j = 0; j < 8; j++) {
                int col = n0 + wc0 + j*8 + qc*2;
                float2 bb = *(const float2*)&b1[col];
                float v0 = fmaxf(d[i][j][h*2]   + bb.x, 0.f);
                float v1 = fmaxf(d[i][j][h*2+1] + bb.y, 0.f);
                u32 hh, ll; pack_hl(v0, v1, hh, ll);
                size_t o = (size_t)row*FFD + col;
                *(u32*)&HIDH[o] = hh;
                *(u32*)&HIDL[o] = ll;
            }
        }
}

// =====================================================================
// FF2: y = h + hid@W2 + b2  (K=512, 16 chunks)
// =====================================================================
__global__ __launch_bounds__(256, 2) void ff2_tc(
        const u16* __restrict__ HIDH, const u16* __restrict__ HIDL,
        const u16* __restrict__ W2H,
        const float* __restrict__ b2,
        const float* __restrict__ H,
        float* __restrict__ Y) {
    extern __shared__ u32 smu[];
    const u32 sb = smem_u32(smu);
    const int tid = threadIdx.x, lane = tid & 31, w = tid >> 5;
    const int wr0 = (w >> 1)*32, wc0 = (w & 1)*64;
    const int qr = lane >> 2, qc = lane & 3;
    const int m0 = blockIdx.x*128;
    ldA128_async(HIDH, HIDL, FFD, m0, 0, sb, sb + SZU*4, tid);
    ldB128_async(W2H, FFD, 0, 0, sb + 2*SZU*4, tid);
    CPA_COMMIT();
    float d[2][8][4] = {};
    for (int t = 0; t < 16; t++) {
        CPA_WAIT0();
        __syncthreads();
        if (t + 1 < 16) {
            int s2 = (t+1) & 1, k2 = (t+1)*32;
            ldA128_async(HIDH, HIDL, FFD, m0, k2,
                         sb + (3*s2)*SZU*4, sb + (3*s2+1)*SZU*4, tid);
            ldB128_async(W2H, FFD, 0, k2, sb + (3*s2+2)*SZU*4, tid);
            CPA_COMMIT();
        }
        int s = t & 1;
        mma128(smu + 3*s*SZU, smu + (3*s+1)*SZU, smu + (3*s+2)*SZU,
               d, wr0, wc0, qr, qc);
    }
    #pragma unroll
    for (int i = 0; i < 2; i++)
        #pragma unroll
        for (int h = 0; h < 2; h++) {
            int row = m0 + wr0 + i*16 + qr + h*8;
            #pragma unroll
            for (int j = 0; j < 8; j++) {
                int col = wc0 + j*8 + qc*2;
                float2 bb = *(const float2*)&b2[col];
                size_t o = (size_t)row*EE + col;
                float2 hv = *(const float2*)&H[o];
                *(float2*)&Y[o] = make_float2(
                    hv.x + d[i][j][h*2]   + bb.x,
                    hv.y + d[i][j][h*2+1] + bb.y);
            }
        }
}

// =====================================================================
// score: S = aft @ enc^T + epilogue (K=128)
// =====================================================================
__global__ __launch_bounds__(256, 2) void score_tc(
        const u16* __restrict__ AFTH, const u16* __restrict__ AFTL,
        const u16* __restrict__ XH,
        const float* __restrict__ cur_dist,
        const float* __restrict__ ninf,
        const float* __restrict__ ls,
        const float* __restrict__ palpha,
        float* __restrict__ OUT) {
    extern __shared__ u32 smu[];
    const u32 sb = smem_u32(smu);
    const int tid = threadIdx.x, lane = tid & 31, w = tid >> 5;
    const int wr0 = (w >> 1)*32, wc0 = (w & 1)*64;
    const int qr = lane >> 2, qc = lane & 3;
    const int b = blockIdx.z;
    const int p0 = blockIdx.x*128, n0 = blockIdx.y*128;
    const float ps = ls[0]*palpha[0];
    const u16* AgH = AFTH + (size_t)b*PP*EE;
    const u16* AgL = AFTL + (size_t)b*PP*EE;
    const u16* BgH = XH + (size_t)b*NN*EE;
    ldA128_async(AgH, AgL, EE, p0, 0, sb, sb + SZU*4, tid);
    ldB128_async(BgH, EE, n0, 0, sb + 2*SZU*4, tid);
    CPA_COMMIT();
    float d[2][8][4] = {};
    for (int t = 0; t < 4; t++) {
        CPA_WAIT0();
        __syncthreads();
        if (t + 1 < 4) {
            int s2 = (t+1) & 1, k2 = (t+1)*32;
            ldA128_async(AgH, AgL, EE, p0, k2,
                         sb + (3*s2)*SZU*4, sb + (3*s2+1)*SZU*4, tid);
            ldB128_async(BgH, EE, n0, k2, sb + (3*s2+2)*SZU*4, tid);
            CPA_COMMIT();
        }
        int s = t & 1;
        mma128(smu + 3*s*SZU, smu + (3*s+1)*SZU, smu + (3*s+2)*SZU,
               d, wr0, wc0, qr, qc);
    }
    #pragma unroll
    for (int i = 0; i < 2; i++)
        #pragma unroll
        for (int h = 0; h < 2; h++) {
            int p = p0 + wr0 + i*16 + qr + h*8;
            #pragma unroll
            for (int j = 0; j < 8; j++) {
                int n = n0 + wc0 + j*8 + qc*2;
                size_t o = ((size_t)b*PP + p)*NN + n;
                float2 cd = *(const float2*)&cur_dist[o];
                float2 nm = *(const float2*)&ninf[o];
                float s0 = d[i][j][h*2]  *INV_SQRT_E + ps*cd.x;
                float s1 = d[i][j][h*2+1]*INV_SQRT_E + ps*cd.y;
                *(float2*)&OUT[o] = make_float2(
                    10.f*tanhf(s0) + nm.x, 10.f*tanhf(s1) + nm.y);
            }
        }
}

// =====================================================================
// weight transpose-convert (batched; hi only)
// =====================================================================
__device__ __forceinline__ void wconv_body(const float* __restrict__ src,
                                           u16* __restrict__ dH,
                                           int K, int N) {
    __shared__ float t[32][33];
    int n0 = blockIdx.x*32, k0 = blockIdx.y*32;
    int tr = threadIdx.x >> 3, tc4 = (threadIdx.x & 7)*4;
    float4 v = *(const float4*)&src[(size_t)(k0+tr)*N + n0 + tc4];
    t[tc4+0][tr] = v.x; t[tc4+1][tr] = v.y;
    t[tc4+2][tr] = v.z; t[tc4+3][tr] = v.w;
    __syncthreads();
    int r = threadIdx.x >> 3, c4 = (threadIdx.x & 7)*4;
    u16 h[4];
    #pragma unroll
    for (int i = 0; i < 4; i++) h[i] = cvt_h(t[r][c4+i]);
    size_t o = (size_t)(n0+r)*K + k0 + c4;
    *(uint2*)&dH[o] = *(uint2*)h;
}
__global__ void wconv_sq(const float* __restrict__ Wq, const float* __restrict__ Wk,
                         const float* __restrict__ Wv,
                         const float* __restrict__ dWk, const float* __restrict__ dWv,
                         u16* qH, u16* kH, u16* vH, u16* dkH, u16* dvH) {
    int z = blockIdx.z;
    const float* src; u16 *dH;
    size_t off = (size_t)(z % 6)*EE*EE;
    if (z < 6)       { src = Wq + off; dH = qH + off; }
    else if (z < 12) { src = Wk + off; dH = kH + off; }
    else if (z < 18) { src = Wv + off; dH = vH + off; }
    else if (z == 18){ src = dWk; dH = dkH; }
    else             { src = dWv; dH = dvH; }
    wconv_body(src, dH, EE, EE);
}
__global__ void wconv_w1(const float* __restrict__ W1, u16* dH) {
    int l = blockIdx.z;
    wconv_body(W1 + (size_t)l*EE*FFD, dH + (size_t)l*FFD*EE, EE, FFD);
}
__global__ void wconv_w2(const float* __restrict__ W2, u16* dH) {
    int l = blockIdx.z;
    wconv_body(W2 + (size_t)l*FFD*EE, dH + (size_t)l*EE*FFD, FFD, EE);
}

// =====================================================================
// ek/v transpose-convert: ekT = fp16(ek), ekvT = fp16(ek * v_raw), hi only
// =====================================================================
__global__ void ekconv_kernel(const float* __restrict__ ek,
                              const float* __restrict__ vraw,
                              u16* __restrict__ ekTH,
                              u16* __restrict__ ekvTH) {
    __shared__ float t1[32][33], t2[32][33];
    int b = blockIdx.z;
    int e0 = blockIdx.x*32, nd0 = blockIdx.y*32;
    const float* S1 = ek   + (size_t)b*NN*EE;
    const float* S2 = vraw + (size_t)b*NN*EE;
    int tr = threadIdx.x >> 3, tc4 = (threadIdx.x & 7)*4;
    size_t so = (size_t)(nd0+tr)*EE + e0 + tc4;
    float4 v1 = *(const float4*)&S1[so];
    float4 v2 = *(const float4*)&S2[so];
    t1[tc4+0][tr]=v1.x; t1[tc4+1][tr]=v1.y; t1[tc4+2][tr]=v1.z; t1[tc4+3][tr]=v1.w;
    t2[tc4+0][tr]=v2.x; t2[tc4+1][tr]=v2.y; t2[tc4+2][tr]=v2.z; t2[tc4+3][tr]=v2.w;
    __syncthreads();
    int r = threadIdx.x >> 3, c4 = (threadIdx.x & 7)*4;
    size_t o = (size_t)b*EE*NN + (size_t)(e0+r)*NN + nd0 + c4;
    u16 h[4];
    #pragma unroll
    for (int i = 0; i < 4; i++) h[i] = cvt_h(t1[r][c4+i]);
    *(uint2*)&ekTH[o] = *(uint2*)h;
    #pragma unroll
    for (int i = 0; i < 4; i++) h[i] = cvt_h(t1[r][c4+i]*t2[r][c4+i]);
    *(uint2*)&ekvTH[o] = *(uint2*)h;
}

// ---------------- embedding (2 rows/block; also writes fp16 hi/lo) ----------------
__global__ void embed_kernel(const float* __restrict__ data,
                             const float* __restrict__ W,
                             const float* __restrict__ bias,
                             float* __restrict__ X,
                             u16* __restrict__ XH, u16* __restrict__ XL) {
    int idx = blockIdx.x*2 + threadIdx.y;
    int e   = threadIdx.x;
    float d0 = data[idx*2+0], d1 = data[idx*2+1];
    float v = d0*W[e] + d1*W[EE+e] + bias[e];
    size_t o = (size_t)idx*EE + e;
    X[o] = v;
    u16 h, l; cvt_hl(v, h, l);
    XH[o] = h; XL[o] = l;
}

// ---------------- instance norm: grid (BB,4), block (32,8) ----------------
__global__ void inorm_kernel(const float* __restrict__ src,
                             float* __restrict__ dst,
                             u16* __restrict__ dstH, u16* __restrict__ dstL,
                             const float* __restrict__ w,
                             const float* __restrict__ bias) {
    int b  = blockIdx.x;
    int ge = blockIdx.y*32 + threadIdx.x;   // global channel
    int e  = threadIdx.x;                   // 0..31
    int c  = threadIdx.y;                   // 0..7
    const float* S = src + (size_t)b*NN*EE;
    float s = 0.f, s2 = 0.f;
    for (int n = c*64; n < c*64 + 64; n++) {
        float v = S[(size_t)n*EE + ge];
        s += v; s2 += v*v;
    }
    __shared__ float ssum[8][32], ssq[8][32];
    __shared__ float smu2[32], srs[32];
    ssum[c][e] = s; ssq[c][e] = s2;
    __syncthreads();
    if (c == 0) {
        float ts = 0.f, t2 = 0.f;
        #pragma unroll
        for (int i = 0; i < 8; i++) { ts += ssum[i][e]; t2 += ssq[i][e]; }
        float mu = ts*(1.f/NN);
        float var = t2*(1.f/NN) - mu*mu;
        smu2[e] = mu;
        srs[e] = rsqrtf(var + EPS);
    }
    __syncthreads();
    float mu = smu2[e], rs = srs[e], ww = w[ge], bb = bias[ge];
    size_t base = (size_t)b*NN*EE;
    for (int n = c*64; n < c*64 + 64; n++) {
        size_t o = base + (size_t)n*EE + ge;
        float v = (S[(size_t)n*EE + ge] - mu)*rs*ww + bb;
        dst[o] = v;
        u16 h, l; cvt_hl(v, h, l);
        dstH[o] = h; dstL[o] = l;
    }
}

// ---------------- fused graph-mean + gq: GQ[b,e] = mean_n(X)[b] @ dWq[:,e] ----------------
__global__ void gmeanq_kernel(const float* __restrict__ X,
                              const float* __restrict__ dWq,
                              float* __restrict__ GQ) {
    int b = blockIdx.x, e = threadIdx.x, c = threadIdx.y;  // (128, 8)
    float s = 0.f;
    for (int n = c*64; n < c*64 + 64; n++)
        s += X[((size_t)b*NN + n)*EE + e];
    __shared__ float sm[8][128];
    __shared__ float gm[128];
    sm[c][e] = s;
    __syncthreads();
    if (c == 0) {
        float t = 0.f;
        #pragma unroll
        for (int i = 0; i < 8; i++) t += sm[i][e];
        gm[e] = t*(1.f/NN);
    }
    __syncthreads();
    // gq: partial dot over i-range per c, then ordered 8-way reduce
    float acc = 0.f;
    for (int i = c*16; i < c*16 + 16; i++)
        acc += gm[i]*dWq[i*EE + e];
    __syncthreads();
    sm[c][e] = acc;
    __syncthreads();
    if (c == 0) {
        float t = 0.f;
        #pragma unroll
        for (int i = 0; i < 8; i++) t += sm[i][e];
        GQ[b*EE + e] = t;
    }
}

// ---------------- row softmax over last dim (512) ----------------
__global__ void softmax_kernel(float* __restrict__ OUT) {
    float* row = OUT + (size_t)blockIdx.x*NN;
    int t = threadIdx.x;
    float v[4];
    #pragma unroll
    for (int i = 0; i < 4; i++) v[i] = row[t + i*128];
    float m = fmaxf(fmaxf(v[0], v[1]), fmaxf(v[2], v[3]));
    __shared__ float red[4];
    #pragma unroll
    for (int off = 16; off > 0; off >>= 1)
        m = fmaxf(m, __shfl_xor_sync(0xffffffff, m, off));
    if ((t & 31) == 0) red[t >> 5] = m;
    __syncthreads();
    m = fmaxf(fmaxf(red[0], red[1]), fmaxf(red[2], red[3]));
    __syncthreads();
    float s = 0.f;
    #pragma unroll
    for (int i = 0; i < 4; i++) { v[i] = __expf(v[i] - m); s += v[i]; }
    #pragma unroll
    for (int off = 16; off > 0; off >>= 1)
        s += __shfl_xor_sync(0xffffffff, s, off);
    if ((t & 31) == 0) red[t >> 5] = s;
    __syncthreads();
    s = red[0] + red[1] + red[2] + red[3];
    float inv = 1.f/s;
    #pragma unroll
    for (int i = 0; i < 4; i++) row[t + i*128] = v[i]*inv;
}

// ---------------- launch ----------------
extern "C" void kernel_launch(void* const* d_in, const int* in_sizes, int n_in,
                              void* d_out, int out_size) {
    const float* data      = (const float*)d_in[0];
    const float* dist      = (const float*)d_in[1];
    const float* cur_dist  = (const float*)d_in[2];
    const float* capacity  = (const float*)d_in[3];
    const float* ninf_mask = (const float*)d_in[4];
    const float* log_scale = (const float*)d_in[5];
    const float* emb_W     = (const float*)d_in[6];
    const float* emb_b     = (const float*)d_in[7];
    const float* Wq        = (const float*)d_in[8];
    const float* Wk        = (const float*)d_in[9];
    const float* Wv        = (const float*)d_in[10];
    const float* aft_alpha = (const float*)d_in[11];
    const float* n1_w      = (const float*)d_in[12];
    const float* n1_b      = (const float*)d_in[13];
    const float* ff_W1     = (const float*)d_in[14];
    const float* ff_b1     = (const float*)d_in[15];
    const float* ff_W2     = (const float*)d_in[16];
    const float* ff_b2     = (const float*)d_in[17];
    const float* n2_w      = (const float*)d_in[18];
    const float* n2_b      = (const float*)d_in[19];
    const float* dWq       = (const float*)d_in[20];
    const float* dWk       = (const float*)d_in[21];
    const float* dWv       = (const float*)d_in[22];
    const float* dec_alpha = (const float*)d_in[23];
    const float* p_alpha   = (const float*)d_in[24];
    float* out = (float*)d_out;

    float *x, *y, *h, *sq, *ek, *ekv, *gq;
    cudaGetSymbolAddress((void**)&x,   g_x);
    cudaGetSymbolAddress((void**)&y,   g_y);
    cudaGetSymbolAddress((void**)&h,   g_h);
    cudaGetSymbolAddress((void**)&sq,  g_sq);
    cudaGetSymbolAddress((void**)&ek,  g_ek);
    cudaGetSymbolAddress((void**)&ekv, g_ekv);
    cudaGetSymbolAddress((void**)&gq,  g_gq);

    u16 *xH,*xL,*hH,*hL,*hidH,*hidL,*aftH,*aftL;
    u16 *ekTH,*ekvTH;
    u16 *wqTH,*wkTH,*wvTH,*w1TH,*w2TH,*dkTH,*dvTH;
    cudaGetSymbolAddress((void**)&xH,   g_xH);   cudaGetSymbolAddress((void**)&xL,   g_xL);
    cudaGetSymbolAddress((void**)&hH,   g_hH);   cudaGetSymbolAddress((void**)&hL,   g_hL);
    cudaGetSymbolAddress((void**)&hidH, g_hidH); cudaGetSymbolAddress((void**)&hidL, g_hidL);
    cudaGetSymbolAddress((void**)&aftH, g_aftH); cudaGetSymbolAddress((void**)&aftL, g_aftL);
    cudaGetSymbolAddress((void**)&ekTH, g_ekTH);
    cudaGetSymbolAddress((void**)&ekvTH,g_ekvTH);
    cudaGetSymbolAddress((void**)&wqTH, g_wqTH);
    cudaGetSymbolAddress((void**)&wkTH, g_wkTH);
    cudaGetSymbolAddress((void**)&wvTH, g_wvTH);
    cudaGetSymbolAddress((void**)&w1TH, g_w1TH);
    cudaGetSymbolAddress((void**)&w2TH, g_w2TH);
    cudaGetSymbolAddress((void**)&dkTH, g_dkTH);
    cudaGetSymbolAddress((void**)&dvTH, g_dvTH);

    cudaFuncSetAttribute(qkv_tc,     cudaFuncAttributeMaxDynamicSharedMemorySize, SMEM_SZ);
    cudaFuncSetAttribute(aft_enc_tc, cudaFuncAttributeMaxDynamicSharedMemorySize, SMEM_SZ);
    cudaFuncSetAttribute(dec_aft_tc, cudaFuncAttributeMaxDynamicSharedMemorySize, SMEM_SZ);
    cudaFuncSetAttribute(ff1_tc,     cudaFuncAttributeMaxDynamicSharedMemorySize, SMEM_SZ);
    cudaFuncSetAttribute(ff2_tc,     cudaFuncAttributeMaxDynamicSharedMemorySize, SMEM_SZ);
    cudaFuncSetAttribute(score_tc,   cudaFuncAttributeMaxDynamicSharedMemorySize, SMEM_SZ);

    // ---- batched weight transpose+convert (3 launches) ----
    wconv_sq<<<dim3(EE/32, EE/32, 20), 256>>>(Wq, Wk, Wv, dWk, dWv,
        wqTH, wkTH, wvTH, dkTH, dvTH);
    wconv_w1<<<dim3(FFD/32, EE/32, LLAYERS), 256>>>(ff_W1, w1TH);
    wconv_w2<<<dim3(EE/32, FFD/32, LLAYERS), 256>>>(ff_W2, w2TH);

    embed_kernel<<<M_TOT/2, dim3(EE, 2)>>>(data, emb_W, emb_b, x, xH, xL);

    for (int l = 0; l < LLAYERS; l++) {
        // 3 independent passes: q->SQ, k->EK, v->Vraw(in ekv buffer)
        qkv_tc<<<dim3(M_TOT/128, 3), 256, SMEM_SZ>>>(
            xH, xL,
            wqTH + (size_t)l*EE*EE,
            wkTH + (size_t)l*EE*EE,
            wvTH + (size_t)l*EE*EE,
            sq, ek, ekv, 0);
        ekconv_kernel<<<dim3(EE/32, NN/32, BB), 256>>>(ek, ekv, ekTH, ekvTH);
        aft_enc_tc<<<dim3(NN/128, EE/64, BB), 256, SMEM_SZ>>>(
            dist, log_scale, aft_alpha, l, ekvTH, ekTH, x, sq, y);
        inorm_kernel<<<dim3(BB, 4), dim3(32, 8)>>>(y, h, hH, hL,
                                                   n1_w + l*EE, n1_b + l*EE);
        ff1_tc<<<dim3(M_TOT/128, FFD/128), 256, SMEM_SZ>>>(
            hH, hL, w1TH + (size_t)l*FFD*EE, ff_b1 + l*FFD, hidH, hidL);
        ff2_tc<<<M_TOT/128, 256, SMEM_SZ>>>(
            hidH, hidL, w2TH + (size_t)l*EE*FFD, ff_b2 + l*EE, h, y);
        inorm_kernel<<<dim3(BB, 4), dim3(32, 8)>>>(y, x, xH, xL,
                                                   n2_w + l*EE, n2_b + l*EE);
    }

    // decoder: passes 1,2 of qkv_tc (k->EK, v->Vraw)
    qkv_tc<<<dim3(M_TOT/128, 2), 256, SMEM_SZ>>>(
        xH, xL,
        dkTH,            /* unused slot (pass 0 never taken) */
        dkTH,            /* pass 1: dWk */
        dvTH,            /* pass 2: dWv */
        sq, ek, ekv, 1);
    ekconv_kernel<<<dim3(EE/32, NN/32, BB), 256>>>(ek, ekv, ekTH, ekvTH);
    gmeanq_kernel<<<BB, dim3(128, 8)>>>(x, dWq, gq);
    dec_aft_tc<<<dim3(PP/128, EE/64, BB), 256, SMEM_SZ>>>(
        cur_dist, ninf_mask, log_scale, dec_alpha,
        ekvTH, ekTH, gq, capacity, dWq, aftH, aftL);
    score_tc<<<dim3(PP/128, NN/128, BB), 256, SMEM_SZ>>>(
        aftH, aftL, xH, cur_dist, ninf_mask, log_scale, p_alpha, out);
    softmax_kernel<<<BB*PP, 128>>>(out);
}